// round 2
// baseline (speedup 1.0000x reference)
#include <cuda_runtime.h>
#include <math.h>
#include <stdint.h>

#define TOK   16384
#define DM    1024
#define DFF   4096
#define NH    16
#define HD    64

// ---------------- scratch (static device allocations; no cudaMalloc) --------
__device__ float g_xln  [(size_t)TOK * DM];        // 64 MB (reused as hln)
__device__ float g_qkv  [(size_t)TOK * 3 * DM];    // 192 MB
__device__ float g_kvz  [64 * 4160];               // per (b,h): 64x64 kv + 64 z
__device__ float g_attny[(size_t)TOK * DM];        // 64 MB
__device__ float g_x    [(size_t)TOK * DM];        // 64 MB
__device__ float g_h    [(size_t)TOK * DFF];       // 256 MB

// ---------------- helpers ---------------------------------------------------
__device__ __forceinline__ float to_tf32(float x) {
    unsigned u;
    asm("cvt.rna.tf32.f32 %0, %1;" : "=r"(u) : "f"(x));
    return __uint_as_float(u);
}

__device__ __forceinline__ float phi(float x) {           // elu(x)+1
    return x > 0.f ? x + 1.f : expf(x);
}

__device__ __forceinline__ float gelu_exact(float x) {
    return 0.5f * x * (1.f + erff(x * 0.70710678118654752440f));
}

__device__ __forceinline__ void mma_tf32(float* d, const unsigned* a, const unsigned* b) {
    asm volatile(
        "mma.sync.aligned.m16n8k8.row.col.f32.tf32.tf32.f32 "
        "{%0,%1,%2,%3}, {%4,%5,%6,%7}, {%8,%9}, {%0,%1,%2,%3};\n"
        : "+f"(d[0]), "+f"(d[1]), "+f"(d[2]), "+f"(d[3])
        : "r"(a[0]), "r"(a[1]), "r"(a[2]), "r"(a[3]), "r"(b[0]), "r"(b[1]));
}

// ---------------- LayerNorm --------------------------------------------------
__global__ void __launch_bounds__(256)
ln_kernel(const float* __restrict__ x, const float* __restrict__ g,
          const float* __restrict__ b, float* __restrict__ y)
{
    int row = blockIdx.x;
    int tid = threadIdx.x;
    const float4* xr = (const float4*)(x + (size_t)row * DM);
    float4 v = xr[tid];
    float s = v.x + v.y + v.z + v.w;
    float q = v.x * v.x + v.y * v.y + v.z * v.z + v.w * v.w;
#pragma unroll
    for (int o = 16; o; o >>= 1) {
        s += __shfl_xor_sync(0xffffffffu, s, o);
        q += __shfl_xor_sync(0xffffffffu, q, o);
    }
    __shared__ float ss[8], sq[8];
    __shared__ float smu, srs;
    int warp = tid >> 5, lane = tid & 31;
    if (!lane) { ss[warp] = s; sq[warp] = q; }
    __syncthreads();
    if (!tid) {
        float S = 0.f, Q = 0.f;
#pragma unroll
        for (int i = 0; i < 8; i++) { S += ss[i]; Q += sq[i]; }
        float mu = S * (1.f / DM);
        float var = Q * (1.f / DM) - mu * mu;
        smu = mu;
        srs = rsqrtf(var + 1e-5f);
    }
    __syncthreads();
    float mu = smu, rs = srs;
    float4 gv = ((const float4*)g)[tid];
    float4 bv = ((const float4*)b)[tid];
    float4 o;
    o.x = (v.x - mu) * rs * gv.x + bv.x;
    o.y = (v.y - mu) * rs * gv.y + bv.y;
    o.z = (v.z - mu) * rs * gv.z + bv.z;
    o.w = (v.w - mu) * rs * gv.w + bv.w;
    ((float4*)(y + (size_t)row * DM))[tid] = o;
}

// ---------------- tf32 tensor-core GEMM -------------------------------------
// C[M,N] = A[M,K] @ B[K,N] + bias  (+resid | gelu)
// Block tile 128x128x32, 256 threads (8 warps: 4(m) x 2(n)), warp tile 32x64.
#define BM 128
#define BN 128
#define BK 32

__global__ void __launch_bounds__(256)
gemm_tf32_kernel(const float* __restrict__ A, const float* __restrict__ B,
                 const float* __restrict__ bias, const float* __restrict__ resid,
                 float* __restrict__ C, int M, int N, int K, int epi)
{
    __shared__ float As[BK][BM + 1];   // stride 129: conflict-lean transposed store
    __shared__ float Bs[BK][BN + 4];   // stride 132: float4-aligned rows

    int tid  = threadIdx.x;
    int bm   = blockIdx.y * BM;
    int bn   = blockIdx.x * BN;
    int warp = tid >> 5, lane = tid & 31;
    int wm   = warp >> 1, wn = warp & 1;
    int gid  = lane >> 2, tig = lane & 3;

    float acc[2][8][4];
#pragma unroll
    for (int i = 0; i < 2; i++)
#pragma unroll
        for (int j = 0; j < 8; j++)
#pragma unroll
            for (int l = 0; l < 4; l++) acc[i][j][l] = 0.f;

    const float* Aptr = A + (size_t)bm * K;
    const float* Bptr = B + bn;

    for (int k0 = 0; k0 < K; k0 += BK) {
        // ---- stage A tile (transposed into As[k][m]) ----
#pragma unroll
        for (int i = 0; i < 4; i++) {
            int e  = tid + i * 256;        // 0..1023 float4 chunks
            int m  = e >> 3;
            int kc = (e & 7) << 2;
            float4 va = *(const float4*)(Aptr + (size_t)m * K + k0 + kc);
            As[kc + 0][m] = to_tf32(va.x);
            As[kc + 1][m] = to_tf32(va.y);
            As[kc + 2][m] = to_tf32(va.z);
            As[kc + 3][m] = to_tf32(va.w);
        }
        // ---- stage B tile (Bs[k][n]) ----
#pragma unroll
        for (int i = 0; i < 4; i++) {
            int e  = tid + i * 256;
            int kk = e >> 5;
            int nc = (e & 31) << 2;
            float4 vb = *(const float4*)(Bptr + (size_t)(k0 + kk) * N + nc);
            vb.x = to_tf32(vb.x); vb.y = to_tf32(vb.y);
            vb.z = to_tf32(vb.z); vb.w = to_tf32(vb.w);
            *(float4*)&Bs[kk][nc] = vb;
        }
        __syncthreads();

#pragma unroll
        for (int kk = 0; kk < BK; kk += 8) {
            unsigned a[2][4], b[8][2];
            int ar = kk + tig;
#pragma unroll
            for (int mf = 0; mf < 2; mf++) {
                int m0 = wm * 32 + mf * 16 + gid;
                a[mf][0] = __float_as_uint(As[ar    ][m0    ]);
                a[mf][1] = __float_as_uint(As[ar    ][m0 + 8]);
                a[mf][2] = __float_as_uint(As[ar + 4][m0    ]);
                a[mf][3] = __float_as_uint(As[ar + 4][m0 + 8]);
            }
#pragma unroll
            for (int nf = 0; nf < 8; nf++) {
                int n0 = wn * 64 + nf * 8 + gid;
                b[nf][0] = __float_as_uint(Bs[ar    ][n0]);
                b[nf][1] = __float_as_uint(Bs[ar + 4][n0]);
            }
#pragma unroll
            for (int mf = 0; mf < 2; mf++)
#pragma unroll
                for (int nf = 0; nf < 8; nf++)
                    mma_tf32(acc[mf][nf], a[mf], b[nf]);
        }
        __syncthreads();
    }

    // ---- epilogue: bias + (none | +resid | gelu), float2 stores ----
#pragma unroll
    for (int mf = 0; mf < 2; mf++) {
#pragma unroll
        for (int nf = 0; nf < 8; nf++) {
            int r = bm + wm * 32 + mf * 16 + gid;
            int c = bn + wn * 64 + nf * 8 + tig * 2;
            float bx = bias[c], by = bias[c + 1];
            float2 v0 = make_float2(acc[mf][nf][0] + bx, acc[mf][nf][1] + by);
            float2 v1 = make_float2(acc[mf][nf][2] + bx, acc[mf][nf][3] + by);
            if (epi == 1) {
                const float* r0 = resid + (size_t)r * N + c;
                const float* r1 = resid + (size_t)(r + 8) * N + c;
                v0.x += r0[0]; v0.y += r0[1];
                v1.x += r1[0]; v1.y += r1[1];
            } else if (epi == 2) {
                v0.x = gelu_exact(v0.x); v0.y = gelu_exact(v0.y);
                v1.x = gelu_exact(v1.x); v1.y = gelu_exact(v1.y);
            }
            *(float2*)(C + (size_t)r * N + c)       = v0;
            *(float2*)(C + (size_t)(r + 8) * N + c) = v1;
        }
    }
}

// ---------------- attention: kv & z accumulation ----------------------------
// grid (64 bh, 32 chunks of 128 rows), 256 threads
__global__ void __launch_bounds__(256)
attn_kv_kernel(const float* __restrict__ qkv)
{
    int bh = blockIdx.x;
    int b = bh >> 4, h = bh & 15;
    int chunk = blockIdx.y;
    int row0 = b * 4096 + chunk * 128;
    const float* kbase = qkv + (size_t)row0 * 3072 + 1024 + h * 64;
    const float* vbase = qkv + (size_t)row0 * 3072 + 2048 + h * 64;

    __shared__ float kb[32][64];
    __shared__ float vb[32][68];

    int tid = threadIdx.x;
    int d  = tid >> 2;
    int e0 = (tid & 3) * 16;
    float acc[16];
#pragma unroll
    for (int j = 0; j < 16; j++) acc[j] = 0.f;
    float zacc = 0.f;

    for (int t0 = 0; t0 < 128; t0 += 32) {
#pragma unroll
        for (int i = 0; i < 2; i++) {
            int e = tid + i * 256;                 // 0..511 float4 chunks
            int r = e >> 4, c4 = (e & 15) << 2;
            float4 kv4 = *(const float4*)(kbase + (size_t)(t0 + r) * 3072 + c4);
            kb[r][c4 + 0] = phi(kv4.x);
            kb[r][c4 + 1] = phi(kv4.y);
            kb[r][c4 + 2] = phi(kv4.z);
            kb[r][c4 + 3] = phi(kv4.w);
            float4 vv4 = *(const float4*)(vbase + (size_t)(t0 + r) * 3072 + c4);
            *(float4*)&vb[r][c4] = vv4;
        }
        __syncthreads();
#pragma unroll 8
        for (int r = 0; r < 32; r++) {
            float kd = kb[r][d];
            zacc += kd;
#pragma unroll
            for (int j = 0; j < 16; j++) acc[j] += kd * vb[r][e0 + j];
        }
        __syncthreads();
    }

    float* kvp = g_kvz + (size_t)bh * 4160;
#pragma unroll
    for (int j = 0; j < 16; j++) atomicAdd(&kvp[d * 64 + e0 + j], acc[j]);
    if ((tid & 3) == 0) atomicAdd(&kvp[4096 + d], zacc);
}

__global__ void zero_kvz_kernel()
{
    int i = blockIdx.x * 256 + threadIdx.x;
    if (i < 64 * 4160) g_kvz[i] = 0.f;
}

// ---------------- attention: y = (qf @ kv) / max(qf.z, eps) -----------------
// grid (64 bh, 32 chunks of 128 tokens), 128 threads (1 token / thread)
__global__ void __launch_bounds__(128)
attn_y_kernel(const float* __restrict__ qkv, float* __restrict__ y)
{
    int bh = blockIdx.x;
    int b = bh >> 4, h = bh & 15;
    int chunk = blockIdx.y;
    int tid = threadIdx.x;

    __shared__ float kvs[4096];
    __shared__ float zs[64];
    const float* kvp = g_kvz + (size_t)bh * 4160;
    for (int i = tid; i < 4160; i += 128) {
        float v = kvp[i];
        if (i < 4096) kvs[i] = v; else zs[i - 4096] = v;
    }
    __syncthreads();

    int row = b * 4096 + chunk * 128 + tid;
    const float* qp = qkv + (size_t)row * 3072 + h * 64;
    float qf[64];
#pragma unroll
    for (int i = 0; i < 16; i++) {
        float4 v = *(const float4*)(qp + i * 4);
        qf[i * 4 + 0] = phi(v.x);
        qf[i * 4 + 1] = phi(v.y);
        qf[i * 4 + 2] = phi(v.z);
        qf[i * 4 + 3] = phi(v.w);
    }
    float den = 0.f;
#pragma unroll
    for (int d2 = 0; d2 < 64; d2++) den += qf[d2] * zs[d2];
    den = fmaxf(den, 1e-6f);
    float inv = 1.f / den;

    float* yp = y + (size_t)row * 1024 + h * 64;
#pragma unroll
    for (int eg = 0; eg < 16; eg++) {
        float a0 = 0.f, a1 = 0.f, a2 = 0.f, a3 = 0.f;
#pragma unroll
        for (int d2 = 0; d2 < 64; d2++) {
            float q = qf[d2];
            const float* kr = kvs + d2 * 64 + eg * 4;
            a0 += q * kr[0]; a1 += q * kr[1];
            a2 += q * kr[2]; a3 += q * kr[3];
        }
        float4 o = make_float4(a0 * inv, a1 * inv, a2 * inv, a3 * inv);
        *(float4*)(yp + eg * 4) = o;
    }
}

// ---------------- launch ----------------------------------------------------
extern "C" void kernel_launch(void* const* d_in, const int* in_sizes, int n_in,
                              void* d_out, int out_size)
{
    (void)in_sizes; (void)n_in; (void)out_size;
    const float* src   = (const float*)d_in[0];
    const float* qkv_w = (const float*)d_in[1];
    const float* qkv_b = (const float*)d_in[2];
    const float* out_w = (const float*)d_in[3];
    const float* out_b = (const float*)d_in[4];
    const float* w1    = (const float*)d_in[5];
    const float* b1    = (const float*)d_in[6];
    const float* w2    = (const float*)d_in[7];
    const float* b2    = (const float*)d_in[8];
    const float* g1    = (const float*)d_in[9];
    const float* be1   = (const float*)d_in[10];
    const float* g2    = (const float*)d_in[11];
    const float* be2   = (const float*)d_in[12];
    float* out = (float*)d_out;

    float *xln, *qkv, *attny, *x, *h;
    cudaGetSymbolAddress((void**)&xln,   g_xln);
    cudaGetSymbolAddress((void**)&qkv,   g_qkv);
    cudaGetSymbolAddress((void**)&attny, g_attny);
    cudaGetSymbolAddress((void**)&x,     g_x);
    cudaGetSymbolAddress((void**)&h,     g_h);
    float* hln = xln;   // xln dead after QKV GEMM; reuse for LN2 output

    // 1. LN1
    ln_kernel<<<TOK, 256>>>(src, g1, be1, xln);
    // 2. qkv = xln @ qkv_w + qkv_b
    gemm_tf32_kernel<<<dim3(3 * DM / BN, TOK / BM), 256>>>(
        xln, qkv_w, qkv_b, nullptr, qkv, TOK, 3 * DM, DM, 0);
    // 3-5. linear attention
    zero_kvz_kernel<<<(64 * 4160 + 255) / 256, 256>>>();
    attn_kv_kernel<<<dim3(64, 32), 256>>>(qkv);
    attn_y_kernel<<<dim3(64, 32), 128>>>(qkv, attny);
    // 6. x = src + attny @ out_w + out_b
    gemm_tf32_kernel<<<dim3(DM / BN, TOK / BM), 256>>>(
        attny, out_w, out_b, src, x, TOK, DM, DM, 1);
    // 7. LN2
    ln_kernel<<<TOK, 256>>>(x, g2, be2, hln);
    // 8. h = gelu(hln @ w1 + b1)
    gemm_tf32_kernel<<<dim3(DFF / BN, TOK / BM), 256>>>(
        hln, w1, b1, nullptr, h, TOK, DFF, DM, 2);
    // 9. out = x + h @ w2 + b2
    gemm_tf32_kernel<<<dim3(DM / BN, TOK / BM), 256>>>(
        h, w2, b2, x, out, TOK, DM, DFF, 1);
}

// round 4
// speedup vs baseline: 1.7346x; 1.7346x over previous
#include <cuda_runtime.h>
#include <math.h>
#include <stdint.h>

#define TOK   16384
#define DM    1024
#define DFF   4096
#define NH    16
#define HD    64

// ---------------- scratch (static device allocations; no cudaMalloc) --------
__device__ float g_xln  [(size_t)TOK * DM];        // 64 MB (reused as hln)
__device__ float g_qkv  [(size_t)TOK * 3 * DM];    // 192 MB
__device__ float g_kvz  [64 * 4160];               // per (b,h): 64x64 kv + 64 z
__device__ float g_attny[(size_t)TOK * DM];        // 64 MB
__device__ float g_x    [(size_t)TOK * DM];        // 64 MB
__device__ float g_h    [(size_t)TOK * DFF];       // 256 MB
// tf32-preconverted weights
__device__ float g_wq   [(size_t)DM * 3 * DM];     // 12 MB
__device__ float g_wo   [(size_t)DM * DM];         // 4 MB
__device__ float g_w1   [(size_t)DM * DFF];        // 16 MB
__device__ float g_w2   [(size_t)DFF * DM];        // 16 MB

// ---------------- helpers ---------------------------------------------------
__device__ __forceinline__ float to_tf32(float x) {
    unsigned u;
    asm("cvt.rna.tf32.f32 %0, %1;" : "=r"(u) : "f"(x));
    return __uint_as_float(u);
}

__device__ __forceinline__ float phi(float x) {           // elu(x)+1
    return x > 0.f ? x + 1.f : expf(x);
}

__device__ __forceinline__ float gelu_exact(float x) {
    return 0.5f * x * (1.f + erff(x * 0.70710678118654752440f));
}

__device__ __forceinline__ void mma_tf32(float* d, const unsigned* a, const unsigned* b) {
    asm volatile(
        "mma.sync.aligned.m16n8k8.row.col.f32.tf32.tf32.f32 "
        "{%0,%1,%2,%3}, {%4,%5,%6,%7}, {%8,%9}, {%0,%1,%2,%3};\n"
        : "+f"(d[0]), "+f"(d[1]), "+f"(d[2]), "+f"(d[3])
        : "r"(a[0]), "r"(a[1]), "r"(a[2]), "r"(a[3]), "r"(b[0]), "r"(b[1]));
}

__device__ __forceinline__ void cp16(void* dst, const void* src) {
    unsigned d = (unsigned)__cvta_generic_to_shared(dst);
    asm volatile("cp.async.cg.shared.global [%0], [%1], 16;\n" :: "r"(d), "l"(src));
}
__device__ __forceinline__ void cp_commit() {
    asm volatile("cp.async.commit_group;\n");
}
template<int N> __device__ __forceinline__ void cp_wait() {
    asm volatile("cp.async.wait_group %0;\n" :: "n"(N));
}

// ---------------- weight preconvert -----------------------------------------
__global__ void __launch_bounds__(256)
cvt_tf32_kernel(const float* __restrict__ in, float* __restrict__ out, int n4)
{
    int i = blockIdx.x * 256 + threadIdx.x;
    if (i < n4) {
        float4 v = ((const float4*)in)[i];
        v.x = to_tf32(v.x); v.y = to_tf32(v.y);
        v.z = to_tf32(v.z); v.w = to_tf32(v.w);
        ((float4*)out)[i] = v;
    }
}

// ---------------- LayerNorm (tf32-rounded output) ---------------------------
__global__ void __launch_bounds__(256)
ln_kernel(const float* __restrict__ x, const float* __restrict__ g,
          const float* __restrict__ b, float* __restrict__ y)
{
    int row = blockIdx.x;
    int tid = threadIdx.x;
    const float4* xr = (const float4*)(x + (size_t)row * DM);
    float4 v = xr[tid];
    float s = v.x + v.y + v.z + v.w;
    float q = v.x * v.x + v.y * v.y + v.z * v.z + v.w * v.w;
#pragma unroll
    for (int o = 16; o; o >>= 1) {
        s += __shfl_xor_sync(0xffffffffu, s, o);
        q += __shfl_xor_sync(0xffffffffu, q, o);
    }
    __shared__ float ss[8], sq[8];
    __shared__ float smu, srs;
    int warp = tid >> 5, lane = tid & 31;
    if (!lane) { ss[warp] = s; sq[warp] = q; }
    __syncthreads();
    if (!tid) {
        float S = 0.f, Q = 0.f;
#pragma unroll
        for (int i = 0; i < 8; i++) { S += ss[i]; Q += sq[i]; }
        float mu = S * (1.f / DM);
        float var = Q * (1.f / DM) - mu * mu;
        smu = mu;
        srs = rsqrtf(var + 1e-5f);
    }
    __syncthreads();
    float mu = smu, rs = srs;
    float4 gv = ((const float4*)g)[tid];
    float4 bv = ((const float4*)b)[tid];
    float4 o;
    o.x = to_tf32((v.x - mu) * rs * gv.x + bv.x);
    o.y = to_tf32((v.y - mu) * rs * gv.y + bv.y);
    o.z = to_tf32((v.z - mu) * rs * gv.z + bv.z);
    o.w = to_tf32((v.w - mu) * rs * gv.w + bv.w);
    ((float4*)(y + (size_t)row * DM))[tid] = o;
}

// ---------------- tf32 tensor-core GEMM, 2-stage cp.async pipeline ----------
// C[M,N] = A[M,K] @ B[K,N] + bias  (+resid | gelu)
// Block tile 128x128x32, 256 threads (8 warps: 4(m) x 2(n)), warp tile 32x64.
// A and B must already be tf32-rounded values (producers round on store).
#define BM 128
#define BN 128
#define BK 32
#define AS_W 36            // padded row for A tile [BM][AS_W] (16B-aligned rows)
#define BS_W 136           // padded row for B tile [BK][BS_W]
#define STAGE_FLOATS (BM * AS_W + BK * BS_W)   // 8960 floats = 35840 B
#define GEMM_SMEM (2 * STAGE_FLOATS * 4)       // 71680 B

__global__ void __launch_bounds__(256, 2)
gemm_tf32_kernel(const float* __restrict__ A, const float* __restrict__ B,
                 const float* __restrict__ bias, const float* __restrict__ resid,
                 float* __restrict__ C, int M, int N, int K, int epi)
{
    extern __shared__ float sm[];

    int tid  = threadIdx.x;
    int bm   = blockIdx.y * BM;
    int bn   = blockIdx.x * BN;
    int warp = tid >> 5, lane = tid & 31;
    int wm   = warp >> 1, wn = warp & 1;
    int gid  = lane >> 2, tig = lane & 3;

    float acc[2][8][4];
#pragma unroll
    for (int i = 0; i < 2; i++)
#pragma unroll
        for (int j = 0; j < 8; j++)
#pragma unroll
            for (int l = 0; l < 4; l++) acc[i][j][l] = 0.f;

    const float* Aptr = A + (size_t)bm * K;
    const float* Bptr = B + bn;

    // precomputed staging coordinates
    int am = tid >> 3,        akc = (tid & 7) << 2;    // A: 8 threads/row
    int br = tid >> 5,        bnc = (tid & 31) << 2;   // B: 32 threads/row

    int ktiles = K / BK;

    // ---- prefetch tile 0 ----
    {
        float* As = sm;
        float* Bs = sm + BM * AS_W;
#pragma unroll
        for (int i = 0; i < 4; i++) {
            int m = am + i * 32;
            cp16(&As[m * AS_W + akc], Aptr + (size_t)m * K + akc);
        }
#pragma unroll
        for (int i = 0; i < 4; i++) {
            int r = br + i * 8;
            cp16(&Bs[r * BS_W + bnc], Bptr + (size_t)r * N + bnc);
        }
        cp_commit();
    }

    for (int t = 0; t < ktiles; t++) {
        int cur = t & 1;
        if (t + 1 < ktiles) {
            int k0 = (t + 1) * BK;
            float* As = sm + (cur ^ 1) * STAGE_FLOATS;
            float* Bs = As + BM * AS_W;
#pragma unroll
            for (int i = 0; i < 4; i++) {
                int m = am + i * 32;
                cp16(&As[m * AS_W + akc], Aptr + (size_t)m * K + k0 + akc);
            }
#pragma unroll
            for (int i = 0; i < 4; i++) {
                int r = br + i * 8;
                cp16(&Bs[r * BS_W + bnc], Bptr + (size_t)(k0 + r) * N + bnc);
            }
            cp_commit();
            cp_wait<1>();
        } else {
            cp_wait<0>();
        }
        __syncthreads();

        const float* As = sm + cur * STAGE_FLOATS;
        const float* Bs = As + BM * AS_W;

#pragma unroll
        for (int kk = 0; kk < BK; kk += 8) {
            unsigned a[2][4], b[8][2];
            int ar = kk + tig;
#pragma unroll
            for (int mf = 0; mf < 2; mf++) {
                int m0 = wm * 32 + mf * 16 + gid;
                a[mf][0] = __float_as_uint(As[(m0    ) * AS_W + ar    ]);
                a[mf][1] = __float_as_uint(As[(m0 + 8) * AS_W + ar    ]);
                a[mf][2] = __float_as_uint(As[(m0    ) * AS_W + ar + 4]);
                a[mf][3] = __float_as_uint(As[(m0 + 8) * AS_W + ar + 4]);
            }
#pragma unroll
            for (int nf = 0; nf < 8; nf++) {
                int n0 = wn * 64 + nf * 8 + gid;
                b[nf][0] = __float_as_uint(Bs[(ar    ) * BS_W + n0]);
                b[nf][1] = __float_as_uint(Bs[(ar + 4) * BS_W + n0]);
            }
#pragma unroll
            for (int mf = 0; mf < 2; mf++)
#pragma unroll
                for (int nf = 0; nf < 8; nf++)
                    mma_tf32(acc[mf][nf], a[mf], b[nf]);
        }
        __syncthreads();
    }

    // ---- epilogue: bias + (none | +resid | gelu(tf32)), float2 stores ------
#pragma unroll
    for (int mf = 0; mf < 2; mf++) {
#pragma unroll
        for (int nf = 0; nf < 8; nf++) {
            int r = bm + wm * 32 + mf * 16 + gid;
            int c = bn + wn * 64 + nf * 8 + tig * 2;
            float bx = bias[c], by = bias[c + 1];
            float2 v0 = make_float2(acc[mf][nf][0] + bx, acc[mf][nf][1] + by);
            float2 v1 = make_float2(acc[mf][nf][2] + bx, acc[mf][nf][3] + by);
            if (epi == 1) {
                const float* r0 = resid + (size_t)r * N + c;
                const float* r1 = resid + (size_t)(r + 8) * N + c;
                v0.x += r0[0]; v0.y += r0[1];
                v1.x += r1[0]; v1.y += r1[1];
            } else if (epi == 2) {
                v0.x = to_tf32(gelu_exact(v0.x)); v0.y = to_tf32(gelu_exact(v0.y));
                v1.x = to_tf32(gelu_exact(v1.x)); v1.y = to_tf32(gelu_exact(v1.y));
            }
            *(float2*)(C + (size_t)r * N + c)       = v0;
            *(float2*)(C + (size_t)(r + 8) * N + c) = v1;
        }
    }
}

// ---------------- attention: kv & z accumulation ----------------------------
// grid (64 bh, 8 chunks of 512 rows), 256 threads
// thread = (d-pair p = tid>>3, e-group g = tid&7): 2 d x 8 e accumulators
__global__ void __launch_bounds__(256)
attn_kv_kernel(const float* __restrict__ qkv)
{
    int bh = blockIdx.x;
    int b = bh >> 4, h = bh & 15;
    int chunk = blockIdx.y;
    int row0 = b * 4096 + chunk * 512;
    const float* kbase = qkv + (size_t)row0 * 3072 + 1024 + h * 64;
    const float* vbase = qkv + (size_t)row0 * 3072 + 2048 + h * 64;

    __shared__ float kb[32][64];
    __shared__ float vb[32][72];

    int tid = threadIdx.x;
    int d0 = (tid >> 3) * 2;
    int e0 = (tid & 7) * 8;
    float acc[16];
#pragma unroll
    for (int j = 0; j < 16; j++) acc[j] = 0.f;
    float z0 = 0.f, z1 = 0.f;

    for (int t0 = 0; t0 < 512; t0 += 32) {
#pragma unroll
        for (int i = 0; i < 2; i++) {
            int e = tid + i * 256;                 // 0..511 float4 chunks
            int r = e >> 4, c4 = (e & 15) << 2;
            float4 kv4 = *(const float4*)(kbase + (size_t)(t0 + r) * 3072 + c4);
            kb[r][c4 + 0] = phi(kv4.x);
            kb[r][c4 + 1] = phi(kv4.y);
            kb[r][c4 + 2] = phi(kv4.z);
            kb[r][c4 + 3] = phi(kv4.w);
            float4 vv4 = *(const float4*)(vbase + (size_t)(t0 + r) * 3072 + c4);
            *(float4*)&vb[r][c4] = vv4;
        }
        __syncthreads();
#pragma unroll 8
        for (int r = 0; r < 32; r++) {
            float2 kd = *(const float2*)&kb[r][d0];
            float4 v0 = *(const float4*)&vb[r][e0];
            float4 v1 = *(const float4*)&vb[r][e0 + 4];
            acc[0]  += kd.x * v0.x;  acc[1]  += kd.x * v0.y;
            acc[2]  += kd.x * v0.z;  acc[3]  += kd.x * v0.w;
            acc[4]  += kd.x * v1.x;  acc[5]  += kd.x * v1.y;
            acc[6]  += kd.x * v1.z;  acc[7]  += kd.x * v1.w;
            acc[8]  += kd.y * v0.x;  acc[9]  += kd.y * v0.y;
            acc[10] += kd.y * v0.z;  acc[11] += kd.y * v0.w;
            acc[12] += kd.y * v1.x;  acc[13] += kd.y * v1.y;
            acc[14] += kd.y * v1.z;  acc[15] += kd.y * v1.w;
            z0 += kd.x; z1 += kd.y;
        }
        __syncthreads();
    }

    float* kvp = g_kvz + (size_t)bh * 4160;
#pragma unroll
    for (int j = 0; j < 8; j++) atomicAdd(&kvp[(d0    ) * 64 + e0 + j], acc[j]);
#pragma unroll
    for (int j = 0; j < 8; j++) atomicAdd(&kvp[(d0 + 1) * 64 + e0 + j], acc[8 + j]);
    if ((tid & 7) == 0) {
        atomicAdd(&kvp[4096 + d0], z0);
        atomicAdd(&kvp[4096 + d0 + 1], z1);
    }
}

__global__ void zero_kvz_kernel()
{
    int i = blockIdx.x * 256 + threadIdx.x;
    if (i < 64 * 4160) g_kvz[i] = 0.f;
}

// ---------------- attention: y = (qf @ kv) / max(qf.z, eps) -----------------
// grid (64 bh, 32 chunks of 128 tokens), 128 threads (1 token / thread)
__global__ void __launch_bounds__(128)
attn_y_kernel(const float* __restrict__ qkv, float* __restrict__ y)
{
    int bh = blockIdx.x;
    int b = bh >> 4, h = bh & 15;
    int chunk = blockIdx.y;
    int tid = threadIdx.x;

    __shared__ float kvs[4096];
    __shared__ float zs[64];
    const float* kvp = g_kvz + (size_t)bh * 4160;
    for (int i = tid; i < 4160; i += 128) {
        float v = kvp[i];
        if (i < 4096) kvs[i] = v; else zs[i - 4096] = v;
    }
    __syncthreads();

    int row = b * 4096 + chunk * 128 + tid;
    const float* qp = qkv + (size_t)row * 3072 + h * 64;
    float qf[64];
#pragma unroll
    for (int i = 0; i < 16; i++) {
        float4 v = *(const float4*)(qp + i * 4);
        qf[i * 4 + 0] = phi(v.x);
        qf[i * 4 + 1] = phi(v.y);
        qf[i * 4 + 2] = phi(v.z);
        qf[i * 4 + 3] = phi(v.w);
    }
    float den = 0.f;
#pragma unroll
    for (int d2 = 0; d2 < 64; d2++) den += qf[d2] * zs[d2];
    den = fmaxf(den, 1e-6f);
    float inv = 1.f / den;

    float* yp = y + (size_t)row * 1024 + h * 64;
#pragma unroll
    for (int eg = 0; eg < 16; eg++) {
        float a0 = 0.f, a1 = 0.f, a2 = 0.f, a3 = 0.f;
#pragma unroll
        for (int d2 = 0; d2 < 64; d2++) {
            float q = qf[d2];
            const float* kr = kvs + d2 * 64 + eg * 4;
            a0 += q * kr[0]; a1 += q * kr[1];
            a2 += q * kr[2]; a3 += q * kr[3];
        }
        float4 o = make_float4(to_tf32(a0 * inv), to_tf32(a1 * inv),
                               to_tf32(a2 * inv), to_tf32(a3 * inv));
        *(float4*)(yp + eg * 4) = o;
    }
}

// ---------------- launch ----------------------------------------------------
extern "C" void kernel_launch(void* const* d_in, const int* in_sizes, int n_in,
                              void* d_out, int out_size)
{
    (void)in_sizes; (void)n_in; (void)out_size;
    const float* src   = (const float*)d_in[0];
    const float* qkv_w = (const float*)d_in[1];
    const float* qkv_b = (const float*)d_in[2];
    const float* out_w = (const float*)d_in[3];
    const float* out_b = (const float*)d_in[4];
    const float* w1    = (const float*)d_in[5];
    const float* b1    = (const float*)d_in[6];
    const float* w2    = (const float*)d_in[7];
    const float* b2    = (const float*)d_in[8];
    const float* g1    = (const float*)d_in[9];
    const float* be1   = (const float*)d_in[10];
    const float* g2    = (const float*)d_in[11];
    const float* be2   = (const float*)d_in[12];
    float* out = (float*)d_out;

    float *xln, *qkv, *attny, *x, *h, *wq, *wo, *w1c, *w2c;
    cudaGetSymbolAddress((void**)&xln,   g_xln);
    cudaGetSymbolAddress((void**)&qkv,   g_qkv);
    cudaGetSymbolAddress((void**)&attny, g_attny);
    cudaGetSymbolAddress((void**)&x,     g_x);
    cudaGetSymbolAddress((void**)&h,     g_h);
    cudaGetSymbolAddress((void**)&wq,    g_wq);
    cudaGetSymbolAddress((void**)&wo,    g_wo);
    cudaGetSymbolAddress((void**)&w1c,   g_w1);
    cudaGetSymbolAddress((void**)&w2c,   g_w2);
    float* hln = xln;   // xln dead after QKV GEMM; reuse for LN2 output

    cudaFuncSetAttribute(gemm_tf32_kernel,
                         cudaFuncAttributeMaxDynamicSharedMemorySize, GEMM_SMEM);

    // 0. preconvert weights to tf32 (idempotent)
    cvt_tf32_kernel<<<(3 * DM * DM / 4 + 255) / 256, 256>>>(qkv_w, wq,  3 * DM * DM / 4);
    cvt_tf32_kernel<<<(DM * DM / 4 + 255) / 256, 256>>>(out_w, wo,  DM * DM / 4);
    cvt_tf32_kernel<<<(DM * DFF / 4 + 255) / 256, 256>>>(w1,    w1c, DM * DFF / 4);
    cvt_tf32_kernel<<<(DFF * DM / 4 + 255) / 256, 256>>>(w2,    w2c, DFF * DM / 4);

    // 1. LN1 (tf32-rounded output)
    ln_kernel<<<TOK, 256>>>(src, g1, be1, xln);
    // 2. qkv = xln @ qkv_w + qkv_b
    gemm_tf32_kernel<<<dim3(3 * DM / BN, TOK / BM), 256, GEMM_SMEM>>>(
        xln, wq, qkv_b, nullptr, qkv, TOK, 3 * DM, DM, 0);
    // 3-5. linear attention
    zero_kvz_kernel<<<(64 * 4160 + 255) / 256, 256>>>();
    attn_kv_kernel<<<dim3(64, 8), 256>>>(qkv);
    attn_y_kernel<<<dim3(64, 32), 128>>>(qkv, attny);
    // 6. x = src + attny @ out_w + out_b
    gemm_tf32_kernel<<<dim3(DM / BN, TOK / BM), 256, GEMM_SMEM>>>(
        attny, wo, out_b, src, x, TOK, DM, DM, 1);
    // 7. LN2
    ln_kernel<<<TOK, 256>>>(x, g2, be2, hln);
    // 8. h = gelu(hln @ w1 + b1)  (tf32-rounded output)
    gemm_tf32_kernel<<<dim3(DFF / BN, TOK / BM), 256, GEMM_SMEM>>>(
        hln, w1c, b1, nullptr, h, TOK, DFF, DM, 2);
    // 9. out = x + h @ w2 + b2
    gemm_tf32_kernel<<<dim3(DM / BN, TOK / BM), 256, GEMM_SMEM>>>(
        h, w2c, b2, x, out, TOK, DM, DFF, 1);
}

// round 9
// speedup vs baseline: 2.1437x; 1.2359x over previous
#include <cuda_runtime.h>
#include <cuda_fp16.h>
#include <math.h>
#include <stdint.h>

#define TOK   16384
#define DM    1024
#define DFF   4096
#define NH    16
#define HD    64

// ---------------- scratch (static device allocations; no cudaMalloc) --------
__device__ float g_xln  [(size_t)TOK * DM];        // used as half buffer (ln out)
__device__ float g_qkv  [(size_t)TOK * 3 * DM];    // fp32
__device__ float g_kvz  [64 * 4160];
__device__ float g_attny[(size_t)TOK * DM];        // used as half buffer
__device__ float g_x    [(size_t)TOK * DM];        // fp32
__device__ float g_h    [(size_t)TOK * DFF];       // used as half buffer
// half, TRANSPOSED weights [N][K]
__device__ float g_wq   [(size_t)3 * DM * DM / 2];
__device__ float g_wo   [(size_t)DM * DM / 2];
__device__ float g_w1   [(size_t)DFF * DM / 2];
__device__ float g_w2   [(size_t)DM * DFF / 2];

// ---------------- helpers ---------------------------------------------------
__device__ __forceinline__ uint32_t smem_u32(const void* p) {
    uint32_t a;
    asm("{ .reg .u64 t; cvta.to.shared.u64 t, %1; cvt.u32.u64 %0, t; }" : "=r"(a) : "l"(p));
    return a;
}
__device__ __forceinline__ float phi(float x) { return x > 0.f ? x + 1.f : expf(x); }
__device__ __forceinline__ float gelu_exact(float x) {
    return 0.5f * x * (1.f + erff(x * 0.70710678118654752440f));
}
__device__ __forceinline__ void cp16s(uint32_t dst, const void* src) {
    asm volatile("cp.async.cg.shared.global [%0], [%1], 16;\n" :: "r"(dst), "l"(src));
}
__device__ __forceinline__ void cp_commit() { asm volatile("cp.async.commit_group;\n"); }
template<int N> __device__ __forceinline__ void cp_wait() {
    asm volatile("cp.async.wait_group %0;\n" :: "n"(N));
}
__device__ __forceinline__ void mma_f16(float* d, const unsigned* a, const unsigned* b) {
    asm volatile(
        "mma.sync.aligned.m16n8k16.row.col.f32.f16.f16.f32 "
        "{%0,%1,%2,%3}, {%4,%5,%6,%7}, {%8,%9}, {%0,%1,%2,%3};\n"
        : "+f"(d[0]), "+f"(d[1]), "+f"(d[2]), "+f"(d[3])
        : "r"(a[0]), "r"(a[1]), "r"(a[2]), "r"(a[3]), "r"(b[0]), "r"(b[1]));
}

// ---------------- weight transpose + fp16 round ------------------------------
// out[n][k] = half(in[k][n]); grid (N/32, K/32), block (32,8)
__global__ void __launch_bounds__(256)
transpose_h_kernel(const float* __restrict__ in, __half* __restrict__ out, int K, int N)
{
    __shared__ float tile[32][33];
    int n0 = blockIdx.x * 32, k0 = blockIdx.y * 32;
#pragma unroll
    for (int i = threadIdx.y; i < 32; i += 8)
        tile[i][threadIdx.x] = in[(size_t)(k0 + i) * N + n0 + threadIdx.x];
    __syncthreads();
#pragma unroll
    for (int i = threadIdx.y; i < 32; i += 8)
        out[(size_t)(n0 + i) * K + k0 + threadIdx.x] = __float2half_rn(tile[threadIdx.x][i]);
}

// ---------------- LayerNorm (half output) ------------------------------------
__global__ void __launch_bounds__(256)
ln_kernel(const float* __restrict__ x, const float* __restrict__ g,
          const float* __restrict__ b, __half* __restrict__ y)
{
    int row = blockIdx.x;
    int tid = threadIdx.x;
    const float4* xr = (const float4*)(x + (size_t)row * DM);
    float4 v = xr[tid];
    float s = v.x + v.y + v.z + v.w;
    float q = v.x * v.x + v.y * v.y + v.z * v.z + v.w * v.w;
#pragma unroll
    for (int o = 16; o; o >>= 1) {
        s += __shfl_xor_sync(0xffffffffu, s, o);
        q += __shfl_xor_sync(0xffffffffu, q, o);
    }
    __shared__ float ss[8], sq[8];
    __shared__ float smu, srs;
    int warp = tid >> 5, lane = tid & 31;
    if (!lane) { ss[warp] = s; sq[warp] = q; }
    __syncthreads();
    if (!tid) {
        float S = 0.f, Q = 0.f;
#pragma unroll
        for (int i = 0; i < 8; i++) { S += ss[i]; Q += sq[i]; }
        float mu = S * (1.f / DM);
        float var = Q * (1.f / DM) - mu * mu;
        smu = mu;
        srs = rsqrtf(var + 1e-5f);
    }
    __syncthreads();
    float mu = smu, rs = srs;
    float4 gv = ((const float4*)g)[tid];
    float4 bv = ((const float4*)b)[tid];
    __half2 h01 = __floats2half2_rn((v.x - mu) * rs * gv.x + bv.x,
                                    (v.y - mu) * rs * gv.y + bv.y);
    __half2 h23 = __floats2half2_rn((v.z - mu) * rs * gv.z + bv.z,
                                    (v.w - mu) * rs * gv.w + bv.w);
    uint2 u;
    u.x = *(uint32_t*)&h01;
    u.y = *(uint32_t*)&h23;
    ((uint2*)(y + (size_t)row * DM))[tid] = u;
}

// ---------------- fp16 tensor-core GEMM, 3-stage cp.async pipeline -----------
// C[M,N] = A[M,K] @ BT[N,K]^T + bias (+resid | gelu->half)
// Block 128x128xBK32(halves); 8 warps: 4(m) x 2(n); warp tile 32x64.
// smem rows padded to 80B -> LDS bank-conflict-free fragment loads.
#define BM 128
#define BN 128
#define BKH 32
#define ROW_B 80
#define HALF_TILE_B (128 * ROW_B)              // 10240
#define STAGE_B (2 * HALF_TILE_B)              // 20480
#define GSMEM (3 * STAGE_B)                    // 61440

__global__ void __launch_bounds__(256, 2)
gemm_h_kernel(const __half* __restrict__ A, const __half* __restrict__ BT,
              const float* __restrict__ bias, const float* __restrict__ resid,
              void* __restrict__ Cv, int N, int K, int epi)
{
    extern __shared__ char smem[];
    uint32_t sb = smem_u32(smem);

    int tid  = threadIdx.x;
    int bm   = blockIdx.y * BM;
    int bn   = blockIdx.x * BN;
    int warp = tid >> 5, lane = tid & 31;
    int wm   = warp >> 1, wn = warp & 1;
    int gid  = lane >> 2, tig = lane & 3;

    float acc[2][8][4];
#pragma unroll
    for (int i = 0; i < 2; i++)
#pragma unroll
        for (int j = 0; j < 8; j++)
#pragma unroll
            for (int l = 0; l < 4; l++) acc[i][j][l] = 0.f;

    // staging: thread -> row tid>>1, half-offset (tid&1)*16; 2 cp16 for A, 2 for B
    int srow = tid >> 1;
    int shalf = (tid & 1) * 16;
    uint32_t soff = (uint32_t)srow * ROW_B + (tid & 1) * 32;
    const __half* ag = A + (size_t)(bm + srow) * K + shalf;
    const __half* bg = BT + (size_t)(bn + srow) * K + shalf;

    int T = K / BKH;

#define LOAD_STAGE(t, s) do { \
    uint32_t base = sb + (uint32_t)(s) * STAGE_B; \
    const __half* ap = ag + (size_t)(t) * BKH; \
    const __half* bp = bg + (size_t)(t) * BKH; \
    cp16s(base + soff,                    ap); \
    cp16s(base + soff + 16,               ap + 8); \
    cp16s(base + HALF_TILE_B + soff,      bp); \
    cp16s(base + HALF_TILE_B + soff + 16, bp + 8); \
} while (0)

    LOAD_STAGE(0, 0); cp_commit();
    LOAD_STAGE(1, 1); cp_commit();

    const char* smc = (const char*)smem;

    for (int t = 0; t < T; t++) {
        if (t + 2 < T) { LOAD_STAGE(t + 2, (t + 2) % 3); }
        cp_commit();
        cp_wait<2>();
        __syncthreads();

        const char* ab = smc + (t % 3) * STAGE_B;
        const char* bb = ab + HALF_TILE_B;

#pragma unroll
        for (int kk = 0; kk < 2; kk++) {     // two k16 slices of the 32-half tile
            unsigned a[2][4], b[8][2];
            int kb = kk * 32 + tig * 4;      // byte offset of this thread's k pair
#pragma unroll
            for (int mf = 0; mf < 2; mf++) {
                int m0 = wm * 32 + mf * 16 + gid;
                const char* ar = ab + m0 * ROW_B + kb;
                a[mf][0] = *(const uint32_t*)(ar);
                a[mf][1] = *(const uint32_t*)(ar + 8 * ROW_B);
                a[mf][2] = *(const uint32_t*)(ar + 16);
                a[mf][3] = *(const uint32_t*)(ar + 8 * ROW_B + 16);
            }
#pragma unroll
            for (int nf = 0; nf < 8; nf++) {
                int n0 = wn * 64 + nf * 8 + gid;
                const char* br = bb + n0 * ROW_B + kb;
                b[nf][0] = *(const uint32_t*)(br);
                b[nf][1] = *(const uint32_t*)(br + 16);
            }
#pragma unroll
            for (int mf = 0; mf < 2; mf++)
#pragma unroll
                for (int nf = 0; nf < 8; nf++)
                    mma_f16(acc[mf][nf], a[mf], b[nf]);
        }
        __syncthreads();
    }

    // ---- epilogue ----
    float* Cf = (float*)Cv;
    __half* Ch = (__half*)Cv;
#pragma unroll
    for (int mf = 0; mf < 2; mf++) {
#pragma unroll
        for (int nf = 0; nf < 8; nf++) {
            int r = bm + wm * 32 + mf * 16 + gid;
            int c = bn + wn * 64 + nf * 8 + tig * 2;
            float bx = bias[c], by = bias[c + 1];
            float2 v0 = make_float2(acc[mf][nf][0] + bx, acc[mf][nf][1] + by);
            float2 v1 = make_float2(acc[mf][nf][2] + bx, acc[mf][nf][3] + by);
            if (epi == 1) {
                const float* r0 = resid + (size_t)r * N + c;
                const float* r1 = resid + (size_t)(r + 8) * N + c;
                v0.x += r0[0]; v0.y += r0[1];
                v1.x += r1[0]; v1.y += r1[1];
            }
            if (epi == 2) {
                __half2 h0 = __floats2half2_rn(gelu_exact(v0.x), gelu_exact(v0.y));
                __half2 h1 = __floats2half2_rn(gelu_exact(v1.x), gelu_exact(v1.y));
                *(__half2*)(Ch + (size_t)r * N + c)       = h0;
                *(__half2*)(Ch + (size_t)(r + 8) * N + c) = h1;
            } else {
                *(float2*)(Cf + (size_t)r * N + c)       = v0;
                *(float2*)(Cf + (size_t)(r + 8) * N + c) = v1;
            }
        }
    }
}

// ---------------- attention: kv & z accumulation (fp32 qkv) -----------------
__global__ void __launch_bounds__(256)
attn_kv_kernel(const float* __restrict__ qkv)
{
    int bh = blockIdx.x;
    int b = bh >> 4, h = bh & 15;
    int chunk = blockIdx.y;
    int row0 = b * 4096 + chunk * 512;
    const float* kbase = qkv + (size_t)row0 * 3072 + 1024 + h * 64;
    const float* vbase = qkv + (size_t)row0 * 3072 + 2048 + h * 64;

    __shared__ float kb[32][64];
    __shared__ float vb[32][72];

    int tid = threadIdx.x;
    int d0 = (tid >> 3) * 2;
    int e0 = (tid & 7) * 8;
    float acc[16];
#pragma unroll
    for (int j = 0; j < 16; j++) acc[j] = 0.f;
    float z0 = 0.f, z1 = 0.f;

    for (int t0 = 0; t0 < 512; t0 += 32) {
#pragma unroll
        for (int i = 0; i < 2; i++) {
            int e = tid + i * 256;
            int r = e >> 4, c4 = (e & 15) << 2;
            float4 kv4 = *(const float4*)(kbase + (size_t)(t0 + r) * 3072 + c4);
            kb[r][c4 + 0] = phi(kv4.x);
            kb[r][c4 + 1] = phi(kv4.y);
            kb[r][c4 + 2] = phi(kv4.z);
            kb[r][c4 + 3] = phi(kv4.w);
            float4 vv4 = *(const float4*)(vbase + (size_t)(t0 + r) * 3072 + c4);
            *(float4*)&vb[r][c4] = vv4;
        }
        __syncthreads();
#pragma unroll 8
        for (int r = 0; r < 32; r++) {
            float2 kd = *(const float2*)&kb[r][d0];
            float4 v0 = *(const float4*)&vb[r][e0];
            float4 v1 = *(const float4*)&vb[r][e0 + 4];
            acc[0]  += kd.x * v0.x;  acc[1]  += kd.x * v0.y;
            acc[2]  += kd.x * v0.z;  acc[3]  += kd.x * v0.w;
            acc[4]  += kd.x * v1.x;  acc[5]  += kd.x * v1.y;
            acc[6]  += kd.x * v1.z;  acc[7]  += kd.x * v1.w;
            acc[8]  += kd.y * v0.x;  acc[9]  += kd.y * v0.y;
            acc[10] += kd.y * v0.z;  acc[11] += kd.y * v0.w;
            acc[12] += kd.y * v1.x;  acc[13] += kd.y * v1.y;
            acc[14] += kd.y * v1.z;  acc[15] += kd.y * v1.w;
            z0 += kd.x; z1 += kd.y;
        }
        __syncthreads();
    }

    float* kvp = g_kvz + (size_t)bh * 4160;
#pragma unroll
    for (int j = 0; j < 8; j++) atomicAdd(&kvp[(d0    ) * 64 + e0 + j], acc[j]);
#pragma unroll
    for (int j = 0; j < 8; j++) atomicAdd(&kvp[(d0 + 1) * 64 + e0 + j], acc[8 + j]);
    if ((tid & 7) == 0) {
        atomicAdd(&kvp[4096 + d0], z0);
        atomicAdd(&kvp[4096 + d0 + 1], z1);
    }
}

__global__ void zero_kvz_kernel()
{
    int i = blockIdx.x * 256 + threadIdx.x;
    if (i < 64 * 4160) g_kvz[i] = 0.f;
}

// ---------------- attention y (half output) ----------------------------------
__global__ void __launch_bounds__(128)
attn_y_kernel(const float* __restrict__ qkv, __half* __restrict__ y)
{
    int bh = blockIdx.x;
    int b = bh >> 4, h = bh & 15;
    int chunk = blockIdx.y;
    int tid = threadIdx.x;

    __shared__ float kvs[4096];
    __shared__ float zs[64];
    const float* kvp = g_kvz + (size_t)bh * 4160;
    for (int i = tid; i < 4160; i += 128) {
        float v = kvp[i];
        if (i < 4096) kvs[i] = v; else zs[i - 4096] = v;
    }
    __syncthreads();

    int row = b * 4096 + chunk * 128 + tid;
    const float* qp = qkv + (size_t)row * 3072 + h * 64;
    float qf[64];
#pragma unroll
    for (int i = 0; i < 16; i++) {
        float4 v = *(const float4*)(qp + i * 4);
        qf[i * 4 + 0] = phi(v.x);
        qf[i * 4 + 1] = phi(v.y);
        qf[i * 4 + 2] = phi(v.z);
        qf[i * 4 + 3] = phi(v.w);
    }
    float den = 0.f;
#pragma unroll
    for (int d2 = 0; d2 < 64; d2++) den += qf[d2] * zs[d2];
    den = fmaxf(den, 1e-6f);
    float inv = 1.f / den;

    __half* yp = y + (size_t)row * 1024 + h * 64;
#pragma unroll
    for (int eg = 0; eg < 16; eg++) {
        float a0 = 0.f, a1 = 0.f, a2 = 0.f, a3 = 0.f;
#pragma unroll
        for (int d2 = 0; d2 < 64; d2++) {
            float q = qf[d2];
            const float* kr = kvs + d2 * 64 + eg * 4;
            a0 += q * kr[0]; a1 += q * kr[1];
            a2 += q * kr[2]; a3 += q * kr[3];
        }
        __half2 h0 = __floats2half2_rn(a0 * inv, a1 * inv);
        __half2 h1 = __floats2half2_rn(a2 * inv, a3 * inv);
        uint2 u;
        u.x = *(uint32_t*)&h0;
        u.y = *(uint32_t*)&h1;
        *(uint2*)(yp + eg * 4) = u;
    }
}

// ---------------- launch ----------------------------------------------------
extern "C" void kernel_launch(void* const* d_in, const int* in_sizes, int n_in,
                              void* d_out, int out_size)
{
    (void)in_sizes; (void)n_in; (void)out_size;
    const float* src   = (const float*)d_in[0];
    const float* qkv_w = (const float*)d_in[1];
    const float* qkv_b = (const float*)d_in[2];
    const float* out_w = (const float*)d_in[3];
    const float* out_b = (const float*)d_in[4];
    const float* w1    = (const float*)d_in[5];
    const float* b1    = (const float*)d_in[6];
    const float* w2    = (const float*)d_in[7];
    const float* b2    = (const float*)d_in[8];
    const float* g1    = (const float*)d_in[9];
    const float* be1   = (const float*)d_in[10];
    const float* g2    = (const float*)d_in[11];
    const float* be2   = (const float*)d_in[12];
    float* out = (float*)d_out;

    void *xlnp, *qkvp, *attnyp, *xp, *hp, *wqp, *wop, *w1p, *w2p;
    cudaGetSymbolAddress(&xlnp,   g_xln);
    cudaGetSymbolAddress(&qkvp,   g_qkv);
    cudaGetSymbolAddress(&attnyp, g_attny);
    cudaGetSymbolAddress(&xp,     g_x);
    cudaGetSymbolAddress(&hp,     g_h);
    cudaGetSymbolAddress(&wqp,    g_wq);
    cudaGetSymbolAddress(&wop,    g_wo);
    cudaGetSymbolAddress(&w1p,    g_w1);
    cudaGetSymbolAddress(&w2p,    g_w2);

    __half* xln_h   = (__half*)xlnp;      // LN1/LN2 output (half)
    float*  qkv     = (float*)qkvp;
    __half* attny_h = (__half*)attnyp;
    float*  x       = (float*)xp;
    __half* h_h     = (__half*)hp;
    __half* wq_h    = (__half*)wqp;
    __half* wo_h    = (__half*)wop;
    __half* w1_h    = (__half*)w1p;
    __half* w2_h    = (__half*)w2p;

    cudaFuncSetAttribute(gemm_h_kernel,
                         cudaFuncAttributeMaxDynamicSharedMemorySize, GSMEM);

    // 0. transpose + fp16-round weights: WT[n][k] = half(W[k][n])
    transpose_h_kernel<<<dim3(3 * DM / 32, DM / 32), dim3(32, 8)>>>(qkv_w, wq_h, DM, 3 * DM);
    transpose_h_kernel<<<dim3(DM / 32, DM / 32),     dim3(32, 8)>>>(out_w, wo_h, DM, DM);
    transpose_h_kernel<<<dim3(DFF / 32, DM / 32),    dim3(32, 8)>>>(w1, w1_h, DM, DFF);
    transpose_h_kernel<<<dim3(DM / 32, DFF / 32),    dim3(32, 8)>>>(w2, w2_h, DFF, DM);

    // 1. LN1 -> half
    ln_kernel<<<TOK, 256>>>(src, g1, be1, xln_h);
    // 2. qkv = xln @ qkv_w + qkv_b (fp32 out)
    gemm_h_kernel<<<dim3(3 * DM / BN, TOK / BM), 256, GSMEM>>>(
        xln_h, wq_h, qkv_b, nullptr, qkv, 3 * DM, DM, 0);
    // 3-5. linear attention (fp32 in, half y out)
    zero_kvz_kernel<<<(64 * 4160 + 255) / 256, 256>>>();
    attn_kv_kernel<<<dim3(64, 8), 256>>>(qkv);
    attn_y_kernel<<<dim3(64, 32), 128>>>(qkv, attny_h);
    // 6. x = src + attny @ out_w + out_b (fp32 out)
    gemm_h_kernel<<<dim3(DM / BN, TOK / BM), 256, GSMEM>>>(
        attny_h, wo_h, out_b, src, x, DM, DM, 1);
    // 7. LN2 -> half
    ln_kernel<<<TOK, 256>>>(x, g2, be2, xln_h);
    // 8. h = gelu(hln @ w1 + b1) -> half
    gemm_h_kernel<<<dim3(DFF / BN, TOK / BM), 256, GSMEM>>>(
        xln_h, w1_h, b1, nullptr, h_h, DFF, DM, 2);
    // 9. out = x + h @ w2 + b2 (fp32 out)
    gemm_h_kernel<<<dim3(DM / BN, TOK / BM), 256, GSMEM>>>(
        h_h, w2_h, b2, x, out, DM, DFF, 1);
}

// round 11
// speedup vs baseline: 2.1555x; 1.0055x over previous
#include <cuda_runtime.h>
#include <cuda_fp16.h>
#include <math.h>
#include <stdint.h>

#define TOK   16384
#define DM    1024
#define DFF   4096
#define NH    16
#define HD    64

// ---------------- scratch (static device allocations; no cudaMalloc) --------
__device__ float g_xln  [(size_t)TOK * DM];        // used as half buffer (ln out)
__device__ float g_qkv  [(size_t)TOK * 3 * DM];    // fp32
__device__ float g_kvz  [64 * 4160];
__device__ float g_attny[(size_t)TOK * DM];        // used as half buffer
__device__ float g_x    [(size_t)TOK * DM];        // fp32
__device__ float g_h    [(size_t)TOK * DFF];       // used as half buffer
// half, TRANSPOSED weights [N][K]
__device__ float g_wq   [(size_t)3 * DM * DM / 2];
__device__ float g_wo   [(size_t)DM * DM / 2];
__device__ float g_w1   [(size_t)DFF * DM / 2];
__device__ float g_w2   [(size_t)DM * DFF / 2];

// ---------------- helpers ---------------------------------------------------
__device__ __forceinline__ uint32_t smem_u32(const void* p) {
    uint32_t a;
    asm("{ .reg .u64 t; cvta.to.shared.u64 t, %1; cvt.u32.u64 %0, t; }" : "=r"(a) : "l"(p));
    return a;
}
__device__ __forceinline__ float phi(float x) { return x > 0.f ? x + 1.f : expf(x); }
__device__ __forceinline__ float gelu_exact(float x) {
    return 0.5f * x * (1.f + erff(x * 0.70710678118654752440f));
}
__device__ __forceinline__ void cp16s(uint32_t dst, const void* src) {
    asm volatile("cp.async.cg.shared.global [%0], [%1], 16;\n" :: "r"(dst), "l"(src));
}
__device__ __forceinline__ void cp_commit() { asm volatile("cp.async.commit_group;\n"); }
template<int N> __device__ __forceinline__ void cp_wait() {
    asm volatile("cp.async.wait_group %0;\n" :: "n"(N));
}
__device__ __forceinline__ void mma_f16(float* d, const unsigned* a, const unsigned* b) {
    asm volatile(
        "mma.sync.aligned.m16n8k16.row.col.f32.f16.f16.f32 "
        "{%0,%1,%2,%3}, {%4,%5,%6,%7}, {%8,%9}, {%0,%1,%2,%3};\n"
        : "+f"(d[0]), "+f"(d[1]), "+f"(d[2]), "+f"(d[3])
        : "r"(a[0]), "r"(a[1]), "r"(a[2]), "r"(a[3]), "r"(b[0]), "r"(b[1]));
}
__device__ __forceinline__ void ldsm4(unsigned* r, uint32_t addr) {
    asm volatile("ldmatrix.sync.aligned.m8n8.x4.shared.b16 {%0,%1,%2,%3}, [%4];"
                 : "=r"(r[0]), "=r"(r[1]), "=r"(r[2]), "=r"(r[3]) : "r"(addr));
}

// packed f32x2 (Blackwell base-family PTX)
#define FMA2(acc, a, b) asm("fma.rn.f32x2 %0, %1, %2, %0;" : "+l"(acc) : "l"(a), "l"(b))
#define ADD2(acc, a)    asm("add.rn.f32x2 %0, %1, %0;" : "+l"(acc) : "l"(a))
#define PACK2(out, lo, hi) asm("mov.b64 %0, {%1, %2};" : "=l"(out) : "f"(lo), "f"(hi))
#define UNPACK2(lo, hi, in) asm("mov.b64 {%0, %1}, %2;" : "=f"(lo), "=f"(hi) : "l"(in))

// ---------------- weight transpose + fp16 round ------------------------------
__global__ void __launch_bounds__(256)
transpose_h_kernel(const float* __restrict__ in, __half* __restrict__ out, int K, int N)
{
    __shared__ float tile[32][33];
    int n0 = blockIdx.x * 32, k0 = blockIdx.y * 32;
#pragma unroll
    for (int i = threadIdx.y; i < 32; i += 8)
        tile[i][threadIdx.x] = in[(size_t)(k0 + i) * N + n0 + threadIdx.x];
    __syncthreads();
#pragma unroll
    for (int i = threadIdx.y; i < 32; i += 8)
        out[(size_t)(n0 + i) * K + k0 + threadIdx.x] = __float2half_rn(tile[threadIdx.x][i]);
}

// ---------------- LayerNorm (half output) ------------------------------------
__global__ void __launch_bounds__(256)
ln_kernel(const float* __restrict__ x, const float* __restrict__ g,
          const float* __restrict__ b, __half* __restrict__ y)
{
    int row = blockIdx.x;
    int tid = threadIdx.x;
    const float4* xr = (const float4*)(x + (size_t)row * DM);
    float4 v = xr[tid];
    float s = v.x + v.y + v.z + v.w;
    float q = v.x * v.x + v.y * v.y + v.z * v.z + v.w * v.w;
#pragma unroll
    for (int o = 16; o; o >>= 1) {
        s += __shfl_xor_sync(0xffffffffu, s, o);
        q += __shfl_xor_sync(0xffffffffu, q, o);
    }
    __shared__ float ss[8], sq[8];
    __shared__ float smu, srs;
    int warp = tid >> 5, lane = tid & 31;
    if (!lane) { ss[warp] = s; sq[warp] = q; }
    __syncthreads();
    if (!tid) {
        float S = 0.f, Q = 0.f;
#pragma unroll
        for (int i = 0; i < 8; i++) { S += ss[i]; Q += sq[i]; }
        float mu = S * (1.f / DM);
        float var = Q * (1.f / DM) - mu * mu;
        smu = mu;
        srs = rsqrtf(var + 1e-5f);
    }
    __syncthreads();
    float mu = smu, rs = srs;
    float4 gv = ((const float4*)g)[tid];
    float4 bv = ((const float4*)b)[tid];
    __half2 h01 = __floats2half2_rn((v.x - mu) * rs * gv.x + bv.x,
                                    (v.y - mu) * rs * gv.y + bv.y);
    __half2 h23 = __floats2half2_rn((v.z - mu) * rs * gv.z + bv.z,
                                    (v.w - mu) * rs * gv.w + bv.w);
    uint2 u;
    u.x = *(uint32_t*)&h01;
    u.y = *(uint32_t*)&h23;
    ((uint2*)(y + (size_t)row * DM))[tid] = u;
}

// ---------------- fp16 tensor-core GEMM: BK=64, ldmatrix, 3-stage ------------
// C[M,N] = A[M,K] @ BT[N,K]^T + bias (+resid | gelu->half)
// Block 128x128x64(halves); 8 warps: 4(m) x 2(n); warp tile 32x64.
// smem rows 144B (128B data + 16B pad) -> conflict-free LDSM (stride 36 banks).
#define BM 128
#define BN 128
#define BKH 64
#define ROW_B 144
#define TILE_B (128 * ROW_B)                   // 18432
#define STAGE_B (2 * TILE_B)                   // 36864
#define GSMEM (3 * STAGE_B)                    // 110592

__global__ void __launch_bounds__(256, 2)
gemm_h_kernel(const __half* __restrict__ A, const __half* __restrict__ BT,
              const float* __restrict__ bias, const float* __restrict__ resid,
              void* __restrict__ Cv, int N, int K, int epi)
{
    extern __shared__ char smem[];
    uint32_t sb = smem_u32(smem);

    int tid  = threadIdx.x;
    int bm   = blockIdx.y * BM;
    int bn   = blockIdx.x * BN;
    int warp = tid >> 5, lane = tid & 31;
    int wm   = warp >> 1, wn = warp & 1;
    int gid  = lane >> 2, tig = lane & 3;

    float acc[2][8][4];
#pragma unroll
    for (int i = 0; i < 2; i++)
#pragma unroll
        for (int j = 0; j < 8; j++)
#pragma unroll
            for (int l = 0; l < 4; l++) acc[i][j][l] = 0.f;

    // staging: thread -> row tid>>1, side (tid&1); 4 cp16 for A + 4 for B
    int srow = tid >> 1;
    int side = tid & 1;
    uint32_t soff = (uint32_t)srow * ROW_B + side * 64;
    const __half* ag = A + (size_t)(bm + srow) * K + side * 32;
    const __half* bg = BT + (size_t)(bn + srow) * K + side * 32;

    int T = K / BKH;

#define LOAD_STAGE(t, s) do { \
    uint32_t base = sb + (uint32_t)(s) * STAGE_B; \
    const __half* ap = ag + (size_t)(t) * BKH; \
    const __half* bp = bg + (size_t)(t) * BKH; \
    _Pragma("unroll") \
    for (int i = 0; i < 4; i++) { \
        cp16s(base + soff + i * 16,          ap + i * 8); \
        cp16s(base + TILE_B + soff + i * 16, bp + i * 8); \
    } \
} while (0)

    LOAD_STAGE(0, 0); cp_commit();
    LOAD_STAGE(1, 1); cp_commit();

    // per-thread ldmatrix row offsets (within a tile)
    // A x4: lanes 0-7 (m0-7,kLo) | 8-15 (m8-15,kLo) | 16-23 (m0-7,kHi) | 24-31 (m8-15,kHi)
    uint32_t a_off = (uint32_t)(wm * 32 + (lane & 7) + ((lane >> 3) & 1) * 8) * ROW_B
                   + ((lane >> 4) & 1) * 16;
    // B x4: lanes 0-7 (n0-7,kLo) | 8-15 (n0-7,kHi) | 16-23 (n8-15,kLo) | 24-31 (n8-15,kHi)
    uint32_t b_off = (uint32_t)(wn * 64 + (lane & 7) + ((lane >> 4) & 1) * 8) * ROW_B
                   + ((lane >> 3) & 1) * 16;

    for (int t = 0; t < T; t++) {
        if (t + 2 < T) { LOAD_STAGE(t + 2, (t + 2) % 3); }
        cp_commit();
        cp_wait<2>();
        __syncthreads();

        uint32_t ab = sb + (uint32_t)(t % 3) * STAGE_B;
        uint32_t bb = ab + TILE_B;

#pragma unroll
        for (int kk = 0; kk < 4; kk++) {       // four k16 slices of the 64-half tile
            uint32_t kb = kk * 32;
            unsigned a[2][4], b[4][4];
#pragma unroll
            for (int mf = 0; mf < 2; mf++)
                ldsm4(a[mf], ab + a_off + mf * 16 * ROW_B + kb);
#pragma unroll
            for (int nfp = 0; nfp < 4; nfp++)
                ldsm4(b[nfp], bb + b_off + nfp * 16 * ROW_B + kb);
#pragma unroll
            for (int mf = 0; mf < 2; mf++)
#pragma unroll
                for (int nf = 0; nf < 8; nf++) {
                    unsigned bfr[2] = { b[nf >> 1][(nf & 1) * 2],
                                        b[nf >> 1][(nf & 1) * 2 + 1] };
                    mma_f16(acc[mf][nf], a[mf], bfr);
                }
        }
        __syncthreads();
    }

    // ---- epilogue ----
    float* Cf = (float*)Cv;
    __half* Ch = (__half*)Cv;
#pragma unroll
    for (int mf = 0; mf < 2; mf++) {
#pragma unroll
        for (int nf = 0; nf < 8; nf++) {
            int r = bm + wm * 32 + mf * 16 + gid;
            int c = bn + wn * 64 + nf * 8 + tig * 2;
            float bx = bias[c], by = bias[c + 1];
            float2 v0 = make_float2(acc[mf][nf][0] + bx, acc[mf][nf][1] + by);
            float2 v1 = make_float2(acc[mf][nf][2] + bx, acc[mf][nf][3] + by);
            if (epi == 1) {
                const float* r0 = resid + (size_t)r * N + c;
                const float* r1 = resid + (size_t)(r + 8) * N + c;
                v0.x += r0[0]; v0.y += r0[1];
                v1.x += r1[0]; v1.y += r1[1];
            }
            if (epi == 2) {
                __half2 h0 = __floats2half2_rn(gelu_exact(v0.x), gelu_exact(v0.y));
                __half2 h1 = __floats2half2_rn(gelu_exact(v1.x), gelu_exact(v1.y));
                *(__half2*)(Ch + (size_t)r * N + c)       = h0;
                *(__half2*)(Ch + (size_t)(r + 8) * N + c) = h1;
            } else {
                *(float2*)(Cf + (size_t)r * N + c)       = v0;
                *(float2*)(Cf + (size_t)(r + 8) * N + c) = v1;
            }
        }
    }
}

// ---------------- attention: kv & z accumulation (f32x2) ---------------------
__global__ void __launch_bounds__(256)
attn_kv_kernel(const float* __restrict__ qkv)
{
    int bh = blockIdx.x;
    int b = bh >> 4, h = bh & 15;
    int chunk = blockIdx.y;
    int row0 = b * 4096 + chunk * 512;
    const float* kbase = qkv + (size_t)row0 * 3072 + 1024 + h * 64;
    const float* vbase = qkv + (size_t)row0 * 3072 + 2048 + h * 64;

    __shared__ float kb[32][64];
    __shared__ float vb[32][72];

    int tid = threadIdx.x;
    int d0 = (tid >> 3) * 2;
    int e0 = (tid & 7) * 8;
    unsigned long long acc2[8];
#pragma unroll
    for (int j = 0; j < 8; j++) acc2[j] = 0ull;
    unsigned long long z2 = 0ull;

    for (int t0 = 0; t0 < 512; t0 += 32) {
#pragma unroll
        for (int i = 0; i < 2; i++) {
            int e = tid + i * 256;
            int r = e >> 4, c4 = (e & 15) << 2;
            float4 kv4 = *(const float4*)(kbase + (size_t)(t0 + r) * 3072 + c4);
            kb[r][c4 + 0] = phi(kv4.x);
            kb[r][c4 + 1] = phi(kv4.y);
            kb[r][c4 + 2] = phi(kv4.z);
            kb[r][c4 + 3] = phi(kv4.w);
            float4 vv4 = *(const float4*)(vbase + (size_t)(t0 + r) * 3072 + c4);
            *(float4*)&vb[r][c4] = vv4;
        }
        __syncthreads();
#pragma unroll 8
        for (int r = 0; r < 32; r++) {
            float2 kd = *(const float2*)&kb[r][d0];
            float4 v0 = *(const float4*)&vb[r][e0];
            float4 v1 = *(const float4*)&vb[r][e0 + 4];
            unsigned long long kx2, ky2, kz2, p0, p1, p2, p3;
            PACK2(kx2, kd.x, kd.x);
            PACK2(ky2, kd.y, kd.y);
            PACK2(kz2, kd.x, kd.y);
            PACK2(p0, v0.x, v0.y);
            PACK2(p1, v0.z, v0.w);
            PACK2(p2, v1.x, v1.y);
            PACK2(p3, v1.z, v1.w);
            FMA2(acc2[0], kx2, p0); FMA2(acc2[1], kx2, p1);
            FMA2(acc2[2], kx2, p2); FMA2(acc2[3], kx2, p3);
            FMA2(acc2[4], ky2, p0); FMA2(acc2[5], ky2, p1);
            FMA2(acc2[6], ky2, p2); FMA2(acc2[7], ky2, p3);
            ADD2(z2, kz2);
        }
        __syncthreads();
    }

    float* kvp = g_kvz + (size_t)bh * 4160;
#pragma unroll
    for (int j = 0; j < 4; j++) {
        float lo, hi;
        UNPACK2(lo, hi, acc2[j]);
        atomicAdd(&kvp[(d0) * 64 + e0 + 2 * j], lo);
        atomicAdd(&kvp[(d0) * 64 + e0 + 2 * j + 1], hi);
    }
#pragma unroll
    for (int j = 0; j < 4; j++) {
        float lo, hi;
        UNPACK2(lo, hi, acc2[4 + j]);
        atomicAdd(&kvp[(d0 + 1) * 64 + e0 + 2 * j], lo);
        atomicAdd(&kvp[(d0 + 1) * 64 + e0 + 2 * j + 1], hi);
    }
    if ((tid & 7) == 0) {
        float z0, z1;
        UNPACK2(z0, z1, z2);
        atomicAdd(&kvp[4096 + d0], z0);
        atomicAdd(&kvp[4096 + d0 + 1], z1);
    }
}

__global__ void zero_kvz_kernel()
{
    int i = blockIdx.x * 256 + threadIdx.x;
    if (i < 64 * 4160) g_kvz[i] = 0.f;
}

// ---------------- attention y (f32x2, half output) ----------------------------
__global__ void __launch_bounds__(128)
attn_y_kernel(const float* __restrict__ qkv, __half* __restrict__ y)
{
    int bh = blockIdx.x;
    int b = bh >> 4, h = bh & 15;
    int chunk = blockIdx.y;
    int tid = threadIdx.x;

    __shared__ float kvs[4096];
    __shared__ float zs[64];
    const float* kvp = g_kvz + (size_t)bh * 4160;
    for (int i = tid; i < 4160; i += 128) {
        float v = kvp[i];
        if (i < 4096) kvs[i] = v; else zs[i - 4096] = v;
    }
    __syncthreads();

    int row = b * 4096 + chunk * 128 + tid;
    const float* qp = qkv + (size_t)row * 3072 + h * 64;
    float qf[64];
#pragma unroll
    for (int i = 0; i < 16; i++) {
        float4 v = *(const float4*)(qp + i * 4);
        qf[i * 4 + 0] = phi(v.x);
        qf[i * 4 + 1] = phi(v.y);
        qf[i * 4 + 2] = phi(v.z);
        qf[i * 4 + 3] = phi(v.w);
    }
    float den = 0.f;
#pragma unroll
    for (int d2 = 0; d2 < 64; d2++) den += qf[d2] * zs[d2];
    den = fmaxf(den, 1e-6f);
    float inv = 1.f / den;

    unsigned long long acc2[32];
#pragma unroll
    for (int j = 0; j < 32; j++) acc2[j] = 0ull;

#pragma unroll 8
    for (int d2 = 0; d2 < 64; d2++) {
        float q = qf[d2];
        unsigned long long q2;
        PACK2(q2, q, q);
        const float4* kr = (const float4*)(kvs + d2 * 64);
#pragma unroll
        for (int eg = 0; eg < 16; eg++) {
            float4 kv4 = kr[eg];
            unsigned long long p0, p1;
            PACK2(p0, kv4.x, kv4.y);
            PACK2(p1, kv4.z, kv4.w);
            FMA2(acc2[eg * 2], q2, p0);
            FMA2(acc2[eg * 2 + 1], q2, p1);
        }
    }

    __half* yp = y + (size_t)row * 1024 + h * 64;
#pragma unroll
    for (int eg = 0; eg < 16; eg++) {
        float a0, a1, a2, a3;
        UNPACK2(a0, a1, acc2[eg * 2]);
        UNPACK2(a2, a3, acc2[eg * 2 + 1]);
        __half2 h0 = __floats2half2_rn(a0 * inv, a1 * inv);
        __half2 h1 = __floats2half2_rn(a2 * inv, a3 * inv);
        uint2 u;
        u.x = *(uint32_t*)&h0;
        u.y = *(uint32_t*)&h1;
        *(uint2*)(yp + eg * 4) = u;
    }
}

// ---------------- launch ----------------------------------------------------
extern "C" void kernel_launch(void* const* d_in, const int* in_sizes, int n_in,
                              void* d_out, int out_size)
{
    (void)in_sizes; (void)n_in; (void)out_size;
    const float* src   = (const float*)d_in[0];
    const float* qkv_w = (const float*)d_in[1];
    const float* qkv_b = (const float*)d_in[2];
    const float* out_w = (const float*)d_in[3];
    const float* out_b = (const float*)d_in[4];
    const float* w1    = (const float*)d_in[5];
    const float* b1    = (const float*)d_in[6];
    const float* w2    = (const float*)d_in[7];
    const float* b2    = (const float*)d_in[8];
    const float* g1    = (const float*)d_in[9];
    const float* be1   = (const float*)d_in[10];
    const float* g2    = (const float*)d_in[11];
    const float* be2   = (const float*)d_in[12];
    float* out = (float*)d_out;

    void *xlnp, *qkvp, *attnyp, *xp, *hp, *wqp, *wop, *w1p, *w2p;
    cudaGetSymbolAddress(&xlnp,   g_xln);
    cudaGetSymbolAddress(&qkvp,   g_qkv);
    cudaGetSymbolAddress(&attnyp, g_attny);
    cudaGetSymbolAddress(&xp,     g_x);
    cudaGetSymbolAddress(&hp,     g_h);
    cudaGetSymbolAddress(&wqp,    g_wq);
    cudaGetSymbolAddress(&wop,    g_wo);
    cudaGetSymbolAddress(&w1p,    g_w1);
    cudaGetSymbolAddress(&w2p,    g_w2);

    __half* xln_h   = (__half*)xlnp;      // LN1/LN2 output (half)
    float*  qkv     = (float*)qkvp;
    __half* attny_h = (__half*)attnyp;
    float*  x       = (float*)xp;
    __half* h_h     = (__half*)hp;
    __half* wq_h    = (__half*)wqp;
    __half* wo_h    = (__half*)wop;
    __half* w1_h    = (__half*)w1p;
    __half* w2_h    = (__half*)w2p;

    cudaFuncSetAttribute(gemm_h_kernel,
                         cudaFuncAttributeMaxDynamicSharedMemorySize, GSMEM);

    // 0. transpose + fp16-round weights: WT[n][k] = half(W[k][n])
    transpose_h_kernel<<<dim3(3 * DM / 32, DM / 32), dim3(32, 8)>>>(qkv_w, wq_h, DM, 3 * DM);
    transpose_h_kernel<<<dim3(DM / 32, DM / 32),     dim3(32, 8)>>>(out_w, wo_h, DM, DM);
    transpose_h_kernel<<<dim3(DFF / 32, DM / 32),    dim3(32, 8)>>>(w1, w1_h, DM, DFF);
    transpose_h_kernel<<<dim3(DM / 32, DFF / 32),    dim3(32, 8)>>>(w2, w2_h, DFF, DM);

    // 1. LN1 -> half
    ln_kernel<<<TOK, 256>>>(src, g1, be1, xln_h);
    // 2. qkv = xln @ qkv_w + qkv_b (fp32 out)
    gemm_h_kernel<<<dim3(3 * DM / BN, TOK / BM), 256, GSMEM>>>(
        xln_h, wq_h, qkv_b, nullptr, qkv, 3 * DM, DM, 0);
    // 3-5. linear attention (fp32 in, half y out)
    zero_kvz_kernel<<<(64 * 4160 + 255) / 256, 256>>>();
    attn_kv_kernel<<<dim3(64, 8), 256>>>(qkv);
    attn_y_kernel<<<dim3(64, 32), 128>>>(qkv, attny_h);
    // 6. x = src + attny @ out_w + out_b (fp32 out)
    gemm_h_kernel<<<dim3(DM / BN, TOK / BM), 256, GSMEM>>>(
        attny_h, wo_h, out_b, src, x, DM, DM, 1);
    // 7. LN2 -> half
    ln_kernel<<<TOK, 256>>>(x, g2, be2, xln_h);
    // 8. h = gelu(hln @ w1 + b1) -> half
    gemm_h_kernel<<<dim3(DFF / BN, TOK / BM), 256, GSMEM>>>(
        xln_h, w1_h, b1, nullptr, h_h, DFF, DM, 2);
    // 9. out = x + h @ w2 + b2 (fp32 out)
    gemm_h_kernel<<<dim3(DM / BN, TOK / BM), 256, GSMEM>>>(
        h_h, w2_h, b2, x, out, DM, DFF, 1);
}

// round 12
// speedup vs baseline: 2.1780x; 1.0104x over previous
#include <cuda_runtime.h>
#include <cuda_fp16.h>
#include <math.h>
#include <stdint.h>

#define TOK   16384
#define DM    1024
#define DFF   4096
#define NH    16
#define HD    64

// ---------------- scratch (static device allocations; no cudaMalloc) --------
__device__ float g_xln  [(size_t)TOK * DM];        // half buffer (ln out)
__device__ float g_qkv  [(size_t)TOK * 3 * DM];    // half buffer: phi(q),phi(k),unused-v third
__device__ float g_kvz  [64 * 4160];
__device__ float g_attny[(size_t)TOK * DM];        // half buffer
__device__ float g_x    [(size_t)TOK * DM];        // fp32
__device__ float g_h    [(size_t)TOK * DFF];       // first 64MB: v fp32; later h half
// half, TRANSPOSED weights [N][K]
__device__ float g_wq   [(size_t)3 * DM * DM / 2];
__device__ float g_wo   [(size_t)DM * DM / 2];
__device__ float g_w1   [(size_t)DFF * DM / 2];
__device__ float g_w2   [(size_t)DM * DFF / 2];

// ---------------- helpers ---------------------------------------------------
__device__ __forceinline__ uint32_t smem_u32(const void* p) {
    uint32_t a;
    asm("{ .reg .u64 t; cvta.to.shared.u64 t, %1; cvt.u32.u64 %0, t; }" : "=r"(a) : "l"(p));
    return a;
}
__device__ __forceinline__ float phi(float x) { return x > 0.f ? x + 1.f : expf(x); }
__device__ __forceinline__ float gelu_exact(float x) {
    return 0.5f * x * (1.f + erff(x * 0.70710678118654752440f));
}
__device__ __forceinline__ void cp16s(uint32_t dst, const void* src) {
    asm volatile("cp.async.cg.shared.global [%0], [%1], 16;\n" :: "r"(dst), "l"(src));
}
__device__ __forceinline__ void cp_commit() { asm volatile("cp.async.commit_group;\n"); }
template<int N> __device__ __forceinline__ void cp_wait() {
    asm volatile("cp.async.wait_group %0;\n" :: "n"(N));
}
__device__ __forceinline__ void mma_f16(float* d, const unsigned* a, const unsigned* b) {
    asm volatile(
        "mma.sync.aligned.m16n8k16.row.col.f32.f16.f16.f32 "
        "{%0,%1,%2,%3}, {%4,%5,%6,%7}, {%8,%9}, {%0,%1,%2,%3};\n"
        : "+f"(d[0]), "+f"(d[1]), "+f"(d[2]), "+f"(d[3])
        : "r"(a[0]), "r"(a[1]), "r"(a[2]), "r"(a[3]), "r"(b[0]), "r"(b[1]));
}
__device__ __forceinline__ void ldsm4(unsigned* r, uint32_t addr) {
    asm volatile("ldmatrix.sync.aligned.m8n8.x4.shared.b16 {%0,%1,%2,%3}, [%4];"
                 : "=r"(r[0]), "=r"(r[1]), "=r"(r[2]), "=r"(r[3]) : "r"(addr));
}

// packed f32x2 (Blackwell base-family PTX)
#define FMA2(acc, a, b) asm("fma.rn.f32x2 %0, %1, %2, %0;" : "+l"(acc) : "l"(a), "l"(b))
#define ADD2(acc, a)    asm("add.rn.f32x2 %0, %1, %0;" : "+l"(acc) : "l"(a))
#define PACK2(out, lo, hi) asm("mov.b64 %0, {%1, %2};" : "=l"(out) : "f"(lo), "f"(hi))
#define UNPACK2(lo, hi, in) asm("mov.b64 {%0, %1}, %2;" : "=f"(lo), "=f"(hi) : "l"(in))

// ---------------- weight transpose + fp16 round ------------------------------
__global__ void __launch_bounds__(256)
transpose_h_kernel(const float* __restrict__ in, __half* __restrict__ out, int K, int N)
{
    __shared__ float tile[32][33];
    int n0 = blockIdx.x * 32, k0 = blockIdx.y * 32;
#pragma unroll
    for (int i = threadIdx.y; i < 32; i += 8)
        tile[i][threadIdx.x] = in[(size_t)(k0 + i) * N + n0 + threadIdx.x];
    __syncthreads();
#pragma unroll
    for (int i = threadIdx.y; i < 32; i += 8)
        out[(size_t)(n0 + i) * K + k0 + threadIdx.x] = __float2half_rn(tile[threadIdx.x][i]);
}

// ---------------- LayerNorm (half output) ------------------------------------
__global__ void __launch_bounds__(256)
ln_kernel(const float* __restrict__ x, const float* __restrict__ g,
          const float* __restrict__ b, __half* __restrict__ y)
{
    int row = blockIdx.x;
    int tid = threadIdx.x;
    const float4* xr = (const float4*)(x + (size_t)row * DM);
    float4 v = xr[tid];
    float s = v.x + v.y + v.z + v.w;
    float q = v.x * v.x + v.y * v.y + v.z * v.z + v.w * v.w;
#pragma unroll
    for (int o = 16; o; o >>= 1) {
        s += __shfl_xor_sync(0xffffffffu, s, o);
        q += __shfl_xor_sync(0xffffffffu, q, o);
    }
    __shared__ float ss[8], sq[8];
    __shared__ float smu, srs;
    int warp = tid >> 5, lane = tid & 31;
    if (!lane) { ss[warp] = s; sq[warp] = q; }
    __syncthreads();
    if (!tid) {
        float S = 0.f, Q = 0.f;
#pragma unroll
        for (int i = 0; i < 8; i++) { S += ss[i]; Q += sq[i]; }
        float mu = S * (1.f / DM);
        float var = Q * (1.f / DM) - mu * mu;
        smu = mu;
        srs = rsqrtf(var + 1e-5f);
    }
    __syncthreads();
    float mu = smu, rs = srs;
    float4 gv = ((const float4*)g)[tid];
    float4 bv = ((const float4*)b)[tid];
    __half2 h01 = __floats2half2_rn((v.x - mu) * rs * gv.x + bv.x,
                                    (v.y - mu) * rs * gv.y + bv.y);
    __half2 h23 = __floats2half2_rn((v.z - mu) * rs * gv.z + bv.z,
                                    (v.w - mu) * rs * gv.w + bv.w);
    uint2 u;
    u.x = *(uint32_t*)&h01;
    u.y = *(uint32_t*)&h23;
    ((uint2*)(y + (size_t)row * DM))[tid] = u;
}

// ---------------- fp16 tensor-core GEMM: BK=64, ldmatrix, 3-stage ------------
// C[M,N] = A[M,K] @ BT[N,K]^T + bias
// epi: 0 = fp32 out; 1 = +resid fp32 out; 2 = gelu -> half out;
//      3 = qkv: c<2048 -> phi -> half (row stride 3072); c>=2048 -> fp32 into
//          resid-ptr buffer at [row][c-2048] (row stride 1024)
#define BM 128
#define BN 128
#define BKH 64
#define ROW_B 144
#define TILE_B (128 * ROW_B)                   // 18432
#define STAGE_B (2 * TILE_B)                   // 36864
#define GSMEM (3 * STAGE_B)                    // 110592

__global__ void __launch_bounds__(256, 2)
gemm_h_kernel(const __half* __restrict__ A, const __half* __restrict__ BT,
              const float* __restrict__ bias, const float* __restrict__ resid,
              void* __restrict__ Cv, int N, int K, int epi)
{
    extern __shared__ char smem[];
    uint32_t sb = smem_u32(smem);

    int tid  = threadIdx.x;
    int bm   = blockIdx.y * BM;
    int bn   = blockIdx.x * BN;
    int warp = tid >> 5, lane = tid & 31;
    int wm   = warp >> 1, wn = warp & 1;
    int gid  = lane >> 2, tig = lane & 3;

    float acc[2][8][4];
#pragma unroll
    for (int i = 0; i < 2; i++)
#pragma unroll
        for (int j = 0; j < 8; j++)
#pragma unroll
            for (int l = 0; l < 4; l++) acc[i][j][l] = 0.f;

    int srow = tid >> 1;
    int side = tid & 1;
    uint32_t soff = (uint32_t)srow * ROW_B + side * 64;
    const __half* ag = A + (size_t)(bm + srow) * K + side * 32;
    const __half* bg = BT + (size_t)(bn + srow) * K + side * 32;

    int T = K / BKH;

#define LOAD_STAGE(t, s) do { \
    uint32_t base = sb + (uint32_t)(s) * STAGE_B; \
    const __half* ap = ag + (size_t)(t) * BKH; \
    const __half* bp = bg + (size_t)(t) * BKH; \
    _Pragma("unroll") \
    for (int i = 0; i < 4; i++) { \
        cp16s(base + soff + i * 16,          ap + i * 8); \
        cp16s(base + TILE_B + soff + i * 16, bp + i * 8); \
    } \
} while (0)

    LOAD_STAGE(0, 0); cp_commit();
    LOAD_STAGE(1, 1); cp_commit();

    uint32_t a_off = (uint32_t)(wm * 32 + (lane & 7) + ((lane >> 3) & 1) * 8) * ROW_B
                   + ((lane >> 4) & 1) * 16;
    uint32_t b_off = (uint32_t)(wn * 64 + (lane & 7) + ((lane >> 4) & 1) * 8) * ROW_B
                   + ((lane >> 3) & 1) * 16;

    for (int t = 0; t < T; t++) {
        if (t + 2 < T) { LOAD_STAGE(t + 2, (t + 2) % 3); }
        cp_commit();
        cp_wait<2>();
        __syncthreads();

        uint32_t ab = sb + (uint32_t)(t % 3) * STAGE_B;
        uint32_t bb = ab + TILE_B;

#pragma unroll
        for (int kk = 0; kk < 4; kk++) {
            uint32_t kb = kk * 32;
            unsigned a[2][4], b[4][4];
#pragma unroll
            for (int mf = 0; mf < 2; mf++)
                ldsm4(a[mf], ab + a_off + mf * 16 * ROW_B + kb);
#pragma unroll
            for (int nfp = 0; nfp < 4; nfp++)
                ldsm4(b[nfp], bb + b_off + nfp * 16 * ROW_B + kb);
#pragma unroll
            for (int mf = 0; mf < 2; mf++)
#pragma unroll
                for (int nf = 0; nf < 8; nf++) {
                    unsigned bfr[2] = { b[nf >> 1][(nf & 1) * 2],
                                        b[nf >> 1][(nf & 1) * 2 + 1] };
                    mma_f16(acc[mf][nf], a[mf], bfr);
                }
        }
        __syncthreads();
    }

    // ---- epilogue ----
    float* Cf = (float*)Cv;
    __half* Ch = (__half*)Cv;
    float* Vf = (float*)resid;           // epi 3: v output buffer
#pragma unroll
    for (int mf = 0; mf < 2; mf++) {
#pragma unroll
        for (int nf = 0; nf < 8; nf++) {
            int r = bm + wm * 32 + mf * 16 + gid;
            int c = bn + wn * 64 + nf * 8 + tig * 2;
            float bx = bias[c], by = bias[c + 1];
            float2 v0 = make_float2(acc[mf][nf][0] + bx, acc[mf][nf][1] + by);
            float2 v1 = make_float2(acc[mf][nf][2] + bx, acc[mf][nf][3] + by);
            if (epi == 1) {
                const float* r0 = resid + (size_t)r * N + c;
                const float* r1 = resid + (size_t)(r + 8) * N + c;
                v0.x += r0[0]; v0.y += r0[1];
                v1.x += r1[0]; v1.y += r1[1];
            }
            if (epi == 2) {
                __half2 h0 = __floats2half2_rn(gelu_exact(v0.x), gelu_exact(v0.y));
                __half2 h1 = __floats2half2_rn(gelu_exact(v1.x), gelu_exact(v1.y));
                *(__half2*)(Ch + (size_t)r * N + c)       = h0;
                *(__half2*)(Ch + (size_t)(r + 8) * N + c) = h1;
            } else if (epi == 3) {
                if (c < 2048) {      // q,k: phi then half, row stride 3072
                    __half2 h0 = __floats2half2_rn(phi(v0.x), phi(v0.y));
                    __half2 h1 = __floats2half2_rn(phi(v1.x), phi(v1.y));
                    *(__half2*)(Ch + (size_t)r * 3072 + c)       = h0;
                    *(__half2*)(Ch + (size_t)(r + 8) * 3072 + c) = h1;
                } else {             // v: fp32, row stride 1024
                    int cv = c - 2048;
                    *(float2*)(Vf + (size_t)r * 1024 + cv)       = v0;
                    *(float2*)(Vf + (size_t)(r + 8) * 1024 + cv) = v1;
                }
            } else {
                *(float2*)(Cf + (size_t)r * N + c)       = v0;
                *(float2*)(Cf + (size_t)(r + 8) * N + c) = v1;
            }
        }
    }
}

// ---------------- attention: kv & z accumulation ------------------------------
// inputs: phi(k) fp16 in qkv_h (cols 1024..2047), v fp32 in vbuf [row][1024]
// grid (64 bh, 8 chunks of 512 rows), 256 threads; cp.async double-buffered
#define KSTG 4096      // 32*64*2
#define VSTG 9216      // 32*72*4
__global__ void __launch_bounds__(256)
attn_kv_kernel(const __half* __restrict__ qkv_h, const float* __restrict__ vbuf)
{
    int bh = blockIdx.x;
    int b = bh >> 4, h = bh & 15;
    int row0 = b * 4096 + blockIdx.y * 512;
    const __half* kbase = qkv_h + (size_t)row0 * 3072 + 1024 + h * 64;
    const float*  vbase = vbuf + (size_t)row0 * 1024 + h * 64;

    __shared__ __half kb[2][32][64];
    __shared__ float  vb[2][32][72];

    int tid = threadIdx.x;
    int r = tid >> 3, kc = tid & 7;
    uint32_t kb0 = smem_u32(&kb[0][0][0]);
    uint32_t vb0 = smem_u32(&vb[0][0][0]);

    int d0 = (tid >> 3) * 2;
    int e0 = (tid & 7) * 8;
    unsigned long long acc2[8];
#pragma unroll
    for (int j = 0; j < 8; j++) acc2[j] = 0ull;
    unsigned long long z2 = 0ull;

#define AKV_LOAD(t0, s) do { \
    const __half* kp = kbase + (size_t)((t0) + r) * 3072 + kc * 8; \
    const float*  vp = vbase + (size_t)((t0) + r) * 1024 + kc * 8; \
    cp16s(kb0 + (s) * KSTG + r * 128 + kc * 16, kp); \
    cp16s(vb0 + (s) * VSTG + r * 288 + kc * 32,      vp); \
    cp16s(vb0 + (s) * VSTG + r * 288 + kc * 32 + 16, vp + 4); \
} while (0)

    AKV_LOAD(0, 0); cp_commit();

    for (int it = 0; it < 16; it++) {
        if (it + 1 < 16) { AKV_LOAD((it + 1) * 32, (it + 1) & 1); cp_commit(); cp_wait<1>(); }
        else { cp_wait<0>(); }
        __syncthreads();
        int s = it & 1;
#pragma unroll 8
        for (int r2 = 0; r2 < 32; r2++) {
            float2 kd = __half22float2(*(__half2*)&kb[s][r2][d0]);
            float4 v0 = *(const float4*)&vb[s][r2][e0];
            float4 v1 = *(const float4*)&vb[s][r2][e0 + 4];
            unsigned long long kx2, ky2, kz2, p0, p1, p2, p3;
            PACK2(kx2, kd.x, kd.x);
            PACK2(ky2, kd.y, kd.y);
            PACK2(kz2, kd.x, kd.y);
            PACK2(p0, v0.x, v0.y);
            PACK2(p1, v0.z, v0.w);
            PACK2(p2, v1.x, v1.y);
            PACK2(p3, v1.z, v1.w);
            FMA2(acc2[0], kx2, p0); FMA2(acc2[1], kx2, p1);
            FMA2(acc2[2], kx2, p2); FMA2(acc2[3], kx2, p3);
            FMA2(acc2[4], ky2, p0); FMA2(acc2[5], ky2, p1);
            FMA2(acc2[6], ky2, p2); FMA2(acc2[7], ky2, p3);
            ADD2(z2, kz2);
        }
        __syncthreads();
    }

    float* kvp = g_kvz + (size_t)bh * 4160;
#pragma unroll
    for (int j = 0; j < 4; j++) {
        float lo, hi;
        UNPACK2(lo, hi, acc2[j]);
        atomicAdd(&kvp[(d0) * 64 + e0 + 2 * j], lo);
        atomicAdd(&kvp[(d0) * 64 + e0 + 2 * j + 1], hi);
    }
#pragma unroll
    for (int j = 0; j < 4; j++) {
        float lo, hi;
        UNPACK2(lo, hi, acc2[4 + j]);
        atomicAdd(&kvp[(d0 + 1) * 64 + e0 + 2 * j], lo);
        atomicAdd(&kvp[(d0 + 1) * 64 + e0 + 2 * j + 1], hi);
    }
    if ((tid & 7) == 0) {
        float z0, z1;
        UNPACK2(z0, z1, z2);
        atomicAdd(&kvp[4096 + d0], z0);
        atomicAdd(&kvp[4096 + d0 + 1], z1);
    }
}

__global__ void zero_kvz_kernel()
{
    int i = blockIdx.x * 256 + threadIdx.x;
    if (i < 64 * 4160) g_kvz[i] = 0.f;
}

// ---------------- attention y (phi(q) fp16 in, half out) ----------------------
__global__ void __launch_bounds__(128)
attn_y_kernel(const __half* __restrict__ qkv_h, __half* __restrict__ y)
{
    int bh = blockIdx.x;
    int b = bh >> 4, h = bh & 15;
    int chunk = blockIdx.y;
    int tid = threadIdx.x;

    __shared__ float kvs[4096];
    __shared__ float zs[64];
    const float* kvp = g_kvz + (size_t)bh * 4160;
    for (int i = tid; i < 4160; i += 128) {
        float v = kvp[i];
        if (i < 4096) kvs[i] = v; else zs[i - 4096] = v;
    }
    __syncthreads();

    int row = b * 4096 + chunk * 128 + tid;
    const uint4* qp4 = (const uint4*)(qkv_h + (size_t)row * 3072 + h * 64);
    float qf[64];
#pragma unroll
    for (int i = 0; i < 8; i++) {
        uint4 u = qp4[i];
        unsigned w[4] = { u.x, u.y, u.z, u.w };
#pragma unroll
        for (int j = 0; j < 4; j++) {
            float2 f = __half22float2(*(__half2*)&w[j]);
            qf[i * 8 + j * 2]     = f.x;
            qf[i * 8 + j * 2 + 1] = f.y;
        }
    }
    float den = 0.f;
#pragma unroll
    for (int d2 = 0; d2 < 64; d2++) den += qf[d2] * zs[d2];
    den = fmaxf(den, 1e-6f);
    float inv = 1.f / den;

    unsigned long long acc2[32];
#pragma unroll
    for (int j = 0; j < 32; j++) acc2[j] = 0ull;

#pragma unroll 8
    for (int d2 = 0; d2 < 64; d2++) {
        float q = qf[d2];
        unsigned long long q2;
        PACK2(q2, q, q);
        const float4* kr = (const float4*)(kvs + d2 * 64);
#pragma unroll
        for (int eg = 0; eg < 16; eg++) {
            float4 kv4 = kr[eg];
            unsigned long long p0, p1;
            PACK2(p0, kv4.x, kv4.y);
            PACK2(p1, kv4.z, kv4.w);
            FMA2(acc2[eg * 2], q2, p0);
            FMA2(acc2[eg * 2 + 1], q2, p1);
        }
    }

    __half* yp = y + (size_t)row * 1024 + h * 64;
#pragma unroll
    for (int eg = 0; eg < 16; eg++) {
        float a0, a1, a2, a3;
        UNPACK2(a0, a1, acc2[eg * 2]);
        UNPACK2(a2, a3, acc2[eg * 2 + 1]);
        __half2 h0 = __floats2half2_rn(a0 * inv, a1 * inv);
        __half2 h1 = __floats2half2_rn(a2 * inv, a3 * inv);
        uint2 u;
        u.x = *(uint32_t*)&h0;
        u.y = *(uint32_t*)&h1;
        *(uint2*)(yp + eg * 4) = u;
    }
}

// ---------------- launch ----------------------------------------------------
extern "C" void kernel_launch(void* const* d_in, const int* in_sizes, int n_in,
                              void* d_out, int out_size)
{
    (void)in_sizes; (void)n_in; (void)out_size;
    const float* src   = (const float*)d_in[0];
    const float* qkv_w = (const float*)d_in[1];
    const float* qkv_b = (const float*)d_in[2];
    const float* out_w = (const float*)d_in[3];
    const float* out_b = (const float*)d_in[4];
    const float* w1    = (const float*)d_in[5];
    const float* b1    = (const float*)d_in[6];
    const float* w2    = (const float*)d_in[7];
    const float* b2    = (const float*)d_in[8];
    const float* g1    = (const float*)d_in[9];
    const float* be1   = (const float*)d_in[10];
    const float* g2    = (const float*)d_in[11];
    const float* be2   = (const float*)d_in[12];
    float* out = (float*)d_out;

    void *xlnp, *qkvp, *attnyp, *xp, *hp, *wqp, *wop, *w1p, *w2p;
    cudaGetSymbolAddress(&xlnp,   g_xln);
    cudaGetSymbolAddress(&qkvp,   g_qkv);
    cudaGetSymbolAddress(&attnyp, g_attny);
    cudaGetSymbolAddress(&xp,     g_x);
    cudaGetSymbolAddress(&hp,     g_h);
    cudaGetSymbolAddress(&wqp,    g_wq);
    cudaGetSymbolAddress(&wop,    g_wo);
    cudaGetSymbolAddress(&w1p,    g_w1);
    cudaGetSymbolAddress(&w2p,    g_w2);

    __half* xln_h   = (__half*)xlnp;      // LN1/LN2 output (half)
    __half* qkv_h   = (__half*)qkvp;      // phi(q),phi(k) half (v slot unused)
    float*  vbuf    = (float*)hp;         // v fp32 (first 64MB of g_h)
    __half* attny_h = (__half*)attnyp;
    float*  x       = (float*)xp;
    __half* h_h     = (__half*)hp;        // FFN hidden (after attn consumed v)
    __half* wq_h    = (__half*)wqp;
    __half* wo_h    = (__half*)wop;
    __half* w1_h    = (__half*)w1p;
    __half* w2_h    = (__half*)w2p;

    cudaFuncSetAttribute(gemm_h_kernel,
                         cudaFuncAttributeMaxDynamicSharedMemorySize, GSMEM);

    // launch 0: qkv weight transpose (needed by launch 3)
    transpose_h_kernel<<<dim3(3 * DM / 32, DM / 32), dim3(32, 8)>>>(qkv_w, wq_h, DM, 3 * DM);
    // launch 1: LN1 -> half
    ln_kernel<<<TOK, 256>>>(src, g1, be1, xln_h);
    // launch 2: zero kv accumulators
    zero_kvz_kernel<<<(64 * 4160 + 255) / 256, 256>>>();
    // launch 3 (profiled): qkv GEMM, epi3 -> phi(q),phi(k) half + v fp32
    gemm_h_kernel<<<dim3(3 * DM / BN, TOK / BM), 256, GSMEM>>>(
        xln_h, wq_h, qkv_b, vbuf, qkv_h, 3 * DM, DM, 3);
    // launches 4-6: remaining weight transposes
    transpose_h_kernel<<<dim3(DM / 32, DM / 32),  dim3(32, 8)>>>(out_w, wo_h, DM, DM);
    transpose_h_kernel<<<dim3(DFF / 32, DM / 32), dim3(32, 8)>>>(w1, w1_h, DM, DFF);
    transpose_h_kernel<<<dim3(DM / 32, DFF / 32), dim3(32, 8)>>>(w2, w2_h, DFF, DM);
    // attention
    attn_kv_kernel<<<dim3(64, 8), 256>>>(qkv_h, vbuf);
    attn_y_kernel<<<dim3(64, 32), 128>>>(qkv_h, attny_h);
    // x = src + attny @ out_w + out_b (fp32 out)
    gemm_h_kernel<<<dim3(DM / BN, TOK / BM), 256, GSMEM>>>(
        attny_h, wo_h, out_b, src, x, DM, DM, 1);
    // LN2 -> half
    ln_kernel<<<TOK, 256>>>(x, g2, be2, xln_h);
    // h = gelu(hln @ w1 + b1) -> half
    gemm_h_kernel<<<dim3(DFF / BN, TOK / BM), 256, GSMEM>>>(
        xln_h, w1_h, b1, nullptr, h_h, DFF, DM, 2);
    // out = x + h @ w2 + b2 (fp32 out)
    gemm_h_kernel<<<dim3(DM / BN, TOK / BM), 256, GSMEM>>>(
        h_h, w2_h, b2, x, out, DM, DFF, 1);
}

// round 13
// speedup vs baseline: 2.6887x; 1.2345x over previous
#include <cuda_runtime.h>
#include <cuda_fp16.h>
#include <math.h>
#include <stdint.h>

#define TOK   16384
#define DM    1024
#define DFF   4096
#define NH    16
#define HD    64

// ---------------- scratch (static device allocations; no cudaMalloc) --------
__device__ float g_xln  [(size_t)TOK * DM];        // half buffer (ln out)
__device__ float g_qkv  [(size_t)TOK * 3 * DM];    // half buffer: phi(q),phi(k)
__device__ float g_kvz  [64 * 4160];
__device__ float g_attny[(size_t)TOK * DM];        // half buffer
__device__ float g_x    [(size_t)TOK * DM];        // fp32
__device__ float g_h    [(size_t)TOK * DFF];       // first 64MB: v fp32; later h half
// half, TRANSPOSED weights [N][K]
__device__ float g_wq   [(size_t)3 * DM * DM / 2];
__device__ float g_wo   [(size_t)DM * DM / 2];
__device__ float g_w1   [(size_t)DFF * DM / 2];
__device__ float g_w2   [(size_t)DM * DFF / 2];

// ---------------- helpers ---------------------------------------------------
__device__ __forceinline__ uint32_t smem_u32(const void* p) {
    uint32_t a;
    asm("{ .reg .u64 t; cvta.to.shared.u64 t, %1; cvt.u32.u64 %0, t; }" : "=r"(a) : "l"(p));
    return a;
}
__device__ __forceinline__ float phi(float x) { return x > 0.f ? x + 1.f : expf(x); }
__device__ __forceinline__ float gelu_exact(float x) {
    return 0.5f * x * (1.f + erff(x * 0.70710678118654752440f));
}
__device__ __forceinline__ void cp16s(uint32_t dst, const void* src) {
    asm volatile("cp.async.cg.shared.global [%0], [%1], 16;\n" :: "r"(dst), "l"(src));
}
__device__ __forceinline__ void cp_commit() { asm volatile("cp.async.commit_group;\n"); }
template<int N> __device__ __forceinline__ void cp_wait() {
    asm volatile("cp.async.wait_group %0;\n" :: "n"(N));
}
__device__ __forceinline__ void mma_f16(float* d, const unsigned* a, const unsigned* b) {
    asm volatile(
        "mma.sync.aligned.m16n8k16.row.col.f32.f16.f16.f32 "
        "{%0,%1,%2,%3}, {%4,%5,%6,%7}, {%8,%9}, {%0,%1,%2,%3};\n"
        : "+f"(d[0]), "+f"(d[1]), "+f"(d[2]), "+f"(d[3])
        : "r"(a[0]), "r"(a[1]), "r"(a[2]), "r"(a[3]), "r"(b[0]), "r"(b[1]));
}
__device__ __forceinline__ void ldsm4(unsigned* r, uint32_t addr) {
    asm volatile("ldmatrix.sync.aligned.m8n8.x4.shared.b16 {%0,%1,%2,%3}, [%4];"
                 : "=r"(r[0]), "=r"(r[1]), "=r"(r[2]), "=r"(r[3]) : "r"(addr));
}

// packed f32x2 (Blackwell base-family PTX)
#define FMA2(acc, a, b) asm("fma.rn.f32x2 %0, %1, %2, %0;" : "+l"(acc) : "l"(a), "l"(b))
#define ADD2(acc, a)    asm("add.rn.f32x2 %0, %1, %0;" : "+l"(acc) : "l"(a))
#define PACK2(out, lo, hi) asm("mov.b64 %0, {%1, %2};" : "=l"(out) : "f"(lo), "f"(hi))
#define UNPACK2(lo, hi, in) asm("mov.b64 {%0, %1}, %2;" : "=f"(lo), "=f"(hi) : "l"(in))

// ---------------- weight transpose + fp16 round ------------------------------
__global__ void __launch_bounds__(256)
transpose_h_kernel(const float* __restrict__ in, __half* __restrict__ out, int K, int N)
{
    __shared__ float tile[32][33];
    int n0 = blockIdx.x * 32, k0 = blockIdx.y * 32;
#pragma unroll
    for (int i = threadIdx.y; i < 32; i += 8)
        tile[i][threadIdx.x] = in[(size_t)(k0 + i) * N + n0 + threadIdx.x];
    __syncthreads();
#pragma unroll
    for (int i = threadIdx.y; i < 32; i += 8)
        out[(size_t)(n0 + i) * K + k0 + threadIdx.x] = __float2half_rn(tile[threadIdx.x][i]);
}

// ---------------- LayerNorm (half output) ------------------------------------
__global__ void __launch_bounds__(256)
ln_kernel(const float* __restrict__ x, const float* __restrict__ g,
          const float* __restrict__ b, __half* __restrict__ y)
{
    int row = blockIdx.x;
    int tid = threadIdx.x;
    const float4* xr = (const float4*)(x + (size_t)row * DM);
    float4 v = xr[tid];
    float s = v.x + v.y + v.z + v.w;
    float q = v.x * v.x + v.y * v.y + v.z * v.z + v.w * v.w;
#pragma unroll
    for (int o = 16; o; o >>= 1) {
        s += __shfl_xor_sync(0xffffffffu, s, o);
        q += __shfl_xor_sync(0xffffffffu, q, o);
    }
    __shared__ float ss[8], sq[8];
    __shared__ float smu, srs;
    int warp = tid >> 5, lane = tid & 31;
    if (!lane) { ss[warp] = s; sq[warp] = q; }
    __syncthreads();
    if (!tid) {
        float S = 0.f, Q = 0.f;
#pragma unroll
        for (int i = 0; i < 8; i++) { S += ss[i]; Q += sq[i]; }
        float mu = S * (1.f / DM);
        float var = Q * (1.f / DM) - mu * mu;
        smu = mu;
        srs = rsqrtf(var + 1e-5f);
    }
    __syncthreads();
    float mu = smu, rs = srs;
    float4 gv = ((const float4*)g)[tid];
    float4 bv = ((const float4*)b)[tid];
    __half2 h01 = __floats2half2_rn((v.x - mu) * rs * gv.x + bv.x,
                                    (v.y - mu) * rs * gv.y + bv.y);
    __half2 h23 = __floats2half2_rn((v.z - mu) * rs * gv.z + bv.z,
                                    (v.w - mu) * rs * gv.w + bv.w);
    uint2 u;
    u.x = *(uint32_t*)&h01;
    u.y = *(uint32_t*)&h23;
    ((uint2*)(y + (size_t)row * DM))[tid] = u;
}

// ---------------- fp16 tensor-core GEMM: 512 thr, warp tile 32x32 ------------
// C[M,N] = A[M,K] @ BT[N,K]^T + bias
// epi: 0 = fp32 out; 1 = +resid fp32 out; 2 = gelu -> half out;
//      3 = qkv: c<2048 -> phi -> half (row stride 3072); c>=2048 -> fp32 into
//          resid-ptr buffer at [row][c-2048] (row stride 1024)
// Block 128x128x64(halves); 16 warps 4(m) x 4(n); warp tile 32x32.
// 3-stage cp.async; 2 CTAs/SM (regs capped 64) -> 32 warps/SM.
#define BM 128
#define BN 128
#define BKH 64
#define ROW_B 144
#define TILE_B (128 * ROW_B)                   // 18432
#define STAGE_B (2 * TILE_B)                   // 36864
#define GSMEM (3 * STAGE_B)                    // 110592
#define GT 512

__global__ void __launch_bounds__(GT, 2)
gemm_h_kernel(const __half* __restrict__ A, const __half* __restrict__ BT,
              const float* __restrict__ bias, const float* __restrict__ resid,
              void* __restrict__ Cv, int N, int K, int epi)
{
    extern __shared__ char smem[];
    uint32_t sb = smem_u32(smem);

    int tid  = threadIdx.x;
    int bm   = blockIdx.y * BM;
    int bn   = blockIdx.x * BN;
    int warp = tid >> 5, lane = tid & 31;
    int wm   = warp >> 2, wn = warp & 3;
    int gid  = lane >> 2, tig = lane & 3;

    float acc[2][4][4];
#pragma unroll
    for (int i = 0; i < 2; i++)
#pragma unroll
        for (int j = 0; j < 4; j++)
#pragma unroll
            for (int l = 0; l < 4; l++) acc[i][j][l] = 0.f;

    // staging: 4 threads per 128B row; thread loads 32B (2 cp16) of A and of B
    int srow = tid >> 2;
    int q4   = tid & 3;
    uint32_t soff = (uint32_t)srow * ROW_B + q4 * 32;
    const __half* ag = A + (size_t)(bm + srow) * K + q4 * 16;
    const __half* bg = BT + (size_t)(bn + srow) * K + q4 * 16;

    int T = K / BKH;

#define LOAD_STAGE(t, s) do { \
    uint32_t base = sb + (uint32_t)(s) * STAGE_B; \
    const __half* ap = ag + (size_t)(t) * BKH; \
    const __half* bp = bg + (size_t)(t) * BKH; \
    cp16s(base + soff,               ap); \
    cp16s(base + soff + 16,          ap + 8); \
    cp16s(base + TILE_B + soff,      bp); \
    cp16s(base + TILE_B + soff + 16, bp + 8); \
} while (0)

    LOAD_STAGE(0, 0); cp_commit();
    LOAD_STAGE(1, 1); cp_commit();

    // ldmatrix offsets (within a tile)
    // A x4: lanes 0-7 (m0-7,kLo) | 8-15 (m8-15,kLo) | 16-23 (m0-7,kHi) | 24-31 (m8-15,kHi)
    uint32_t a_off = (uint32_t)(wm * 32 + (lane & 7) + ((lane >> 3) & 1) * 8) * ROW_B
                   + ((lane >> 4) & 1) * 16;
    // B x4: lanes 0-7 (n0-7,kLo) | 8-15 (n0-7,kHi) | 16-23 (n8-15,kLo) | 24-31 (n8-15,kHi)
    uint32_t b_off = (uint32_t)(wn * 32 + (lane & 7) + ((lane >> 4) & 1) * 8) * ROW_B
                   + ((lane >> 3) & 1) * 16;

    for (int t = 0; t < T; t++) {
        if (t + 2 < T) { LOAD_STAGE(t + 2, (t + 2) % 3); }
        cp_commit();
        cp_wait<2>();
        __syncthreads();

        uint32_t ab = sb + (uint32_t)(t % 3) * STAGE_B;
        uint32_t bb = ab + TILE_B;

#pragma unroll
        for (int kk = 0; kk < 4; kk++) {       // four k16 slices
            uint32_t kb = kk * 32;
            unsigned a[2][4], b[2][4];
#pragma unroll
            for (int mf = 0; mf < 2; mf++)
                ldsm4(a[mf], ab + a_off + mf * 16 * ROW_B + kb);
#pragma unroll
            for (int nbp = 0; nbp < 2; nbp++)
                ldsm4(b[nbp], bb + b_off + nbp * 16 * ROW_B + kb);
#pragma unroll
            for (int mf = 0; mf < 2; mf++)
#pragma unroll
                for (int nf = 0; nf < 4; nf++) {
                    unsigned bfr[2] = { b[nf >> 1][(nf & 1) * 2],
                                        b[nf >> 1][(nf & 1) * 2 + 1] };
                    mma_f16(acc[mf][nf], a[mf], bfr);
                }
        }
        __syncthreads();
    }

    // ---- epilogue ----
    float* Cf = (float*)Cv;
    __half* Ch = (__half*)Cv;
    float* Vf = (float*)resid;           // epi 3: v output buffer
#pragma unroll
    for (int mf = 0; mf < 2; mf++) {
#pragma unroll
        for (int nf = 0; nf < 4; nf++) {
            int r = bm + wm * 32 + mf * 16 + gid;
            int c = bn + wn * 32 + nf * 8 + tig * 2;
            float bx = bias[c], by = bias[c + 1];
            float2 v0 = make_float2(acc[mf][nf][0] + bx, acc[mf][nf][1] + by);
            float2 v1 = make_float2(acc[mf][nf][2] + bx, acc[mf][nf][3] + by);
            if (epi == 1) {
                const float* r0 = resid + (size_t)r * N + c;
                const float* r1 = resid + (size_t)(r + 8) * N + c;
                v0.x += r0[0]; v0.y += r0[1];
                v1.x += r1[0]; v1.y += r1[1];
            }
            if (epi == 2) {
                __half2 h0 = __floats2half2_rn(gelu_exact(v0.x), gelu_exact(v0.y));
                __half2 h1 = __floats2half2_rn(gelu_exact(v1.x), gelu_exact(v1.y));
                *(__half2*)(Ch + (size_t)r * N + c)       = h0;
                *(__half2*)(Ch + (size_t)(r + 8) * N + c) = h1;
            } else if (epi == 3) {
                if (c < 2048) {      // q,k: phi then half, row stride 3072
                    __half2 h0 = __floats2half2_rn(phi(v0.x), phi(v0.y));
                    __half2 h1 = __floats2half2_rn(phi(v1.x), phi(v1.y));
                    *(__half2*)(Ch + (size_t)r * 3072 + c)       = h0;
                    *(__half2*)(Ch + (size_t)(r + 8) * 3072 + c) = h1;
                } else {             // v: fp32, row stride 1024
                    int cv = c - 2048;
                    *(float2*)(Vf + (size_t)r * 1024 + cv)       = v0;
                    *(float2*)(Vf + (size_t)(r + 8) * 1024 + cv) = v1;
                }
            } else {
                *(float2*)(Cf + (size_t)r * N + c)       = v0;
                *(float2*)(Cf + (size_t)(r + 8) * N + c) = v1;
            }
        }
    }
}

// ---------------- attention: kv & z accumulation ------------------------------
#define KSTG 4096      // 32*64*2
#define VSTG 9216      // 32*72*4
__global__ void __launch_bounds__(256)
attn_kv_kernel(const __half* __restrict__ qkv_h, const float* __restrict__ vbuf)
{
    int bh = blockIdx.x;
    int b = bh >> 4, h = bh & 15;
    int row0 = b * 4096 + blockIdx.y * 512;
    const __half* kbase = qkv_h + (size_t)row0 * 3072 + 1024 + h * 64;
    const float*  vbase = vbuf + (size_t)row0 * 1024 + h * 64;

    __shared__ __half kb[2][32][64];
    __shared__ float  vb[2][32][72];

    int tid = threadIdx.x;
    int r = tid >> 3, kc = tid & 7;
    uint32_t kb0 = smem_u32(&kb[0][0][0]);
    uint32_t vb0 = smem_u32(&vb[0][0][0]);

    int d0 = (tid >> 3) * 2;
    int e0 = (tid & 7) * 8;
    unsigned long long acc2[8];
#pragma unroll
    for (int j = 0; j < 8; j++) acc2[j] = 0ull;
    unsigned long long z2 = 0ull;

#define AKV_LOAD(t0, s) do { \
    const __half* kp = kbase + (size_t)((t0) + r) * 3072 + kc * 8; \
    const float*  vp = vbase + (size_t)((t0) + r) * 1024 + kc * 8; \
    cp16s(kb0 + (s) * KSTG + r * 128 + kc * 16, kp); \
    cp16s(vb0 + (s) * VSTG + r * 288 + kc * 32,      vp); \
    cp16s(vb0 + (s) * VSTG + r * 288 + kc * 32 + 16, vp + 4); \
} while (0)

    AKV_LOAD(0, 0); cp_commit();

    for (int it = 0; it < 16; it++) {
        if (it + 1 < 16) { AKV_LOAD((it + 1) * 32, (it + 1) & 1); cp_commit(); cp_wait<1>(); }
        else { cp_wait<0>(); }
        __syncthreads();
        int s = it & 1;
#pragma unroll 8
        for (int r2 = 0; r2 < 32; r2++) {
            float2 kd = __half22float2(*(__half2*)&kb[s][r2][d0]);
            float4 v0 = *(const float4*)&vb[s][r2][e0];
            float4 v1 = *(const float4*)&vb[s][r2][e0 + 4];
            unsigned long long kx2, ky2, kz2, p0, p1, p2, p3;
            PACK2(kx2, kd.x, kd.x);
            PACK2(ky2, kd.y, kd.y);
            PACK2(kz2, kd.x, kd.y);
            PACK2(p0, v0.x, v0.y);
            PACK2(p1, v0.z, v0.w);
            PACK2(p2, v1.x, v1.y);
            PACK2(p3, v1.z, v1.w);
            FMA2(acc2[0], kx2, p0); FMA2(acc2[1], kx2, p1);
            FMA2(acc2[2], kx2, p2); FMA2(acc2[3], kx2, p3);
            FMA2(acc2[4], ky2, p0); FMA2(acc2[5], ky2, p1);
            FMA2(acc2[6], ky2, p2); FMA2(acc2[7], ky2, p3);
            ADD2(z2, kz2);
        }
        __syncthreads();
    }

    float* kvp = g_kvz + (size_t)bh * 4160;
#pragma unroll
    for (int j = 0; j < 4; j++) {
        float lo, hi;
        UNPACK2(lo, hi, acc2[j]);
        atomicAdd(&kvp[(d0) * 64 + e0 + 2 * j], lo);
        atomicAdd(&kvp[(d0) * 64 + e0 + 2 * j + 1], hi);
    }
#pragma unroll
    for (int j = 0; j < 4; j++) {
        float lo, hi;
        UNPACK2(lo, hi, acc2[4 + j]);
        atomicAdd(&kvp[(d0 + 1) * 64 + e0 + 2 * j], lo);
        atomicAdd(&kvp[(d0 + 1) * 64 + e0 + 2 * j + 1], hi);
    }
    if ((tid & 7) == 0) {
        float z0, z1;
        UNPACK2(z0, z1, z2);
        atomicAdd(&kvp[4096 + d0], z0);
        atomicAdd(&kvp[4096 + d0 + 1], z1);
    }
}

__global__ void zero_kvz_kernel()
{
    int i = blockIdx.x * 256 + threadIdx.x;
    if (i < 64 * 4160) g_kvz[i] = 0.f;
}

// ---------------- attention y (phi(q) fp16 in, half out) ----------------------
__global__ void __launch_bounds__(128)
attn_y_kernel(const __half* __restrict__ qkv_h, __half* __restrict__ y)
{
    int bh = blockIdx.x;
    int b = bh >> 4, h = bh & 15;
    int chunk = blockIdx.y;
    int tid = threadIdx.x;

    __shared__ float kvs[4096];
    __shared__ float zs[64];
    const float* kvp = g_kvz + (size_t)bh * 4160;
    for (int i = tid; i < 4160; i += 128) {
        float v = kvp[i];
        if (i < 4096) kvs[i] = v; else zs[i - 4096] = v;
    }
    __syncthreads();

    int row = b * 4096 + chunk * 128 + tid;
    const uint4* qp4 = (const uint4*)(qkv_h + (size_t)row * 3072 + h * 64);
    float qf[64];
#pragma unroll
    for (int i = 0; i < 8; i++) {
        uint4 u = qp4[i];
        unsigned w[4] = { u.x, u.y, u.z, u.w };
#pragma unroll
        for (int j = 0; j < 4; j++) {
            float2 f = __half22float2(*(__half2*)&w[j]);
            qf[i * 8 + j * 2]     = f.x;
            qf[i * 8 + j * 2 + 1] = f.y;
        }
    }
    float den = 0.f;
#pragma unroll
    for (int d2 = 0; d2 < 64; d2++) den += qf[d2] * zs[d2];
    den = fmaxf(den, 1e-6f);
    float inv = 1.f / den;

    unsigned long long acc2[32];
#pragma unroll
    for (int j = 0; j < 32; j++) acc2[j] = 0ull;

#pragma unroll 8
    for (int d2 = 0; d2 < 64; d2++) {
        float q = qf[d2];
        unsigned long long q2;
        PACK2(q2, q, q);
        const float4* kr = (const float4*)(kvs + d2 * 64);
#pragma unroll
        for (int eg = 0; eg < 16; eg++) {
            float4 kv4 = kr[eg];
            unsigned long long p0, p1;
            PACK2(p0, kv4.x, kv4.y);
            PACK2(p1, kv4.z, kv4.w);
            FMA2(acc2[eg * 2], q2, p0);
            FMA2(acc2[eg * 2 + 1], q2, p1);
        }
    }

    __half* yp = y + (size_t)row * 1024 + h * 64;
#pragma unroll
    for (int eg = 0; eg < 16; eg++) {
        float a0, a1, a2, a3;
        UNPACK2(a0, a1, acc2[eg * 2]);
        UNPACK2(a2, a3, acc2[eg * 2 + 1]);
        __half2 h0 = __floats2half2_rn(a0 * inv, a1 * inv);
        __half2 h1 = __floats2half2_rn(a2 * inv, a3 * inv);
        uint2 u;
        u.x = *(uint32_t*)&h0;
        u.y = *(uint32_t*)&h1;
        *(uint2*)(yp + eg * 4) = u;
    }
}

// ---------------- launch ----------------------------------------------------
extern "C" void kernel_launch(void* const* d_in, const int* in_sizes, int n_in,
                              void* d_out, int out_size)
{
    (void)in_sizes; (void)n_in; (void)out_size;
    const float* src   = (const float*)d_in[0];
    const float* qkv_w = (const float*)d_in[1];
    const float* qkv_b = (const float*)d_in[2];
    const float* out_w = (const float*)d_in[3];
    const float* out_b = (const float*)d_in[4];
    const float* w1    = (const float*)d_in[5];
    const float* b1    = (const float*)d_in[6];
    const float* w2    = (const float*)d_in[7];
    const float* b2    = (const float*)d_in[8];
    const float* g1    = (const float*)d_in[9];
    const float* be1   = (const float*)d_in[10];
    const float* g2    = (const float*)d_in[11];
    const float* be2   = (const float*)d_in[12];
    float* out = (float*)d_out;

    void *xlnp, *qkvp, *attnyp, *xp, *hp, *wqp, *wop, *w1p, *w2p;
    cudaGetSymbolAddress(&xlnp,   g_xln);
    cudaGetSymbolAddress(&qkvp,   g_qkv);
    cudaGetSymbolAddress(&attnyp, g_attny);
    cudaGetSymbolAddress(&xp,     g_x);
    cudaGetSymbolAddress(&hp,     g_h);
    cudaGetSymbolAddress(&wqp,    g_wq);
    cudaGetSymbolAddress(&wop,    g_wo);
    cudaGetSymbolAddress(&w1p,    g_w1);
    cudaGetSymbolAddress(&w2p,    g_w2);

    __half* xln_h   = (__half*)xlnp;      // LN1/LN2 output (half)
    __half* qkv_h   = (__half*)qkvp;      // phi(q),phi(k) half (v slot unused)
    float*  vbuf    = (float*)hp;         // v fp32 (first 64MB of g_h)
    __half* attny_h = (__half*)attnyp;
    float*  x       = (float*)xp;
    __half* h_h     = (__half*)hp;        // FFN hidden (after attn consumed v)
    __half* wq_h    = (__half*)wqp;
    __half* wo_h    = (__half*)wop;
    __half* w1_h    = (__half*)w1p;
    __half* w2_h    = (__half*)w2p;

    cudaFuncSetAttribute(gemm_h_kernel,
                         cudaFuncAttributeMaxDynamicSharedMemorySize, GSMEM);

    // launch 0: qkv weight transpose (needed by launch 3)
    transpose_h_kernel<<<dim3(3 * DM / 32, DM / 32), dim3(32, 8)>>>(qkv_w, wq_h, DM, 3 * DM);
    // launch 1: LN1 -> half
    ln_kernel<<<TOK, 256>>>(src, g1, be1, xln_h);
    // launch 2: zero kv accumulators
    zero_kvz_kernel<<<(64 * 4160 + 255) / 256, 256>>>();
    // launch 3 (profiled): qkv GEMM, epi3 -> phi(q),phi(k) half + v fp32
    gemm_h_kernel<<<dim3(3 * DM / BN, TOK / BM), GT, GSMEM>>>(
        xln_h, wq_h, qkv_b, vbuf, qkv_h, 3 * DM, DM, 3);
    // launches 4-6: remaining weight transposes
    transpose_h_kernel<<<dim3(DM / 32, DM / 32),  dim3(32, 8)>>>(out_w, wo_h, DM, DM);
    transpose_h_kernel<<<dim3(DFF / 32, DM / 32), dim3(32, 8)>>>(w1, w1_h, DM, DFF);
    transpose_h_kernel<<<dim3(DM / 32, DFF / 32), dim3(32, 8)>>>(w2, w2_h, DFF, DM);
    // attention
    attn_kv_kernel<<<dim3(64, 8), 256>>>(qkv_h, vbuf);
    attn_y_kernel<<<dim3(64, 32), 128>>>(qkv_h, attny_h);
    // x = src + attny @ out_w + out_b (fp32 out)
    gemm_h_kernel<<<dim3(DM / BN, TOK / BM), GT, GSMEM>>>(
        attny_h, wo_h, out_b, src, x, DM, DM, 1);
    // LN2 -> half
    ln_kernel<<<TOK, 256>>>(x, g2, be2, xln_h);
    // h = gelu(hln @ w1 + b1) -> half
    gemm_h_kernel<<<dim3(DFF / BN, TOK / BM), GT, GSMEM>>>(
        xln_h, w1_h, b1, nullptr, h_h, DFF, DM, 2);
    // out = x + h @ w2 + b2 (fp32 out)
    gemm_h_kernel<<<dim3(DM / BN, TOK / BM), GT, GSMEM>>>(
        h_h, w2_h, b2, x, out, DM, DFF, 1);
}

// round 14
// speedup vs baseline: 2.8597x; 1.0636x over previous
#include <cuda_runtime.h>
#include <cuda_fp16.h>
#include <math.h>
#include <stdint.h>

#define TOK   16384
#define DM    1024
#define DFF   4096
#define NH    16
#define HD    64

// ---------------- scratch (static device allocations; no cudaMalloc) --------
__device__ float g_xln  [(size_t)TOK * DM];        // half buffer (ln out)
__device__ float g_qkv  [(size_t)TOK * 3 * DM];    // half buffer: phi(q),phi(k)
__device__ float g_kvz  [64 * 4160];
__device__ float g_attny[(size_t)TOK * DM];        // half buffer
__device__ float g_x    [(size_t)TOK * DM];        // fp32
__device__ float g_h    [(size_t)TOK * DFF];       // first 64MB: v fp32; later h half
// half, TRANSPOSED weights [N][K]
__device__ float g_wq   [(size_t)3 * DM * DM / 2];
__device__ float g_wo   [(size_t)DM * DM / 2];
__device__ float g_w1   [(size_t)DFF * DM / 2];
__device__ float g_w2   [(size_t)DM * DFF / 2];

// ---------------- helpers ---------------------------------------------------
__device__ __forceinline__ uint32_t smem_u32(const void* p) {
    uint32_t a;
    asm("{ .reg .u64 t; cvta.to.shared.u64 t, %1; cvt.u32.u64 %0, t; }" : "=r"(a) : "l"(p));
    return a;
}
__device__ __forceinline__ float phi(float x) { return x > 0.f ? x + 1.f : expf(x); }
__device__ __forceinline__ float gelu_exact(float x) {
    return 0.5f * x * (1.f + erff(x * 0.70710678118654752440f));
}
__device__ __forceinline__ void cp16s(uint32_t dst, const void* src) {
    asm volatile("cp.async.cg.shared.global [%0], [%1], 16;\n" :: "r"(dst), "l"(src));
}
__device__ __forceinline__ void cp_commit() { asm volatile("cp.async.commit_group;\n"); }
template<int N> __device__ __forceinline__ void cp_wait() {
    asm volatile("cp.async.wait_group %0;\n" :: "n"(N));
}
__device__ __forceinline__ void mma_f16(float* d, const unsigned* a, const unsigned* b) {
    asm volatile(
        "mma.sync.aligned.m16n8k16.row.col.f32.f16.f16.f32 "
        "{%0,%1,%2,%3}, {%4,%5,%6,%7}, {%8,%9}, {%0,%1,%2,%3};\n"
        : "+f"(d[0]), "+f"(d[1]), "+f"(d[2]), "+f"(d[3])
        : "r"(a[0]), "r"(a[1]), "r"(a[2]), "r"(a[3]), "r"(b[0]), "r"(b[1]));
}
__device__ __forceinline__ void ldsm4(unsigned* r, uint32_t addr) {
    asm volatile("ldmatrix.sync.aligned.m8n8.x4.shared.b16 {%0,%1,%2,%3}, [%4];"
                 : "=r"(r[0]), "=r"(r[1]), "=r"(r[2]), "=r"(r[3]) : "r"(addr));
}

// packed f32x2 (Blackwell base-family PTX)
#define FMA2(acc, a, b) asm("fma.rn.f32x2 %0, %1, %2, %0;" : "+l"(acc) : "l"(a), "l"(b))
#define ADD2(acc, a)    asm("add.rn.f32x2 %0, %1, %0;" : "+l"(acc) : "l"(a))
#define PACK2(out, lo, hi) asm("mov.b64 %0, {%1, %2};" : "=l"(out) : "f"(lo), "f"(hi))
#define UNPACK2(lo, hi, in) asm("mov.b64 {%0, %1}, %2;" : "=f"(lo), "=f"(hi) : "l"(in))

// ---------------- weight transpose + fp16 round ------------------------------
__global__ void __launch_bounds__(256)
transpose_h_kernel(const float* __restrict__ in, __half* __restrict__ out, int K, int N)
{
    __shared__ float tile[32][33];
    int n0 = blockIdx.x * 32, k0 = blockIdx.y * 32;
#pragma unroll
    for (int i = threadIdx.y; i < 32; i += 8)
        tile[i][threadIdx.x] = in[(size_t)(k0 + i) * N + n0 + threadIdx.x];
    __syncthreads();
#pragma unroll
    for (int i = threadIdx.y; i < 32; i += 8)
        out[(size_t)(n0 + i) * K + k0 + threadIdx.x] = __float2half_rn(tile[threadIdx.x][i]);
}

// ---------------- LayerNorm (half output) ------------------------------------
__global__ void __launch_bounds__(256)
ln_kernel(const float* __restrict__ x, const float* __restrict__ g,
          const float* __restrict__ b, __half* __restrict__ y)
{
    int row = blockIdx.x;
    int tid = threadIdx.x;
    const float4* xr = (const float4*)(x + (size_t)row * DM);
    float4 v = xr[tid];
    float s = v.x + v.y + v.z + v.w;
    float q = v.x * v.x + v.y * v.y + v.z * v.z + v.w * v.w;
#pragma unroll
    for (int o = 16; o; o >>= 1) {
        s += __shfl_xor_sync(0xffffffffu, s, o);
        q += __shfl_xor_sync(0xffffffffu, q, o);
    }
    __shared__ float ss[8], sq[8];
    __shared__ float smu, srs;
    int warp = tid >> 5, lane = tid & 31;
    if (!lane) { ss[warp] = s; sq[warp] = q; }
    __syncthreads();
    if (!tid) {
        float S = 0.f, Q = 0.f;
#pragma unroll
        for (int i = 0; i < 8; i++) { S += ss[i]; Q += sq[i]; }
        float mu = S * (1.f / DM);
        float var = Q * (1.f / DM) - mu * mu;
        smu = mu;
        srs = rsqrtf(var + 1e-5f);
    }
    __syncthreads();
    float mu = smu, rs = srs;
    float4 gv = ((const float4*)g)[tid];
    float4 bv = ((const float4*)b)[tid];
    __half2 h01 = __floats2half2_rn((v.x - mu) * rs * gv.x + bv.x,
                                    (v.y - mu) * rs * gv.y + bv.y);
    __half2 h23 = __floats2half2_rn((v.z - mu) * rs * gv.z + bv.z,
                                    (v.w - mu) * rs * gv.w + bv.w);
    uint2 u;
    u.x = *(uint32_t*)&h01;
    u.y = *(uint32_t*)&h23;
    ((uint2*)(y + (size_t)row * DM))[tid] = u;
}

// ---------------- fp16 tensor-core GEMM: 512 thr, single-sync mainloop -------
// C[M,N] = A[M,K] @ BT[N,K]^T + bias
// epi: 0 = fp32 out; 1 = +resid fp32 out; 2 = gelu -> half out;
//      3 = qkv: c<2048 -> phi -> half (row stride 3072); c>=2048 -> fp32 into
//          resid-ptr buffer at [row][c-2048] (row stride 1024)
// Block 128x128x64(halves); 16 warps 4(m) x 4(n); warp tile 32x32.
// 3-stage cp.async; ONE barrier per k-tile: wait<1> -> sync -> load(t+2) ->
// compute(t). Load after sync makes overwriting stage (t-1)%3 provably safe.
#define BM 128
#define BN 128
#define BKH 64
#define ROW_B 144
#define TILE_B (128 * ROW_B)                   // 18432
#define STAGE_B (2 * TILE_B)                   // 36864
#define GSMEM (3 * STAGE_B)                    // 110592
#define GT 512

__global__ void __launch_bounds__(GT, 2)
gemm_h_kernel(const __half* __restrict__ A, const __half* __restrict__ BT,
              const float* __restrict__ bias, const float* __restrict__ resid,
              void* __restrict__ Cv, int N, int K, int epi)
{
    extern __shared__ char smem[];
    uint32_t sb = smem_u32(smem);

    int tid  = threadIdx.x;
    int bm   = blockIdx.y * BM;
    int bn   = blockIdx.x * BN;
    int warp = tid >> 5, lane = tid & 31;
    int wm   = warp >> 2, wn = warp & 3;
    int gid  = lane >> 2, tig = lane & 3;

    float acc[2][4][4];
#pragma unroll
    for (int i = 0; i < 2; i++)
#pragma unroll
        for (int j = 0; j < 4; j++)
#pragma unroll
            for (int l = 0; l < 4; l++) acc[i][j][l] = 0.f;

    // staging: 4 threads per 128B row; thread loads 32B (2 cp16) of A and of B
    int srow = tid >> 2;
    int q4   = tid & 3;
    uint32_t soff = (uint32_t)srow * ROW_B + q4 * 32;
    const __half* ag = A + (size_t)(bm + srow) * K + q4 * 16;
    const __half* bg = BT + (size_t)(bn + srow) * K + q4 * 16;

    int T = K / BKH;

#define LOAD_STAGE(t, s) do { \
    uint32_t base = sb + (uint32_t)(s) * STAGE_B; \
    const __half* ap = ag + (size_t)(t) * BKH; \
    const __half* bp = bg + (size_t)(t) * BKH; \
    cp16s(base + soff,               ap); \
    cp16s(base + soff + 16,          ap + 8); \
    cp16s(base + TILE_B + soff,      bp); \
    cp16s(base + TILE_B + soff + 16, bp + 8); \
} while (0)

    LOAD_STAGE(0, 0); cp_commit();
    LOAD_STAGE(1, 1); cp_commit();

    // ldmatrix offsets (within a tile)
    uint32_t a_off = (uint32_t)(wm * 32 + (lane & 7) + ((lane >> 3) & 1) * 8) * ROW_B
                   + ((lane >> 4) & 1) * 16;
    uint32_t b_off = (uint32_t)(wn * 32 + (lane & 7) + ((lane >> 4) & 1) * 8) * ROW_B
                   + ((lane >> 3) & 1) * 16;

    for (int t = 0; t < T; t++) {
        cp_wait<1>();              // stage t resident (groups t+1[, t+2] pending)
        __syncthreads();           // all warps done reading stage (t-1)%3 + visibility
        if (t + 2 < T) { LOAD_STAGE(t + 2, (t + 2) % 3); }  // overwrites (t-1)%3: safe
        cp_commit();

        uint32_t ab = sb + (uint32_t)(t % 3) * STAGE_B;
        uint32_t bb = ab + TILE_B;

#pragma unroll
        for (int kk = 0; kk < 4; kk++) {       // four k16 slices
            uint32_t kb = kk * 32;
            unsigned a[2][4], b[2][4];
#pragma unroll
            for (int mf = 0; mf < 2; mf++)
                ldsm4(a[mf], ab + a_off + mf * 16 * ROW_B + kb);
#pragma unroll
            for (int nbp = 0; nbp < 2; nbp++)
                ldsm4(b[nbp], bb + b_off + nbp * 16 * ROW_B + kb);
#pragma unroll
            for (int mf = 0; mf < 2; mf++)
#pragma unroll
                for (int nf = 0; nf < 4; nf++) {
                    unsigned bfr[2] = { b[nf >> 1][(nf & 1) * 2],
                                        b[nf >> 1][(nf & 1) * 2 + 1] };
                    mma_f16(acc[mf][nf], a[mf], bfr);
                }
        }
    }

    // ---- epilogue ----
    float* Cf = (float*)Cv;
    __half* Ch = (__half*)Cv;
    float* Vf = (float*)resid;           // epi 3: v output buffer
#pragma unroll
    for (int mf = 0; mf < 2; mf++) {
#pragma unroll
        for (int nf = 0; nf < 4; nf++) {
            int r = bm + wm * 32 + mf * 16 + gid;
            int c = bn + wn * 32 + nf * 8 + tig * 2;
            float bx = bias[c], by = bias[c + 1];
            float2 v0 = make_float2(acc[mf][nf][0] + bx, acc[mf][nf][1] + by);
            float2 v1 = make_float2(acc[mf][nf][2] + bx, acc[mf][nf][3] + by);
            if (epi == 1) {
                const float* r0 = resid + (size_t)r * N + c;
                const float* r1 = resid + (size_t)(r + 8) * N + c;
                v0.x += r0[0]; v0.y += r0[1];
                v1.x += r1[0]; v1.y += r1[1];
            }
            if (epi == 2) {
                __half2 h0 = __floats2half2_rn(gelu_exact(v0.x), gelu_exact(v0.y));
                __half2 h1 = __floats2half2_rn(gelu_exact(v1.x), gelu_exact(v1.y));
                *(__half2*)(Ch + (size_t)r * N + c)       = h0;
                *(__half2*)(Ch + (size_t)(r + 8) * N + c) = h1;
            } else if (epi == 3) {
                if (c < 2048) {      // q,k: phi then half, row stride 3072
                    __half2 h0 = __floats2half2_rn(phi(v0.x), phi(v0.y));
                    __half2 h1 = __floats2half2_rn(phi(v1.x), phi(v1.y));
                    *(__half2*)(Ch + (size_t)r * 3072 + c)       = h0;
                    *(__half2*)(Ch + (size_t)(r + 8) * 3072 + c) = h1;
                } else {             // v: fp32, row stride 1024
                    int cv = c - 2048;
                    *(float2*)(Vf + (size_t)r * 1024 + cv)       = v0;
                    *(float2*)(Vf + (size_t)(r + 8) * 1024 + cv) = v1;
                }
            } else {
                *(float2*)(Cf + (size_t)r * N + c)       = v0;
                *(float2*)(Cf + (size_t)(r + 8) * N + c) = v1;
            }
        }
    }
}

// ---------------- attention: kv & z accumulation ------------------------------
#define KSTG 4096      // 32*64*2
#define VSTG 9216      // 32*72*4
__global__ void __launch_bounds__(256)
attn_kv_kernel(const __half* __restrict__ qkv_h, const float* __restrict__ vbuf)
{
    int bh = blockIdx.x;
    int b = bh >> 4, h = bh & 15;
    int row0 = b * 4096 + blockIdx.y * 512;
    const __half* kbase = qkv_h + (size_t)row0 * 3072 + 1024 + h * 64;
    const float*  vbase = vbuf + (size_t)row0 * 1024 + h * 64;

    __shared__ __half kb[2][32][64];
    __shared__ float  vb[2][32][72];

    int tid = threadIdx.x;
    int r = tid >> 3, kc = tid & 7;
    uint32_t kb0 = smem_u32(&kb[0][0][0]);
    uint32_t vb0 = smem_u32(&vb[0][0][0]);

    int d0 = (tid >> 3) * 2;
    int e0 = (tid & 7) * 8;
    unsigned long long acc2[8];
#pragma unroll
    for (int j = 0; j < 8; j++) acc2[j] = 0ull;
    unsigned long long z2 = 0ull;

#define AKV_LOAD(t0, s) do { \
    const __half* kp = kbase + (size_t)((t0) + r) * 3072 + kc * 8; \
    const float*  vp = vbase + (size_t)((t0) + r) * 1024 + kc * 8; \
    cp16s(kb0 + (s) * KSTG + r * 128 + kc * 16, kp); \
    cp16s(vb0 + (s) * VSTG + r * 288 + kc * 32,      vp); \
    cp16s(vb0 + (s) * VSTG + r * 288 + kc * 32 + 16, vp + 4); \
} while (0)

    AKV_LOAD(0, 0); cp_commit();

    for (int it = 0; it < 16; it++) {
        if (it + 1 < 16) { AKV_LOAD((it + 1) * 32, (it + 1) & 1); cp_commit(); cp_wait<1>(); }
        else { cp_wait<0>(); }
        __syncthreads();
        int s = it & 1;
#pragma unroll 8
        for (int r2 = 0; r2 < 32; r2++) {
            float2 kd = __half22float2(*(__half2*)&kb[s][r2][d0]);
            float4 v0 = *(const float4*)&vb[s][r2][e0];
            float4 v1 = *(const float4*)&vb[s][r2][e0 + 4];
            unsigned long long kx2, ky2, kz2, p0, p1, p2, p3;
            PACK2(kx2, kd.x, kd.x);
            PACK2(ky2, kd.y, kd.y);
            PACK2(kz2, kd.x, kd.y);
            PACK2(p0, v0.x, v0.y);
            PACK2(p1, v0.z, v0.w);
            PACK2(p2, v1.x, v1.y);
            PACK2(p3, v1.z, v1.w);
            FMA2(acc2[0], kx2, p0); FMA2(acc2[1], kx2, p1);
            FMA2(acc2[2], kx2, p2); FMA2(acc2[3], kx2, p3);
            FMA2(acc2[4], ky2, p0); FMA2(acc2[5], ky2, p1);
            FMA2(acc2[6], ky2, p2); FMA2(acc2[7], ky2, p3);
            ADD2(z2, kz2);
        }
        __syncthreads();
    }

    float* kvp = g_kvz + (size_t)bh * 4160;
#pragma unroll
    for (int j = 0; j < 4; j++) {
        float lo, hi;
        UNPACK2(lo, hi, acc2[j]);
        atomicAdd(&kvp[(d0) * 64 + e0 + 2 * j], lo);
        atomicAdd(&kvp[(d0) * 64 + e0 + 2 * j + 1], hi);
    }
#pragma unroll
    for (int j = 0; j < 4; j++) {
        float lo, hi;
        UNPACK2(lo, hi, acc2[4 + j]);
        atomicAdd(&kvp[(d0 + 1) * 64 + e0 + 2 * j], lo);
        atomicAdd(&kvp[(d0 + 1) * 64 + e0 + 2 * j + 1], hi);
    }
    if ((tid & 7) == 0) {
        float z0, z1;
        UNPACK2(z0, z1, z2);
        atomicAdd(&kvp[4096 + d0], z0);
        atomicAdd(&kvp[4096 + d0 + 1], z1);
    }
}

__global__ void zero_kvz_kernel()
{
    int i = blockIdx.x * 256 + threadIdx.x;
    if (i < 64 * 4160) g_kvz[i] = 0.f;
}

// ---------------- attention y (phi(q) fp16 in, half out) ----------------------
__global__ void __launch_bounds__(128)
attn_y_kernel(const __half* __restrict__ qkv_h, __half* __restrict__ y)
{
    int bh = blockIdx.x;
    int b = bh >> 4, h = bh & 15;
    int chunk = blockIdx.y;
    int tid = threadIdx.x;

    __shared__ float kvs[4096];
    __shared__ float zs[64];
    const float* kvp = g_kvz + (size_t)bh * 4160;
    for (int i = tid; i < 4160; i += 128) {
        float v = kvp[i];
        if (i < 4096) kvs[i] = v; else zs[i - 4096] = v;
    }
    __syncthreads();

    int row = b * 4096 + chunk * 128 + tid;
    const uint4* qp4 = (const uint4*)(qkv_h + (size_t)row * 3072 + h * 64);
    float qf[64];
#pragma unroll
    for (int i = 0; i < 8; i++) {
        uint4 u = qp4[i];
        unsigned w[4] = { u.x, u.y, u.z, u.w };
#pragma unroll
        for (int j = 0; j < 4; j++) {
            float2 f = __half22float2(*(__half2*)&w[j]);
            qf[i * 8 + j * 2]     = f.x;
            qf[i * 8 + j * 2 + 1] = f.y;
        }
    }
    float den = 0.f;
#pragma unroll
    for (int d2 = 0; d2 < 64; d2++) den += qf[d2] * zs[d2];
    den = fmaxf(den, 1e-6f);
    float inv = 1.f / den;

    unsigned long long acc2[32];
#pragma unroll
    for (int j = 0; j < 32; j++) acc2[j] = 0ull;

#pragma unroll 8
    for (int d2 = 0; d2 < 64; d2++) {
        float q = qf[d2];
        unsigned long long q2;
        PACK2(q2, q, q);
        const float4* kr = (const float4*)(kvs + d2 * 64);
#pragma unroll
        for (int eg = 0; eg < 16; eg++) {
            float4 kv4 = kr[eg];
            unsigned long long p0, p1;
            PACK2(p0, kv4.x, kv4.y);
            PACK2(p1, kv4.z, kv4.w);
            FMA2(acc2[eg * 2], q2, p0);
            FMA2(acc2[eg * 2 + 1], q2, p1);
        }
    }

    __half* yp = y + (size_t)row * 1024 + h * 64;
#pragma unroll
    for (int eg = 0; eg < 16; eg++) {
        float a0, a1, a2, a3;
        UNPACK2(a0, a1, acc2[eg * 2]);
        UNPACK2(a2, a3, acc2[eg * 2 + 1]);
        __half2 h0 = __floats2half2_rn(a0 * inv, a1 * inv);
        __half2 h1 = __floats2half2_rn(a2 * inv, a3 * inv);
        uint2 u;
        u.x = *(uint32_t*)&h0;
        u.y = *(uint32_t*)&h1;
        *(uint2*)(yp + eg * 4) = u;
    }
}

// ---------------- launch ----------------------------------------------------
extern "C" void kernel_launch(void* const* d_in, const int* in_sizes, int n_in,
                              void* d_out, int out_size)
{
    (void)in_sizes; (void)n_in; (void)out_size;
    const float* src   = (const float*)d_in[0];
    const float* qkv_w = (const float*)d_in[1];
    const float* qkv_b = (const float*)d_in[2];
    const float* out_w = (const float*)d_in[3];
    const float* out_b = (const float*)d_in[4];
    const float* w1    = (const float*)d_in[5];
    const float* b1    = (const float*)d_in[6];
    const float* w2    = (const float*)d_in[7];
    const float* b2    = (const float*)d_in[8];
    const float* g1    = (const float*)d_in[9];
    const float* be1   = (const float*)d_in[10];
    const float* g2    = (const float*)d_in[11];
    const float* be2   = (const float*)d_in[12];
    float* out = (float*)d_out;

    void *xlnp, *qkvp, *attnyp, *xp, *hp, *wqp, *wop, *w1p, *w2p;
    cudaGetSymbolAddress(&xlnp,   g_xln);
    cudaGetSymbolAddress(&qkvp,   g_qkv);
    cudaGetSymbolAddress(&attnyp, g_attny);
    cudaGetSymbolAddress(&xp,     g_x);
    cudaGetSymbolAddress(&hp,     g_h);
    cudaGetSymbolAddress(&wqp,    g_wq);
    cudaGetSymbolAddress(&wop,    g_wo);
    cudaGetSymbolAddress(&w1p,    g_w1);
    cudaGetSymbolAddress(&w2p,    g_w2);

    __half* xln_h   = (__half*)xlnp;      // LN1/LN2 output (half)
    __half* qkv_h   = (__half*)qkvp;      // phi(q),phi(k) half (v slot unused)
    float*  vbuf    = (float*)hp;         // v fp32 (first 64MB of g_h)
    __half* attny_h = (__half*)attnyp;
    float*  x       = (float*)xp;
    __half* h_h     = (__half*)hp;        // FFN hidden (after attn consumed v)
    __half* wq_h    = (__half*)wqp;
    __half* wo_h    = (__half*)wop;
    __half* w1_h    = (__half*)w1p;
    __half* w2_h    = (__half*)w2p;

    cudaFuncSetAttribute(gemm_h_kernel,
                         cudaFuncAttributeMaxDynamicSharedMemorySize, GSMEM);

    // launch 0: qkv weight transpose (needed by launch 3)
    transpose_h_kernel<<<dim3(3 * DM / 32, DM / 32), dim3(32, 8)>>>(qkv_w, wq_h, DM, 3 * DM);
    // launch 1: LN1 -> half
    ln_kernel<<<TOK, 256>>>(src, g1, be1, xln_h);
    // launch 2: zero kv accumulators
    zero_kvz_kernel<<<(64 * 4160 + 255) / 256, 256>>>();
    // launch 3 (profiled): qkv GEMM, epi3 -> phi(q),phi(k) half + v fp32
    gemm_h_kernel<<<dim3(3 * DM / BN, TOK / BM), GT, GSMEM>>>(
        xln_h, wq_h, qkv_b, vbuf, qkv_h, 3 * DM, DM, 3);
    // launches 4-6: remaining weight transposes
    transpose_h_kernel<<<dim3(DM / 32, DM / 32),  dim3(32, 8)>>>(out_w, wo_h, DM, DM);
    transpose_h_kernel<<<dim3(DFF / 32, DM / 32), dim3(32, 8)>>>(w1, w1_h, DM, DFF);
    transpose_h_kernel<<<dim3(DM / 32, DFF / 32), dim3(32, 8)>>>(w2, w2_h, DFF, DM);
    // attention
    attn_kv_kernel<<<dim3(64, 8), 256>>>(qkv_h, vbuf);
    attn_y_kernel<<<dim3(64, 32), 128>>>(qkv_h, attny_h);
    // x = src + attny @ out_w + out_b (fp32 out)
    gemm_h_kernel<<<dim3(DM / BN, TOK / BM), GT, GSMEM>>>(
        attny_h, wo_h, out_b, src, x, DM, DM, 1);
    // LN2 -> half
    ln_kernel<<<TOK, 256>>>(x, g2, be2, xln_h);
    // h = gelu(hln @ w1 + b1) -> half
    gemm_h_kernel<<<dim3(DFF / BN, TOK / BM), GT, GSMEM>>>(
        xln_h, w1_h, b1, nullptr, h_h, DFF, DM, 2);
    // out = x + h @ w2 + b2 (fp32 out)
    gemm_h_kernel<<<dim3(DM / BN, TOK / BM), GT, GSMEM>>>(
        h_h, w2_h, b2, x, out, DM, DFF, 1);
}

// round 15
// speedup vs baseline: 2.8730x; 1.0046x over previous
#include <cuda_runtime.h>
#include <cuda_fp16.h>
#include <math.h>
#include <stdint.h>

#define TOK   16384
#define DM    1024
#define DFF   4096
#define NH    16
#define HD    64

// ---------------- scratch (static device allocations; no cudaMalloc) --------
__device__ float g_xln  [(size_t)TOK * DM];        // half buffer (ln out)
__device__ float g_qkv  [(size_t)TOK * 3 * DM];    // half buffer: phi(q),phi(k)
__device__ float g_kvz  [64 * 4160];
__device__ float g_attny[(size_t)TOK * DM];        // half buffer
__device__ float g_x    [(size_t)TOK * DM];        // fp32
__device__ float g_h    [(size_t)TOK * DFF];       // first 64MB: v fp32; later h half
// half, TRANSPOSED weights [N][K]
__device__ float g_wq   [(size_t)3 * DM * DM / 2];
__device__ float g_wo   [(size_t)DM * DM / 2];
__device__ float g_w1   [(size_t)DFF * DM / 2];
__device__ float g_w2   [(size_t)DM * DFF / 2];

// ---------------- helpers ---------------------------------------------------
__device__ __forceinline__ uint32_t smem_u32(const void* p) {
    uint32_t a;
    asm("{ .reg .u64 t; cvta.to.shared.u64 t, %1; cvt.u32.u64 %0, t; }" : "=r"(a) : "l"(p));
    return a;
}
__device__ __forceinline__ float phi(float x) { return x > 0.f ? x + 1.f : expf(x); }
__device__ __forceinline__ float gelu_exact(float x) {
    return 0.5f * x * (1.f + erff(x * 0.70710678118654752440f));
}
__device__ __forceinline__ void cp16s(uint32_t dst, const void* src) {
    asm volatile("cp.async.cg.shared.global [%0], [%1], 16;\n" :: "r"(dst), "l"(src));
}
__device__ __forceinline__ void cp_commit() { asm volatile("cp.async.commit_group;\n"); }
template<int N> __device__ __forceinline__ void cp_wait() {
    asm volatile("cp.async.wait_group %0;\n" :: "n"(N));
}
__device__ __forceinline__ void mma_f16(float* d, const unsigned* a, const unsigned* b) {
    asm volatile(
        "mma.sync.aligned.m16n8k16.row.col.f32.f16.f16.f32 "
        "{%0,%1,%2,%3}, {%4,%5,%6,%7}, {%8,%9}, {%0,%1,%2,%3};\n"
        : "+f"(d[0]), "+f"(d[1]), "+f"(d[2]), "+f"(d[3])
        : "r"(a[0]), "r"(a[1]), "r"(a[2]), "r"(a[3]), "r"(b[0]), "r"(b[1]));
}
__device__ __forceinline__ void ldsm4(unsigned* r, uint32_t addr) {
    asm volatile("ldmatrix.sync.aligned.m8n8.x4.shared.b16 {%0,%1,%2,%3}, [%4];"
                 : "=r"(r[0]), "=r"(r[1]), "=r"(r[2]), "=r"(r[3]) : "r"(addr));
}

// packed f32x2 (Blackwell base-family PTX)
#define FMA2(acc, a, b) asm("fma.rn.f32x2 %0, %1, %2, %0;" : "+l"(acc) : "l"(a), "l"(b))
#define ADD2(acc, a)    asm("add.rn.f32x2 %0, %1, %0;" : "+l"(acc) : "l"(a))
#define PACK2(out, lo, hi) asm("mov.b64 %0, {%1, %2};" : "=l"(out) : "f"(lo), "f"(hi))
#define UNPACK2(lo, hi, in) asm("mov.b64 {%0, %1}, %2;" : "=f"(lo), "=f"(hi) : "l"(in))

// ---------------- fused prep: 4 weight transposes + kvz zero -----------------
// blocks [0,3072): qkv_w  (K=1024,N=3072)  bx=id%96, by=id/96
// [3072,4096): out_w (1024,1024)  [4096,8192): w1 (1024,4096)
// [8192,12288): w2 (4096,1024)   [12288,12548): zero g_kvz (66560 float4)
__global__ void __launch_bounds__(256)
prep_kernel(const float* __restrict__ qkv_w, const float* __restrict__ out_w,
            const float* __restrict__ w1, const float* __restrict__ w2,
            __half* __restrict__ wq, __half* __restrict__ wo,
            __half* __restrict__ w1h, __half* __restrict__ w2h,
            float* __restrict__ kvz)
{
    int id = blockIdx.x;
    int t = threadIdx.y * 32 + threadIdx.x;
    if (id >= 12288) {
        int idx = (id - 12288) * 256 + t;
        if (idx < 66560) ((float4*)kvz)[idx] = make_float4(0.f, 0.f, 0.f, 0.f);
        return;
    }
    const float* in; __half* out; int K, N, bx, by;
    if (id < 3072)      { in = qkv_w; out = wq;  K = 1024; N = 3072; bx = id % 96;  by = id / 96; }
    else if (id < 4096) { int i = id - 3072; in = out_w; out = wo;  K = 1024; N = 1024; bx = i % 32;  by = i / 32; }
    else if (id < 8192) { int i = id - 4096; in = w1;    out = w1h; K = 1024; N = 4096; bx = i % 128; by = i / 128; }
    else                { int i = id - 8192; in = w2;    out = w2h; K = 4096; N = 1024; bx = i % 32;  by = i / 32; }

    __shared__ float tile[32][33];
    int n0 = bx * 32, k0 = by * 32;
#pragma unroll
    for (int i = threadIdx.y; i < 32; i += 8)
        tile[i][threadIdx.x] = in[(size_t)(k0 + i) * N + n0 + threadIdx.x];
    __syncthreads();
#pragma unroll
    for (int i = threadIdx.y; i < 32; i += 8)
        out[(size_t)(n0 + i) * K + k0 + threadIdx.x] = __float2half_rn(tile[threadIdx.x][i]);
}

// ---------------- LayerNorm (half output) ------------------------------------
__global__ void __launch_bounds__(256)
ln_kernel(const float* __restrict__ x, const float* __restrict__ g,
          const float* __restrict__ b, __half* __restrict__ y)
{
    int row = blockIdx.x;
    int tid = threadIdx.x;
    const float4* xr = (const float4*)(x + (size_t)row * DM);
    float4 v = xr[tid];
    float s = v.x + v.y + v.z + v.w;
    float q = v.x * v.x + v.y * v.y + v.z * v.z + v.w * v.w;
#pragma unroll
    for (int o = 16; o; o >>= 1) {
        s += __shfl_xor_sync(0xffffffffu, s, o);
        q += __shfl_xor_sync(0xffffffffu, q, o);
    }
    __shared__ float ss[8], sq[8];
    __shared__ float smu, srs;
    int warp = tid >> 5, lane = tid & 31;
    if (!lane) { ss[warp] = s; sq[warp] = q; }
    __syncthreads();
    if (!tid) {
        float S = 0.f, Q = 0.f;
#pragma unroll
        for (int i = 0; i < 8; i++) { S += ss[i]; Q += sq[i]; }
        float mu = S * (1.f / DM);
        float var = Q * (1.f / DM) - mu * mu;
        smu = mu;
        srs = rsqrtf(var + 1e-5f);
    }
    __syncthreads();
    float mu = smu, rs = srs;
    float4 gv = ((const float4*)g)[tid];
    float4 bv = ((const float4*)b)[tid];
    __half2 h01 = __floats2half2_rn((v.x - mu) * rs * gv.x + bv.x,
                                    (v.y - mu) * rs * gv.y + bv.y);
    __half2 h23 = __floats2half2_rn((v.z - mu) * rs * gv.z + bv.z,
                                    (v.w - mu) * rs * gv.w + bv.w);
    uint2 u;
    u.x = *(uint32_t*)&h01;
    u.y = *(uint32_t*)&h23;
    ((uint2*)(y + (size_t)row * DM))[tid] = u;
}

// ---------------- fp16 tensor-core GEMM: 512 thr, single-sync mainloop -------
#define BM 128
#define BN 128
#define BKH 64
#define ROW_B 144
#define TILE_B (128 * ROW_B)                   // 18432
#define STAGE_B (2 * TILE_B)                   // 36864
#define GSMEM (3 * STAGE_B)                    // 110592
#define GT 512

__global__ void __launch_bounds__(GT, 2)
gemm_h_kernel(const __half* __restrict__ A, const __half* __restrict__ BT,
              const float* __restrict__ bias, const float* __restrict__ resid,
              void* __restrict__ Cv, int N, int K, int epi)
{
    extern __shared__ char smem[];
    uint32_t sb = smem_u32(smem);

    int tid  = threadIdx.x;
    int bm   = blockIdx.y * BM;
    int bn   = blockIdx.x * BN;
    int warp = tid >> 5, lane = tid & 31;
    int wm   = warp >> 2, wn = warp & 3;
    int gid  = lane >> 2, tig = lane & 3;

    float acc[2][4][4];
#pragma unroll
    for (int i = 0; i < 2; i++)
#pragma unroll
        for (int j = 0; j < 4; j++)
#pragma unroll
            for (int l = 0; l < 4; l++) acc[i][j][l] = 0.f;

    int srow = tid >> 2;
    int q4   = tid & 3;
    uint32_t soff = (uint32_t)srow * ROW_B + q4 * 32;
    const __half* ag = A + (size_t)(bm + srow) * K + q4 * 16;
    const __half* bg = BT + (size_t)(bn + srow) * K + q4 * 16;

    int T = K / BKH;

#define LOAD_STAGE(t, s) do { \
    uint32_t base = sb + (uint32_t)(s) * STAGE_B; \
    const __half* ap = ag + (size_t)(t) * BKH; \
    const __half* bp = bg + (size_t)(t) * BKH; \
    cp16s(base + soff,               ap); \
    cp16s(base + soff + 16,          ap + 8); \
    cp16s(base + TILE_B + soff,      bp); \
    cp16s(base + TILE_B + soff + 16, bp + 8); \
} while (0)

    LOAD_STAGE(0, 0); cp_commit();
    LOAD_STAGE(1, 1); cp_commit();

    uint32_t a_off = (uint32_t)(wm * 32 + (lane & 7) + ((lane >> 3) & 1) * 8) * ROW_B
                   + ((lane >> 4) & 1) * 16;
    uint32_t b_off = (uint32_t)(wn * 32 + (lane & 7) + ((lane >> 4) & 1) * 8) * ROW_B
                   + ((lane >> 3) & 1) * 16;

    for (int t = 0; t < T; t++) {
        cp_wait<1>();
        __syncthreads();
        if (t + 2 < T) { LOAD_STAGE(t + 2, (t + 2) % 3); }
        cp_commit();

        uint32_t ab = sb + (uint32_t)(t % 3) * STAGE_B;
        uint32_t bb = ab + TILE_B;

#pragma unroll
        for (int kk = 0; kk < 4; kk++) {
            uint32_t kb = kk * 32;
            unsigned a[2][4], b[2][4];
#pragma unroll
            for (int mf = 0; mf < 2; mf++)
                ldsm4(a[mf], ab + a_off + mf * 16 * ROW_B + kb);
#pragma unroll
            for (int nbp = 0; nbp < 2; nbp++)
                ldsm4(b[nbp], bb + b_off + nbp * 16 * ROW_B + kb);
#pragma unroll
            for (int mf = 0; mf < 2; mf++)
#pragma unroll
                for (int nf = 0; nf < 4; nf++) {
                    unsigned bfr[2] = { b[nf >> 1][(nf & 1) * 2],
                                        b[nf >> 1][(nf & 1) * 2 + 1] };
                    mma_f16(acc[mf][nf], a[mf], bfr);
                }
        }
    }

    // ---- epilogue ----
    float* Cf = (float*)Cv;
    __half* Ch = (__half*)Cv;
    float* Vf = (float*)resid;
#pragma unroll
    for (int mf = 0; mf < 2; mf++) {
#pragma unroll
        for (int nf = 0; nf < 4; nf++) {
            int r = bm + wm * 32 + mf * 16 + gid;
            int c = bn + wn * 32 + nf * 8 + tig * 2;
            float bx = bias[c], by = bias[c + 1];
            float2 v0 = make_float2(acc[mf][nf][0] + bx, acc[mf][nf][1] + by);
            float2 v1 = make_float2(acc[mf][nf][2] + bx, acc[mf][nf][3] + by);
            if (epi == 1) {
                const float* r0 = resid + (size_t)r * N + c;
                const float* r1 = resid + (size_t)(r + 8) * N + c;
                v0.x += r0[0]; v0.y += r0[1];
                v1.x += r1[0]; v1.y += r1[1];
            }
            if (epi == 2) {
                __half2 h0 = __floats2half2_rn(gelu_exact(v0.x), gelu_exact(v0.y));
                __half2 h1 = __floats2half2_rn(gelu_exact(v1.x), gelu_exact(v1.y));
                *(__half2*)(Ch + (size_t)r * N + c)       = h0;
                *(__half2*)(Ch + (size_t)(r + 8) * N + c) = h1;
            } else if (epi == 3) {
                if (c < 2048) {
                    __half2 h0 = __floats2half2_rn(phi(v0.x), phi(v0.y));
                    __half2 h1 = __floats2half2_rn(phi(v1.x), phi(v1.y));
                    *(__half2*)(Ch + (size_t)r * 3072 + c)       = h0;
                    *(__half2*)(Ch + (size_t)(r + 8) * 3072 + c) = h1;
                } else {
                    int cv = c - 2048;
                    *(float2*)(Vf + (size_t)r * 1024 + cv)       = v0;
                    *(float2*)(Vf + (size_t)(r + 8) * 1024 + cv) = v1;
                }
            } else {
                *(float2*)(Cf + (size_t)r * N + c)       = v0;
                *(float2*)(Cf + (size_t)(r + 8) * N + c) = v1;
            }
        }
    }
}

// ---------------- attention: kv & z accumulation (single-sync) ----------------
#define KSTG 4096      // 32*64*2
#define VSTG 9216      // 32*72*4
__global__ void __launch_bounds__(256)
attn_kv_kernel(const __half* __restrict__ qkv_h, const float* __restrict__ vbuf)
{
    int bh = blockIdx.x;
    int b = bh >> 4, h = bh & 15;
    int row0 = b * 4096 + blockIdx.y * 512;
    const __half* kbase = qkv_h + (size_t)row0 * 3072 + 1024 + h * 64;
    const float*  vbase = vbuf + (size_t)row0 * 1024 + h * 64;

    __shared__ __half kb[2][32][64];
    __shared__ float  vb[2][32][72];

    int tid = threadIdx.x;
    int r = tid >> 3, kc = tid & 7;
    uint32_t kb0 = smem_u32(&kb[0][0][0]);
    uint32_t vb0 = smem_u32(&vb[0][0][0]);

    int d0 = (tid >> 3) * 2;
    int e0 = (tid & 7) * 8;
    unsigned long long acc2[8];
#pragma unroll
    for (int j = 0; j < 8; j++) acc2[j] = 0ull;
    unsigned long long z2 = 0ull;

#define AKV_LOAD(t0, s) do { \
    const __half* kp = kbase + (size_t)((t0) + r) * 3072 + kc * 8; \
    const float*  vp = vbase + (size_t)((t0) + r) * 1024 + kc * 8; \
    cp16s(kb0 + (s) * KSTG + r * 128 + kc * 16, kp); \
    cp16s(vb0 + (s) * VSTG + r * 288 + kc * 32,      vp); \
    cp16s(vb0 + (s) * VSTG + r * 288 + kc * 32 + 16, vp + 4); \
} while (0)

    AKV_LOAD(0, 0); cp_commit();

    for (int it = 0; it < 16; it++) {
        cp_wait<0>();
        __syncthreads();
        if (it + 1 < 16) { AKV_LOAD((it + 1) * 32, (it + 1) & 1); cp_commit(); }
        int s = it & 1;
#pragma unroll 8
        for (int r2 = 0; r2 < 32; r2++) {
            float2 kd = __half22float2(*(__half2*)&kb[s][r2][d0]);
            float4 v0 = *(const float4*)&vb[s][r2][e0];
            float4 v1 = *(const float4*)&vb[s][r2][e0 + 4];
            unsigned long long kx2, ky2, kz2, p0, p1, p2, p3;
            PACK2(kx2, kd.x, kd.x);
            PACK2(ky2, kd.y, kd.y);
            PACK2(kz2, kd.x, kd.y);
            PACK2(p0, v0.x, v0.y);
            PACK2(p1, v0.z, v0.w);
            PACK2(p2, v1.x, v1.y);
            PACK2(p3, v1.z, v1.w);
            FMA2(acc2[0], kx2, p0); FMA2(acc2[1], kx2, p1);
            FMA2(acc2[2], kx2, p2); FMA2(acc2[3], kx2, p3);
            FMA2(acc2[4], ky2, p0); FMA2(acc2[5], ky2, p1);
            FMA2(acc2[6], ky2, p2); FMA2(acc2[7], ky2, p3);
            ADD2(z2, kz2);
        }
    }

    float* kvp = g_kvz + (size_t)bh * 4160;
#pragma unroll
    for (int j = 0; j < 4; j++) {
        float lo, hi;
        UNPACK2(lo, hi, acc2[j]);
        atomicAdd(&kvp[(d0) * 64 + e0 + 2 * j], lo);
        atomicAdd(&kvp[(d0) * 64 + e0 + 2 * j + 1], hi);
    }
#pragma unroll
    for (int j = 0; j < 4; j++) {
        float lo, hi;
        UNPACK2(lo, hi, acc2[4 + j]);
        atomicAdd(&kvp[(d0 + 1) * 64 + e0 + 2 * j], lo);
        atomicAdd(&kvp[(d0 + 1) * 64 + e0 + 2 * j + 1], hi);
    }
    if ((tid & 7) == 0) {
        float z0, z1;
        UNPACK2(z0, z1, z2);
        atomicAdd(&kvp[4096 + d0], z0);
        atomicAdd(&kvp[4096 + d0 + 1], z1);
    }
}

// ---------------- attention y: eg-chunked, low-reg ----------------------------
__global__ void __launch_bounds__(128)
attn_y_kernel(const __half* __restrict__ qkv_h, __half* __restrict__ y)
{
    int bh = blockIdx.x;
    int b = bh >> 4, h = bh & 15;
    int chunk = blockIdx.y;
    int tid = threadIdx.x;

    __shared__ float kvs[4096];
    __shared__ float zs[64];
    const float* kvp = g_kvz + (size_t)bh * 4160;
    for (int i = tid; i < 4160; i += 128) {
        float v = kvp[i];
        if (i < 4096) kvs[i] = v; else zs[i - 4096] = v;
    }
    __syncthreads();

    int row = b * 4096 + chunk * 128 + tid;
    const uint4* qp4 = (const uint4*)(qkv_h + (size_t)row * 3072 + h * 64);
    unsigned qh[32];                       // phi(q) as 32x half2
#pragma unroll
    for (int i = 0; i < 8; i++) {
        uint4 u = qp4[i];
        qh[i * 4 + 0] = u.x; qh[i * 4 + 1] = u.y;
        qh[i * 4 + 2] = u.z; qh[i * 4 + 3] = u.w;
    }

    float den = 0.f;
#pragma unroll
    for (int dp = 0; dp < 32; dp++) {
        float2 f = __half22float2(*(__half2*)&qh[dp]);
        den += f.x * zs[2 * dp] + f.y * zs[2 * dp + 1];
    }
    den = fmaxf(den, 1e-6f);
    float inv = 1.f / den;

    __half* yp = y + (size_t)row * 1024 + h * 64;
#pragma unroll
    for (int c = 0; c < 4; c++) {          // 4 eg per chunk -> only 8 live acc2
        unsigned long long acc2[8];
#pragma unroll
        for (int j = 0; j < 8; j++) acc2[j] = 0ull;
#pragma unroll 8
        for (int dp = 0; dp < 32; dp++) {
            float2 f = __half22float2(*(__half2*)&qh[dp]);
            unsigned long long qa, qb;
            PACK2(qa, f.x, f.x);
            PACK2(qb, f.y, f.y);
            const float4* kr0 = (const float4*)(kvs + (2 * dp) * 64) + c * 4;
            const float4* kr1 = (const float4*)(kvs + (2 * dp + 1) * 64) + c * 4;
#pragma unroll
            for (int e = 0; e < 4; e++) {
                float4 k0 = kr0[e];
                unsigned long long p0, p1;
                PACK2(p0, k0.x, k0.y);
                PACK2(p1, k0.z, k0.w);
                FMA2(acc2[e * 2], qa, p0);
                FMA2(acc2[e * 2 + 1], qa, p1);
            }
#pragma unroll
            for (int e = 0; e < 4; e++) {
                float4 k1 = kr1[e];
                unsigned long long p0, p1;
                PACK2(p0, k1.x, k1.y);
                PACK2(p1, k1.z, k1.w);
                FMA2(acc2[e * 2], qb, p0);
                FMA2(acc2[e * 2 + 1], qb, p1);
            }
        }
#pragma unroll
        for (int e = 0; e < 4; e++) {
            float a0, a1, a2, a3;
            UNPACK2(a0, a1, acc2[e * 2]);
            UNPACK2(a2, a3, acc2[e * 2 + 1]);
            __half2 h0 = __floats2half2_rn(a0 * inv, a1 * inv);
            __half2 h1 = __floats2half2_rn(a2 * inv, a3 * inv);
            uint2 u;
            u.x = *(uint32_t*)&h0;
            u.y = *(uint32_t*)&h1;
            *(uint2*)(yp + (c * 4 + e) * 4) = u;
        }
    }
}

// ---------------- launch ----------------------------------------------------
extern "C" void kernel_launch(void* const* d_in, const int* in_sizes, int n_in,
                              void* d_out, int out_size)
{
    (void)in_sizes; (void)n_in; (void)out_size;
    const float* src   = (const float*)d_in[0];
    const float* qkv_w = (const float*)d_in[1];
    const float* qkv_b = (const float*)d_in[2];
    const float* out_w = (const float*)d_in[3];
    const float* out_b = (const float*)d_in[4];
    const float* w1    = (const float*)d_in[5];
    const float* b1    = (const float*)d_in[6];
    const float* w2    = (const float*)d_in[7];
    const float* b2    = (const float*)d_in[8];
    const float* g1    = (const float*)d_in[9];
    const float* be1   = (const float*)d_in[10];
    const float* g2    = (const float*)d_in[11];
    const float* be2   = (const float*)d_in[12];
    float* out = (float*)d_out;

    void *xlnp, *qkvp, *attnyp, *xp, *hp, *wqp, *wop, *w1p, *w2p, *kvzp;
    cudaGetSymbolAddress(&xlnp,   g_xln);
    cudaGetSymbolAddress(&qkvp,   g_qkv);
    cudaGetSymbolAddress(&attnyp, g_attny);
    cudaGetSymbolAddress(&xp,     g_x);
    cudaGetSymbolAddress(&hp,     g_h);
    cudaGetSymbolAddress(&wqp,    g_wq);
    cudaGetSymbolAddress(&wop,    g_wo);
    cudaGetSymbolAddress(&w1p,    g_w1);
    cudaGetSymbolAddress(&w2p,    g_w2);
    cudaGetSymbolAddress(&kvzp,   g_kvz);

    __half* xln_h   = (__half*)xlnp;
    __half* qkv_h   = (__half*)qkvp;
    float*  vbuf    = (float*)hp;
    __half* attny_h = (__half*)attnyp;
    float*  x       = (float*)xp;
    __half* h_h     = (__half*)hp;
    __half* wq_h    = (__half*)wqp;
    __half* wo_h    = (__half*)wop;
    __half* w1_h    = (__half*)w1p;
    __half* w2_h    = (__half*)w2p;

    cudaFuncSetAttribute(gemm_h_kernel,
                         cudaFuncAttributeMaxDynamicSharedMemorySize, GSMEM);

    // 0: all weight transposes + kvz zero in one launch
    prep_kernel<<<12548, dim3(32, 8)>>>(qkv_w, out_w, w1, w2,
                                        wq_h, wo_h, w1_h, w2_h, (float*)kvzp);
    // 1: LN1 -> half
    ln_kernel<<<TOK, 256>>>(src, g1, be1, xln_h);
    // 2: qkv GEMM, epi3 -> phi(q),phi(k) half + v fp32
    gemm_h_kernel<<<dim3(3 * DM / BN, TOK / BM), GT, GSMEM>>>(
        xln_h, wq_h, qkv_b, vbuf, qkv_h, 3 * DM, DM, 3);
    // 3 (profiled): attention kv
    attn_kv_kernel<<<dim3(64, 8), 256>>>(qkv_h, vbuf);
    // 4: attention y
    attn_y_kernel<<<dim3(64, 32), 128>>>(qkv_h, attny_h);
    // 5: x = src + attny @ out_w + out_b
    gemm_h_kernel<<<dim3(DM / BN, TOK / BM), GT, GSMEM>>>(
        attny_h, wo_h, out_b, src, x, DM, DM, 1);
    // 6: LN2 -> half
    ln_kernel<<<TOK, 256>>>(x, g2, be2, xln_h);
    // 7: h = gelu(hln @ w1 + b1) -> half
    gemm_h_kernel<<<dim3(DFF / BN, TOK / BM), GT, GSMEM>>>(
        xln_h, w1_h, b1, nullptr, h_h, DFF, DM, 2);
    // 8: out = x + h @ w2 + b2
    gemm_h_kernel<<<dim3(DM / BN, TOK / BM), GT, GSMEM>>>(
        h_h, w2_h, b2, x, out, DM, DFF, 1);
}

// round 16
// speedup vs baseline: 2.9979x; 1.0435x over previous
#include <cuda_runtime.h>
#include <cuda_fp16.h>
#include <math.h>
#include <stdint.h>

#define TOK   16384
#define DM    1024
#define DFF   4096
#define NH    16
#define HD    64

// ---------------- scratch (static device allocations; no cudaMalloc) --------
__device__ float g_xln  [(size_t)TOK * DM];        // half buffer (ln out)
__device__ float g_qkv  [(size_t)TOK * 3 * DM];    // half buffer: phi(q),phi(k),v
__device__ float g_kvz  [64 * 4160];
__device__ float g_attny[(size_t)TOK * DM];        // half buffer
__device__ float g_x    [(size_t)TOK * DM];        // fp32
__device__ float g_h    [(size_t)TOK * DFF];       // half buffer (FFN hidden)
// half, TRANSPOSED weights [N][K]
__device__ float g_wq   [(size_t)3 * DM * DM / 2];
__device__ float g_wo   [(size_t)DM * DM / 2];
__device__ float g_w1   [(size_t)DFF * DM / 2];
__device__ float g_w2   [(size_t)DM * DFF / 2];

// ---------------- helpers ---------------------------------------------------
__device__ __forceinline__ uint32_t smem_u32(const void* p) {
    uint32_t a;
    asm("{ .reg .u64 t; cvta.to.shared.u64 t, %1; cvt.u32.u64 %0, t; }" : "=r"(a) : "l"(p));
    return a;
}
__device__ __forceinline__ float phi(float x) { return x > 0.f ? x + 1.f : expf(x); }
__device__ __forceinline__ float gelu_exact(float x) {
    return 0.5f * x * (1.f + erff(x * 0.70710678118654752440f));
}
__device__ __forceinline__ void cp16s(uint32_t dst, const void* src) {
    asm volatile("cp.async.cg.shared.global [%0], [%1], 16;\n" :: "r"(dst), "l"(src));
}
__device__ __forceinline__ void cp_commit() { asm volatile("cp.async.commit_group;\n"); }
template<int N> __device__ __forceinline__ void cp_wait() {
    asm volatile("cp.async.wait_group %0;\n" :: "n"(N));
}
__device__ __forceinline__ void mma_f16(float* d, const unsigned* a, const unsigned* b) {
    asm volatile(
        "mma.sync.aligned.m16n8k16.row.col.f32.f16.f16.f32 "
        "{%0,%1,%2,%3}, {%4,%5,%6,%7}, {%8,%9}, {%0,%1,%2,%3};\n"
        : "+f"(d[0]), "+f"(d[1]), "+f"(d[2]), "+f"(d[3])
        : "r"(a[0]), "r"(a[1]), "r"(a[2]), "r"(a[3]), "r"(b[0]), "r"(b[1]));
}
__device__ __forceinline__ void ldsm4(unsigned* r, uint32_t addr) {
    asm volatile("ldmatrix.sync.aligned.m8n8.x4.shared.b16 {%0,%1,%2,%3}, [%4];"
                 : "=r"(r[0]), "=r"(r[1]), "=r"(r[2]), "=r"(r[3]) : "r"(addr));
}

// packed f32x2 (Blackwell base-family PTX)
#define FMA2(acc, a, b) asm("fma.rn.f32x2 %0, %1, %2, %0;" : "+l"(acc) : "l"(a), "l"(b))
#define ADD2(acc, a)    asm("add.rn.f32x2 %0, %1, %0;" : "+l"(acc) : "l"(a))
#define PACK2(out, lo, hi) asm("mov.b64 %0, {%1, %2};" : "=l"(out) : "f"(lo), "f"(hi))
#define UNPACK2(lo, hi, in) asm("mov.b64 {%0, %1}, %2;" : "=f"(lo), "=f"(hi) : "l"(in))

// ---------------- fused prep: 4 weight transposes + kvz zero -----------------
__global__ void __launch_bounds__(256)
prep_kernel(const float* __restrict__ qkv_w, const float* __restrict__ out_w,
            const float* __restrict__ w1, const float* __restrict__ w2,
            __half* __restrict__ wq, __half* __restrict__ wo,
            __half* __restrict__ w1h, __half* __restrict__ w2h,
            float* __restrict__ kvz)
{
    int id = blockIdx.x;
    int t = threadIdx.y * 32 + threadIdx.x;
    if (id >= 12288) {
        int idx = (id - 12288) * 256 + t;
        if (idx < 66560) ((float4*)kvz)[idx] = make_float4(0.f, 0.f, 0.f, 0.f);
        return;
    }
    const float* in; __half* out; int K, N, bx, by;
    if (id < 3072)      { in = qkv_w; out = wq;  K = 1024; N = 3072; bx = id % 96;  by = id / 96; }
    else if (id < 4096) { int i = id - 3072; in = out_w; out = wo;  K = 1024; N = 1024; bx = i % 32;  by = i / 32; }
    else if (id < 8192) { int i = id - 4096; in = w1;    out = w1h; K = 1024; N = 4096; bx = i % 128; by = i / 128; }
    else                { int i = id - 8192; in = w2;    out = w2h; K = 4096; N = 1024; bx = i % 32;  by = i / 32; }

    __shared__ float tile[32][33];
    int n0 = bx * 32, k0 = by * 32;
#pragma unroll
    for (int i = threadIdx.y; i < 32; i += 8)
        tile[i][threadIdx.x] = in[(size_t)(k0 + i) * N + n0 + threadIdx.x];
    __syncthreads();
#pragma unroll
    for (int i = threadIdx.y; i < 32; i += 8)
        out[(size_t)(n0 + i) * K + k0 + threadIdx.x] = __float2half_rn(tile[threadIdx.x][i]);
}

// ---------------- LayerNorm (half output) ------------------------------------
__global__ void __launch_bounds__(256)
ln_kernel(const float* __restrict__ x, const float* __restrict__ g,
          const float* __restrict__ b, __half* __restrict__ y)
{
    int row = blockIdx.x;
    int tid = threadIdx.x;
    const float4* xr = (const float4*)(x + (size_t)row * DM);
    float4 v = xr[tid];
    float s = v.x + v.y + v.z + v.w;
    float q = v.x * v.x + v.y * v.y + v.z * v.z + v.w * v.w;
#pragma unroll
    for (int o = 16; o; o >>= 1) {
        s += __shfl_xor_sync(0xffffffffu, s, o);
        q += __shfl_xor_sync(0xffffffffu, q, o);
    }
    __shared__ float ss[8], sq[8];
    __shared__ float smu, srs;
    int warp = tid >> 5, lane = tid & 31;
    if (!lane) { ss[warp] = s; sq[warp] = q; }
    __syncthreads();
    if (!tid) {
        float S = 0.f, Q = 0.f;
#pragma unroll
        for (int i = 0; i < 8; i++) { S += ss[i]; Q += sq[i]; }
        float mu = S * (1.f / DM);
        float var = Q * (1.f / DM) - mu * mu;
        smu = mu;
        srs = rsqrtf(var + 1e-5f);
    }
    __syncthreads();
    float mu = smu, rs = srs;
    float4 gv = ((const float4*)g)[tid];
    float4 bv = ((const float4*)b)[tid];
    __half2 h01 = __floats2half2_rn((v.x - mu) * rs * gv.x + bv.x,
                                    (v.y - mu) * rs * gv.y + bv.y);
    __half2 h23 = __floats2half2_rn((v.z - mu) * rs * gv.z + bv.z,
                                    (v.w - mu) * rs * gv.w + bv.w);
    uint2 u;
    u.x = *(uint32_t*)&h01;
    u.y = *(uint32_t*)&h23;
    ((uint2*)(y + (size_t)row * DM))[tid] = u;
}

// ---------------- fp16 tensor-core GEMM: 512 thr, single-sync mainloop -------
// epi: 0 = fp32 out; 1 = +resid fp32 out; 2 = gelu -> half out;
//      3 = qkv: all half, row stride 3072; phi applied for c<2048 (q,k)
#define BM 128
#define BN 128
#define BKH 64
#define ROW_B 144
#define TILE_B (128 * ROW_B)                   // 18432
#define STAGE_B (2 * TILE_B)                   // 36864
#define GSMEM (3 * STAGE_B)                    // 110592
#define GT 512

__global__ void __launch_bounds__(GT, 2)
gemm_h_kernel(const __half* __restrict__ A, const __half* __restrict__ BT,
              const float* __restrict__ bias, const float* __restrict__ resid,
              void* __restrict__ Cv, int N, int K, int epi)
{
    extern __shared__ char smem[];
    uint32_t sb = smem_u32(smem);

    int tid  = threadIdx.x;
    int bm   = blockIdx.y * BM;
    int bn   = blockIdx.x * BN;
    int warp = tid >> 5, lane = tid & 31;
    int wm   = warp >> 2, wn = warp & 3;
    int gid  = lane >> 2, tig = lane & 3;

    float acc[2][4][4];
#pragma unroll
    for (int i = 0; i < 2; i++)
#pragma unroll
        for (int j = 0; j < 4; j++)
#pragma unroll
            for (int l = 0; l < 4; l++) acc[i][j][l] = 0.f;

    int srow = tid >> 2;
    int q4   = tid & 3;
    uint32_t soff = (uint32_t)srow * ROW_B + q4 * 32;
    const __half* ag = A + (size_t)(bm + srow) * K + q4 * 16;
    const __half* bg = BT + (size_t)(bn + srow) * K + q4 * 16;

    int T = K / BKH;

#define LOAD_STAGE(t, s) do { \
    uint32_t base = sb + (uint32_t)(s) * STAGE_B; \
    const __half* ap = ag + (size_t)(t) * BKH; \
    const __half* bp = bg + (size_t)(t) * BKH; \
    cp16s(base + soff,               ap); \
    cp16s(base + soff + 16,          ap + 8); \
    cp16s(base + TILE_B + soff,      bp); \
    cp16s(base + TILE_B + soff + 16, bp + 8); \
} while (0)

    LOAD_STAGE(0, 0); cp_commit();
    LOAD_STAGE(1, 1); cp_commit();

    uint32_t a_off = (uint32_t)(wm * 32 + (lane & 7) + ((lane >> 3) & 1) * 8) * ROW_B
                   + ((lane >> 4) & 1) * 16;
    uint32_t b_off = (uint32_t)(wn * 32 + (lane & 7) + ((lane >> 4) & 1) * 8) * ROW_B
                   + ((lane >> 3) & 1) * 16;

    for (int t = 0; t < T; t++) {
        cp_wait<1>();
        __syncthreads();
        if (t + 2 < T) { LOAD_STAGE(t + 2, (t + 2) % 3); }
        cp_commit();

        uint32_t ab = sb + (uint32_t)(t % 3) * STAGE_B;
        uint32_t bb = ab + TILE_B;

#pragma unroll
        for (int kk = 0; kk < 4; kk++) {
            uint32_t kb = kk * 32;
            unsigned a[2][4], b[2][4];
#pragma unroll
            for (int mf = 0; mf < 2; mf++)
                ldsm4(a[mf], ab + a_off + mf * 16 * ROW_B + kb);
#pragma unroll
            for (int nbp = 0; nbp < 2; nbp++)
                ldsm4(b[nbp], bb + b_off + nbp * 16 * ROW_B + kb);
#pragma unroll
            for (int mf = 0; mf < 2; mf++)
#pragma unroll
                for (int nf = 0; nf < 4; nf++) {
                    unsigned bfr[2] = { b[nf >> 1][(nf & 1) * 2],
                                        b[nf >> 1][(nf & 1) * 2 + 1] };
                    mma_f16(acc[mf][nf], a[mf], bfr);
                }
        }
    }

    // ---- epilogue ----
    float* Cf = (float*)Cv;
    __half* Ch = (__half*)Cv;
#pragma unroll
    for (int mf = 0; mf < 2; mf++) {
#pragma unroll
        for (int nf = 0; nf < 4; nf++) {
            int r = bm + wm * 32 + mf * 16 + gid;
            int c = bn + wn * 32 + nf * 8 + tig * 2;
            float bx = bias[c], by = bias[c + 1];
            float2 v0 = make_float2(acc[mf][nf][0] + bx, acc[mf][nf][1] + by);
            float2 v1 = make_float2(acc[mf][nf][2] + bx, acc[mf][nf][3] + by);
            if (epi == 1) {
                const float* r0 = resid + (size_t)r * N + c;
                const float* r1 = resid + (size_t)(r + 8) * N + c;
                v0.x += r0[0]; v0.y += r0[1];
                v1.x += r1[0]; v1.y += r1[1];
            }
            if (epi == 2) {
                __half2 h0 = __floats2half2_rn(gelu_exact(v0.x), gelu_exact(v0.y));
                __half2 h1 = __floats2half2_rn(gelu_exact(v1.x), gelu_exact(v1.y));
                *(__half2*)(Ch + (size_t)r * N + c)       = h0;
                *(__half2*)(Ch + (size_t)(r + 8) * N + c) = h1;
            } else if (epi == 3) {
                __half2 h0, h1;
                if (c < 2048) {      // q,k: phi
                    h0 = __floats2half2_rn(phi(v0.x), phi(v0.y));
                    h1 = __floats2half2_rn(phi(v1.x), phi(v1.y));
                } else {             // v: plain half
                    h0 = __floats2half2_rn(v0.x, v0.y);
                    h1 = __floats2half2_rn(v1.x, v1.y);
                }
                *(__half2*)(Ch + (size_t)r * 3072 + c)       = h0;
                *(__half2*)(Ch + (size_t)(r + 8) * 3072 + c) = h1;
            } else {
                *(float2*)(Cf + (size_t)r * N + c)       = v0;
                *(float2*)(Cf + (size_t)(r + 8) * N + c) = v1;
            }
        }
    }
}

// ---------------- attention: kv & z accumulation (fp16 k AND v) ---------------
// grid (64 bh, 16 chunks of 256 rows), 256 threads; single-sync double buffer
#define KSTG 4096      // 32*64*2
#define VSTG 4608      // 32*72*2
__global__ void __launch_bounds__(256)
attn_kv_kernel(const __half* __restrict__ qkv_h)
{
    int bh = blockIdx.x;
    int b = bh >> 4, h = bh & 15;
    int row0 = b * 4096 + blockIdx.y * 256;
    const __half* kbase = qkv_h + (size_t)row0 * 3072 + 1024 + h * 64;
    const __half* vbase = qkv_h + (size_t)row0 * 3072 + 2048 + h * 64;

    __shared__ __half kb[2][32][64];
    __shared__ __half vb[2][32][72];

    int tid = threadIdx.x;
    int r = tid >> 3, kc = tid & 7;
    uint32_t kb0 = smem_u32(&kb[0][0][0]);
    uint32_t vb0 = smem_u32(&vb[0][0][0]);

    int d0 = (tid >> 3) * 2;
    int e0 = (tid & 7) * 8;
    unsigned long long acc2[8];
#pragma unroll
    for (int j = 0; j < 8; j++) acc2[j] = 0ull;
    unsigned long long z2 = 0ull;

#define AKV_LOAD(t0, s) do { \
    const __half* kp = kbase + (size_t)((t0) + r) * 3072 + kc * 8; \
    const __half* vp = vbase + (size_t)((t0) + r) * 3072 + kc * 8; \
    cp16s(kb0 + (s) * KSTG + r * 128 + kc * 16, kp); \
    cp16s(vb0 + (s) * VSTG + r * 144 + kc * 16, vp); \
} while (0)

    AKV_LOAD(0, 0); cp_commit();

    for (int it = 0; it < 8; it++) {
        cp_wait<0>();
        __syncthreads();
        if (it + 1 < 8) { AKV_LOAD((it + 1) * 32, (it + 1) & 1); cp_commit(); }
        int s = it & 1;
#pragma unroll 8
        for (int r2 = 0; r2 < 32; r2++) {
            float2 kd = __half22float2(*(__half2*)&kb[s][r2][d0]);
            uint4 vv = *(const uint4*)&vb[s][r2][e0];
            float2 f0 = __half22float2(*(__half2*)&vv.x);
            float2 f1 = __half22float2(*(__half2*)&vv.y);
            float2 f2 = __half22float2(*(__half2*)&vv.z);
            float2 f3 = __half22float2(*(__half2*)&vv.w);
            unsigned long long kx2, ky2, kz2, p0, p1, p2, p3;
            PACK2(kx2, kd.x, kd.x);
            PACK2(ky2, kd.y, kd.y);
            PACK2(kz2, kd.x, kd.y);
            PACK2(p0, f0.x, f0.y);
            PACK2(p1, f1.x, f1.y);
            PACK2(p2, f2.x, f2.y);
            PACK2(p3, f3.x, f3.y);
            FMA2(acc2[0], kx2, p0); FMA2(acc2[1], kx2, p1);
            FMA2(acc2[2], kx2, p2); FMA2(acc2[3], kx2, p3);
            FMA2(acc2[4], ky2, p0); FMA2(acc2[5], ky2, p1);
            FMA2(acc2[6], ky2, p2); FMA2(acc2[7], ky2, p3);
            ADD2(z2, kz2);
        }
    }

    float* kvp = g_kvz + (size_t)bh * 4160;
#pragma unroll
    for (int j = 0; j < 4; j++) {
        float lo, hi;
        UNPACK2(lo, hi, acc2[j]);
        atomicAdd(&kvp[(d0) * 64 + e0 + 2 * j], lo);
        atomicAdd(&kvp[(d0) * 64 + e0 + 2 * j + 1], hi);
    }
#pragma unroll
    for (int j = 0; j < 4; j++) {
        float lo, hi;
        UNPACK2(lo, hi, acc2[4 + j]);
        atomicAdd(&kvp[(d0 + 1) * 64 + e0 + 2 * j], lo);
        atomicAdd(&kvp[(d0 + 1) * 64 + e0 + 2 * j + 1], hi);
    }
    if ((tid & 7) == 0) {
        float z0, z1;
        UNPACK2(z0, z1, z2);
        atomicAdd(&kvp[4096 + d0], z0);
        atomicAdd(&kvp[4096 + d0 + 1], z1);
    }
}

// ---------------- attention y: eg-chunked, low-reg ----------------------------
__global__ void __launch_bounds__(128)
attn_y_kernel(const __half* __restrict__ qkv_h, __half* __restrict__ y)
{
    int bh = blockIdx.x;
    int b = bh >> 4, h = bh & 15;
    int chunk = blockIdx.y;
    int tid = threadIdx.x;

    __shared__ float kvs[4096];
    __shared__ float zs[64];
    const float* kvp = g_kvz + (size_t)bh * 4160;
    for (int i = tid; i < 4160; i += 128) {
        float v = kvp[i];
        if (i < 4096) kvs[i] = v; else zs[i - 4096] = v;
    }
    __syncthreads();

    int row = b * 4096 + chunk * 128 + tid;
    const uint4* qp4 = (const uint4*)(qkv_h + (size_t)row * 3072 + h * 64);
    unsigned qh[32];
#pragma unroll
    for (int i = 0; i < 8; i++) {
        uint4 u = qp4[i];
        qh[i * 4 + 0] = u.x; qh[i * 4 + 1] = u.y;
        qh[i * 4 + 2] = u.z; qh[i * 4 + 3] = u.w;
    }

    float den = 0.f;
#pragma unroll
    for (int dp = 0; dp < 32; dp++) {
        float2 f = __half22float2(*(__half2*)&qh[dp]);
        den += f.x * zs[2 * dp] + f.y * zs[2 * dp + 1];
    }
    den = fmaxf(den, 1e-6f);
    float inv = 1.f / den;

    __half* yp = y + (size_t)row * 1024 + h * 64;
#pragma unroll
    for (int c = 0; c < 4; c++) {
        unsigned long long acc2[8];
#pragma unroll
        for (int j = 0; j < 8; j++) acc2[j] = 0ull;
#pragma unroll 8
        for (int dp = 0; dp < 32; dp++) {
            float2 f = __half22float2(*(__half2*)&qh[dp]);
            unsigned long long qa, qb;
            PACK2(qa, f.x, f.x);
            PACK2(qb, f.y, f.y);
            const float4* kr0 = (const float4*)(kvs + (2 * dp) * 64) + c * 4;
            const float4* kr1 = (const float4*)(kvs + (2 * dp + 1) * 64) + c * 4;
#pragma unroll
            for (int e = 0; e < 4; e++) {
                float4 k0 = kr0[e];
                unsigned long long p0, p1;
                PACK2(p0, k0.x, k0.y);
                PACK2(p1, k0.z, k0.w);
                FMA2(acc2[e * 2], qa, p0);
                FMA2(acc2[e * 2 + 1], qa, p1);
            }
#pragma unroll
            for (int e = 0; e < 4; e++) {
                float4 k1 = kr1[e];
                unsigned long long p0, p1;
                PACK2(p0, k1.x, k1.y);
                PACK2(p1, k1.z, k1.w);
                FMA2(acc2[e * 2], qb, p0);
                FMA2(acc2[e * 2 + 1], qb, p1);
            }
        }
#pragma unroll
        for (int e = 0; e < 4; e++) {
            float a0, a1, a2, a3;
            UNPACK2(a0, a1, acc2[e * 2]);
            UNPACK2(a2, a3, acc2[e * 2 + 1]);
            __half2 h0 = __floats2half2_rn(a0 * inv, a1 * inv);
            __half2 h1 = __floats2half2_rn(a2 * inv, a3 * inv);
            uint2 u;
            u.x = *(uint32_t*)&h0;
            u.y = *(uint32_t*)&h1;
            *(uint2*)(yp + (c * 4 + e) * 4) = u;
        }
    }
}

// ---------------- launch ----------------------------------------------------
extern "C" void kernel_launch(void* const* d_in, const int* in_sizes, int n_in,
                              void* d_out, int out_size)
{
    (void)in_sizes; (void)n_in; (void)out_size;
    const float* src   = (const float*)d_in[0];
    const float* qkv_w = (const float*)d_in[1];
    const float* qkv_b = (const float*)d_in[2];
    const float* out_w = (const float*)d_in[3];
    const float* out_b = (const float*)d_in[4];
    const float* w1    = (const float*)d_in[5];
    const float* b1    = (const float*)d_in[6];
    const float* w2    = (const float*)d_in[7];
    const float* b2    = (const float*)d_in[8];
    const float* g1    = (const float*)d_in[9];
    const float* be1   = (const float*)d_in[10];
    const float* g2    = (const float*)d_in[11];
    const float* be2   = (const float*)d_in[12];
    float* out = (float*)d_out;

    void *xlnp, *qkvp, *attnyp, *xp, *hp, *wqp, *wop, *w1p, *w2p, *kvzp;
    cudaGetSymbolAddress(&xlnp,   g_xln);
    cudaGetSymbolAddress(&qkvp,   g_qkv);
    cudaGetSymbolAddress(&attnyp, g_attny);
    cudaGetSymbolAddress(&xp,     g_x);
    cudaGetSymbolAddress(&hp,     g_h);
    cudaGetSymbolAddress(&wqp,    g_wq);
    cudaGetSymbolAddress(&wop,    g_wo);
    cudaGetSymbolAddress(&w1p,    g_w1);
    cudaGetSymbolAddress(&w2p,    g_w2);
    cudaGetSymbolAddress(&kvzp,   g_kvz);

    __half* xln_h   = (__half*)xlnp;
    __half* qkv_h   = (__half*)qkvp;
    __half* attny_h = (__half*)attnyp;
    float*  x       = (float*)xp;
    __half* h_h     = (__half*)hp;
    __half* wq_h    = (__half*)wqp;
    __half* wo_h    = (__half*)wop;
    __half* w1_h    = (__half*)w1p;
    __half* w2_h    = (__half*)w2p;

    cudaFuncSetAttribute(gemm_h_kernel,
                         cudaFuncAttributeMaxDynamicSharedMemorySize, GSMEM);

    // 0: all weight transposes + kvz zero in one launch
    prep_kernel<<<12548, dim3(32, 8)>>>(qkv_w, out_w, w1, w2,
                                        wq_h, wo_h, w1_h, w2_h, (float*)kvzp);
    // 1: LN1 -> half
    ln_kernel<<<TOK, 256>>>(src, g1, be1, xln_h);
    // 2: qkv GEMM, epi3 -> phi(q),phi(k),v all half in qkv_h
    gemm_h_kernel<<<dim3(3 * DM / BN, TOK / BM), GT, GSMEM>>>(
        xln_h, wq_h, qkv_b, nullptr, qkv_h, 3 * DM, DM, 3);
    // 3 (profiled): attention kv
    attn_kv_kernel<<<dim3(64, 16), 256>>>(qkv_h);
    // 4: attention y
    attn_y_kernel<<<dim3(64, 32), 128>>>(qkv_h, attny_h);
    // 5: x = src + attny @ out_w + out_b
    gemm_h_kernel<<<dim3(DM / BN, TOK / BM), GT, GSMEM>>>(
        attny_h, wo_h, out_b, src, x, DM, DM, 1);
    // 6: LN2 -> half
    ln_kernel<<<TOK, 256>>>(x, g2, be2, xln_h);
    // 7: h = gelu(hln @ w1 + b1) -> half
    gemm_h_kernel<<<dim3(DFF / BN, TOK / BM), GT, GSMEM>>>(
        xln_h, w1_h, b1, nullptr, h_h, DFF, DM, 2);
    // 8: out = x + h @ w2 + b2
    gemm_h_kernel<<<dim3(DM / BN, TOK / BM), GT, GSMEM>>>(
        h_h, w2_h, b2, x, out, DM, DFF, 1);
}